// round 2
// baseline (speedup 1.0000x reference)
#include <cuda_runtime.h>
#include <cuda_bf16.h>
#include <math.h>

#define NN   50000
#define EE   800000
#define ET   (EE + NN)      // 850000 edges incl. self loops
#define FDIM 128
#define NH   4
#define CH   32
#define NEG_SLOPE 0.2f

// ---------------- device scratch (module-load allocated, no cudaMalloc) ----
__device__ int   g_cnt[NN];
__device__ int   g_rowptr[NN + 1];
__device__ int   g_cursor[NN];
__device__ int   g_csr[ET];
__device__ int   g_bsums[256];

__device__ float g_hw[NN * FDIM];     // transformed features (current layer)
__device__ float g_f1[NN * FDIM];     // layer1 output
__device__ float g_f2[NN * FDIM];     // layer2 output
__device__ float g_alpha[NN * 2 * NH];// per-node alpha_src[0..3], alpha_dst[4..7]
__device__ float g_hw3[NN * 2];
__device__ float g_a3[NN * 2];

// ---------------- helpers ---------------------------------------------------
__device__ __forceinline__ float wmax(float v) {
    #pragma unroll
    for (int o = 16; o; o >>= 1) v = fmaxf(v, __shfl_xor_sync(0xffffffffu, v, o));
    return v;
}
__device__ __forceinline__ float wsum(float v) {
    #pragma unroll
    for (int o = 16; o; o >>= 1) v += __shfl_xor_sync(0xffffffffu, v, o);
    return v;
}
// packed fp32x2 FMA (Blackwell): d = a*b + d elementwise on two packed floats
__device__ __forceinline__ void fma2(unsigned long long& d,
                                     unsigned long long a, unsigned long long b) {
    asm("fma.rn.f32x2 %0, %1, %2, %0;" : "+l"(d) : "l"(a), "l"(b));
}
__device__ __forceinline__ float f2lo(unsigned long long v) {
    return __uint_as_float((unsigned)(v & 0xffffffffu));
}
__device__ __forceinline__ float f2hi(unsigned long long v) {
    return __uint_as_float((unsigned)(v >> 32));
}

// ---------------- CSR construction ------------------------------------------
__global__ void k_zero_cnt() {
    int i = blockIdx.x * blockDim.x + threadIdx.x;
    if (i < NN) g_cnt[i] = 0;
}

__global__ void k_hist(const int* __restrict__ ei) {
    int e = blockIdx.x * blockDim.x + threadIdx.x;
    if (e >= ET) return;
    int dst = (e < EE) ? ei[EE + e] : (e - EE);
    atomicAdd(&g_cnt[dst], 1);
}

__global__ void k_scan_block() {
    __shared__ int sm[256];
    int i = blockIdx.x * 256 + threadIdx.x;
    int v = (i < NN) ? g_cnt[i] : 0;
    sm[threadIdx.x] = v;
    __syncthreads();
    #pragma unroll
    for (int o = 1; o < 256; o <<= 1) {
        int t = (threadIdx.x >= o) ? sm[threadIdx.x - o] : 0;
        __syncthreads();
        sm[threadIdx.x] += t;
        __syncthreads();
    }
    if (i < NN) g_rowptr[i] = sm[threadIdx.x] - v;       // exclusive, block-local
    if (threadIdx.x == 255) g_bsums[blockIdx.x] = sm[255];
}

__global__ void k_scan_tops(int nb) {
    __shared__ int sm[256];
    int v = (threadIdx.x < nb) ? g_bsums[threadIdx.x] : 0;
    sm[threadIdx.x] = v;
    __syncthreads();
    #pragma unroll
    for (int o = 1; o < 256; o <<= 1) {
        int t = (threadIdx.x >= o) ? sm[threadIdx.x - o] : 0;
        __syncthreads();
        sm[threadIdx.x] += t;
        __syncthreads();
    }
    g_bsums[threadIdx.x] = sm[threadIdx.x] - v;          // exclusive
}

__global__ void k_scan_finish() {
    int i = blockIdx.x * blockDim.x + threadIdx.x;
    if (i < NN) {
        int r = g_rowptr[i] + g_bsums[i >> 8];
        g_rowptr[i] = r;
        g_cursor[i] = r;
    }
    if (i == 0) g_rowptr[NN] = ET;
}

__global__ void k_scatter(const int* __restrict__ ei) {
    int e = blockIdx.x * blockDim.x + threadIdx.x;
    if (e >= ET) return;
    int src, dst;
    if (e < EE) { src = ei[e]; dst = ei[EE + e]; }
    else        { src = dst = e - EE; }
    int p = atomicAdd(&g_cursor[dst], 1);
    g_csr[p] = src;
}

// ---------------- GEMM: C[M,128] = A[M,128] @ W[128,128] --------------------
// 64x128 tile, 128 threads, 8x8 micro-tile per thread, packed f32x2 FMAs.
// As stored transposed [k][m]; Bs stored duplicated [k][2c] so each 64-bit
// shared load directly yields a packed (b,b) operand — no per-iter packing.
__global__ void __launch_bounds__(128)
k_gemm128(const float* __restrict__ A, const float* __restrict__ W,
          float* __restrict__ C, int M) {
    __shared__ float As[32][64];     // [k][m]        8 KB
    __shared__ float Bs[32][256];    // [k][2c] dup  32 KB
    int t  = threadIdx.x;
    int tx = t & 15;                 // column group
    int ty = t >> 4;                 // 0..7 row group
    int row0 = blockIdx.x * 64;

    unsigned long long acc[4][8];    // [rowpair][col]
    #pragma unroll
    for (int r = 0; r < 4; r++)
        #pragma unroll
        for (int c = 0; c < 8; c++) acc[r][c] = 0ull;

    for (int k0 = 0; k0 < 128; k0 += 32) {
        // load A tile transposed: 512 float4s
        #pragma unroll
        for (int i = 0; i < 4; i++) {
            int idx = i * 128 + t;
            int m = idx >> 3, kq = idx & 7;
            int gr = row0 + m;
            float4 v = (gr < M) ? *(const float4*)&A[gr * 128 + k0 + kq * 4]
                                : make_float4(0.f, 0.f, 0.f, 0.f);
            As[kq * 4 + 0][m] = v.x;
            As[kq * 4 + 1][m] = v.y;
            As[kq * 4 + 2][m] = v.z;
            As[kq * 4 + 3][m] = v.w;
        }
        // load W tile duplicated: 1024 float4s of W
        #pragma unroll
        for (int i = 0; i < 8; i++) {
            int idx = i * 128 + t;
            int r = idx >> 5, c4 = (idx & 31) * 4;
            float4 v = *(const float4*)&W[(k0 + r) * 128 + c4];
            *(float4*)&Bs[r][2 * c4]     = make_float4(v.x, v.x, v.y, v.y);
            *(float4*)&Bs[r][2 * c4 + 4] = make_float4(v.z, v.z, v.w, v.w);
        }
        __syncthreads();
        #pragma unroll
        for (int kk = 0; kk < 32; kk++) {
            ulonglong2 a0 = *(const ulonglong2*)&As[kk][4 * ty];       // rows 4ty..+3
            ulonglong2 a1 = *(const ulonglong2*)&As[kk][32 + 4 * ty];  // rows 32+4ty..+3
            ulonglong2 b0 = *(const ulonglong2*)&Bs[kk][8 * tx];       // cols 4tx,4tx+1 dup
            ulonglong2 b1 = *(const ulonglong2*)&Bs[kk][8 * tx + 4];   // cols 4tx+2,+3
            ulonglong2 b2 = *(const ulonglong2*)&Bs[kk][128 + 8 * tx]; // cols 64+4tx,+1
            ulonglong2 b3 = *(const ulonglong2*)&Bs[kk][128 + 8 * tx + 4];
            unsigned long long ap[4] = {a0.x, a0.y, a1.x, a1.y};
            unsigned long long bp[8] = {b0.x, b0.y, b1.x, b1.y, b2.x, b2.y, b3.x, b3.y};
            #pragma unroll
            for (int r = 0; r < 4; r++)
                #pragma unroll
                for (int c = 0; c < 8; c++)
                    fma2(acc[r][c], ap[r], bp[c]);
        }
        __syncthreads();
    }

    // store 8 rows x 8 cols
    #pragma unroll
    for (int rp = 0; rp < 4; rp++) {
        int rl = row0 + ((rp & 2) ? 32 : 0) + 4 * ty + ((rp & 1) ? 2 : 0);
        int rh = rl + 1;
        if (rl < M) {
            *(float4*)&C[rl * 128 + 4 * tx] =
                make_float4(f2lo(acc[rp][0]), f2lo(acc[rp][1]), f2lo(acc[rp][2]), f2lo(acc[rp][3]));
            *(float4*)&C[rl * 128 + 64 + 4 * tx] =
                make_float4(f2lo(acc[rp][4]), f2lo(acc[rp][5]), f2lo(acc[rp][6]), f2lo(acc[rp][7]));
        }
        if (rh < M) {
            *(float4*)&C[rh * 128 + 4 * tx] =
                make_float4(f2hi(acc[rp][0]), f2hi(acc[rp][1]), f2hi(acc[rp][2]), f2hi(acc[rp][3]));
            *(float4*)&C[rh * 128 + 64 + 4 * tx] =
                make_float4(f2hi(acc[rp][4]), f2hi(acc[rp][5]), f2hi(acc[rp][6]), f2hi(acc[rp][7]));
        }
    }
}

// ---------------- per-node alpha (H=4, C=32) --------------------------------
__global__ void k_alpha4(const float* __restrict__ hw,
                         const float* __restrict__ asrc,
                         const float* __restrict__ adst) {
    int n = (blockIdx.x * blockDim.x + threadIdx.x) >> 5;
    if (n >= NN) return;
    int lane = threadIdx.x & 31;
    #pragma unroll
    for (int h = 0; h < NH; h++) {
        float v  = hw[n * FDIM + h * CH + lane];
        float ps = wsum(v * asrc[h * CH + lane]);
        float pd = wsum(v * adst[h * CH + lane]);
        if (lane == 0) {
            g_alpha[n * 8 + h]     = ps;
            g_alpha[n * 8 + 4 + h] = pd;
        }
    }
}

// ---------------- edge softmax + aggregation (H=4, C=32) --------------------
// 2 passes: (1) lane-parallel max, (2) lane-parallel exp staged through smem,
// serially consumed with lane = channel. out = (sum_e e*h)/(sum_e e).
__global__ void k_aggregate4(const float* __restrict__ hw,
                             const float* __restrict__ bias,
                             float* __restrict__ out, int applyElu) {
    __shared__ float4 sm_e[8][32];
    __shared__ int    sm_s[8][32];
    int n = (blockIdx.x * blockDim.x + threadIdx.x) >> 5;
    if (n >= NN) return;
    int lane = threadIdx.x & 31;
    int wrp  = (threadIdx.x >> 5);
    int s0 = g_rowptr[n], s1 = g_rowptr[n + 1];
    float4 ad = *(const float4*)&g_alpha[n * 8 + 4];

    // pass 1: max of leakyrelu(alpha)
    float m0 = -3.4e38f, m1 = -3.4e38f, m2 = -3.4e38f, m3 = -3.4e38f;
    for (int i = s0 + lane; i < s1; i += 32) {
        int s = g_csr[i];
        float4 al = *(const float4*)&g_alpha[s * 8];
        float a;
        a = al.x + ad.x; a = (a > 0.f) ? a : NEG_SLOPE * a; m0 = fmaxf(m0, a);
        a = al.y + ad.y; a = (a > 0.f) ? a : NEG_SLOPE * a; m1 = fmaxf(m1, a);
        a = al.z + ad.z; a = (a > 0.f) ? a : NEG_SLOPE * a; m2 = fmaxf(m2, a);
        a = al.w + ad.w; a = (a > 0.f) ? a : NEG_SLOPE * a; m3 = fmaxf(m3, a);
    }
    m0 = wmax(m0); m1 = wmax(m1); m2 = wmax(m2); m3 = wmax(m3);

    // pass 2: exp (lane-parallel, staged in smem) + serial gather-accumulate
    float sum0 = 0.f, sum1 = 0.f, sum2 = 0.f, sum3 = 0.f;
    float acc0 = 0.f, acc1 = 0.f, acc2 = 0.f, acc3 = 0.f;
    for (int base = s0; base < s1; base += 32) {
        int i = base + lane;
        int s = 0;
        float4 e = make_float4(0.f, 0.f, 0.f, 0.f);
        if (i < s1) {
            s = g_csr[i];
            float4 al = *(const float4*)&g_alpha[s * 8];
            float a;
            a = al.x + ad.x; a = (a > 0.f) ? a : NEG_SLOPE * a; e.x = __expf(a - m0); sum0 += e.x;
            a = al.y + ad.y; a = (a > 0.f) ? a : NEG_SLOPE * a; e.y = __expf(a - m1); sum1 += e.y;
            a = al.z + ad.z; a = (a > 0.f) ? a : NEG_SLOPE * a; e.z = __expf(a - m2); sum2 += e.z;
            a = al.w + ad.w; a = (a > 0.f) ? a : NEG_SLOPE * a; e.w = __expf(a - m3); sum3 += e.w;
        }
        sm_s[wrp][lane] = s;
        sm_e[wrp][lane] = e;
        __syncwarp();
        int cnt = min(32, s1 - base);
        #pragma unroll 2
        for (int j = 0; j < cnt; j++) {
            int ss = sm_s[wrp][j];
            float4 ee = sm_e[wrp][j];
            const float* hp = hw + ss * FDIM + lane;
            acc0 += ee.x * hp[0];
            acc1 += ee.y * hp[32];
            acc2 += ee.z * hp[64];
            acc3 += ee.w * hp[96];
        }
        __syncwarp();
    }
    float inv0 = 1.f / wsum(sum0);
    float inv1 = 1.f / wsum(sum1);
    float inv2 = 1.f / wsum(sum2);
    float inv3 = 1.f / wsum(sum3);

    float v;
    v = acc0 * inv0 + bias[lane];
    if (applyElu) v = (v > 0.f) ? v : (__expf(v) - 1.f);
    out[n * FDIM + lane] = v;
    v = acc1 * inv1 + bias[32 + lane];
    if (applyElu) v = (v > 0.f) ? v : (__expf(v) - 1.f);
    out[n * FDIM + 32 + lane] = v;
    v = acc2 * inv2 + bias[64 + lane];
    if (applyElu) v = (v > 0.f) ? v : (__expf(v) - 1.f);
    out[n * FDIM + 64 + lane] = v;
    v = acc3 * inv3 + bias[96 + lane];
    if (applyElu) v = (v > 0.f) ? v : (__expf(v) - 1.f);
    out[n * FDIM + 96 + lane] = v;
}

// ---------------- layer 3: [N,128]@[128,2] + alphas -------------------------
__global__ void k_l3prep(const float* __restrict__ in, const float* __restrict__ W3,
                         const float* __restrict__ as3, const float* __restrict__ ad3) {
    int n = (blockIdx.x * blockDim.x + threadIdx.x) >> 5;
    if (n >= NN) return;
    int lane = threadIdx.x & 31;
    float4 v = *(const float4*)&in[n * FDIM + lane * 4];
    const float4 w0 = *(const float4*)&W3[2 * (lane * 4)];       // (W[k][0],W[k][1],W[k+1][0],W[k+1][1])
    const float4 w1 = *(const float4*)&W3[2 * (lane * 4) + 4];
    float a0 = v.x * w0.x + v.y * w0.z + v.z * w1.x + v.w * w1.z;
    float a1 = v.x * w0.y + v.y * w0.w + v.z * w1.y + v.w * w1.w;
    a0 = wsum(a0); a1 = wsum(a1);
    if (lane == 0) {
        g_hw3[n * 2] = a0; g_hw3[n * 2 + 1] = a1;
        g_a3[n * 2]     = a0 * as3[0] + a1 * as3[1];
        g_a3[n * 2 + 1] = a0 * ad3[0] + a1 * ad3[1];
    }
}

// layer-3 aggregate (H=1,C=2) + bias + log_softmax (fully lane-parallel)
__global__ void k_aggregate1(const float* __restrict__ b3, float* __restrict__ out) {
    int n = (blockIdx.x * blockDim.x + threadIdx.x) >> 5;
    if (n >= NN) return;
    int lane = threadIdx.x & 31;
    int s0 = g_rowptr[n], s1 = g_rowptr[n + 1];
    float ad = g_a3[n * 2 + 1];

    float m = -3.4e38f;
    for (int i = s0 + lane; i < s1; i += 32) {
        int s = g_csr[i];
        float a = g_a3[s * 2] + ad;
        a = (a > 0.f) ? a : NEG_SLOPE * a;
        m = fmaxf(m, a);
    }
    m = wmax(m);

    float sum = 0.f, a0 = 0.f, a1 = 0.f;
    for (int i = s0 + lane; i < s1; i += 32) {
        int s = g_csr[i];
        float2 al = *(const float2*)&g_a3[s * 2];
        float a = al.x + ad;
        a = (a > 0.f) ? a : NEG_SLOPE * a;
        float e = __expf(a - m);
        sum += e;
        float2 h = *(const float2*)&g_hw3[s * 2];
        a0 += e * h.x;
        a1 += e * h.y;
    }
    sum = wsum(sum); a0 = wsum(a0); a1 = wsum(a1);

    if (lane == 0) {
        float inv = 1.f / sum;
        float z0 = a0 * inv + b3[0];
        float z1 = a1 * inv + b3[1];
        float mx = fmaxf(z0, z1);
        float l  = logf(__expf(z0 - mx) + __expf(z1 - mx));
        out[n * 2]     = z0 - mx - l;
        out[n * 2 + 1] = z1 - mx - l;
    }
}

// ---------------- host driver -----------------------------------------------
extern "C" void kernel_launch(void* const* d_in, const int* in_sizes, int n_in,
                              void* d_out, int out_size) {
    const float* x   = (const float*)d_in[0];
    const int*   ei  = (const int*)  d_in[1];
    const float* W1  = (const float*)d_in[2];
    const float* as1 = (const float*)d_in[3];
    const float* ad1 = (const float*)d_in[4];
    const float* b1  = (const float*)d_in[5];
    const float* W2  = (const float*)d_in[6];
    const float* as2 = (const float*)d_in[7];
    const float* ad2 = (const float*)d_in[8];
    const float* b2  = (const float*)d_in[9];
    const float* W3  = (const float*)d_in[10];
    const float* as3 = (const float*)d_in[11];
    const float* ad3 = (const float*)d_in[12];
    const float* b3  = (const float*)d_in[13];
    float* out = (float*)d_out;

    float *p_hw, *p_f1, *p_f2;
    cudaGetSymbolAddress((void**)&p_hw, g_hw);
    cudaGetSymbolAddress((void**)&p_f1, g_f1);
    cudaGetSymbolAddress((void**)&p_f2, g_f2);

    const int TPB = 256;
    int nbN  = (NN + TPB - 1) / TPB;          // 196
    int nbE  = (ET + TPB - 1) / TPB;          // 3321
    int nbW  = (NN * 32 + TPB - 1) / TPB;     // 6250 (warp per node)
    int nbG  = (NN + 63) / 64;                // 782 (gemm tiles)

    // CSR build
    k_zero_cnt<<<nbN, TPB>>>();
    k_hist<<<nbE, TPB>>>(ei);
    k_scan_block<<<nbN, TPB>>>();
    k_scan_tops<<<1, 256>>>(nbN);
    k_scan_finish<<<nbN, TPB>>>();
    k_scatter<<<nbE, TPB>>>(ei);

    // layer 1
    k_gemm128<<<nbG, 128>>>(x, W1, p_hw, NN);
    k_alpha4<<<nbW, TPB>>>(p_hw, as1, ad1);
    k_aggregate4<<<nbW, TPB>>>(p_hw, b1, p_f1, 1);

    // layer 2
    k_gemm128<<<nbG, 128>>>(p_f1, W2, p_hw, NN);
    k_alpha4<<<nbW, TPB>>>(p_hw, as2, ad2);
    k_aggregate4<<<nbW, TPB>>>(p_hw, b2, p_f2, 1);

    // layer 3
    k_l3prep<<<nbW, TPB>>>(p_f2, W3, as3, ad3);
    k_aggregate1<<<nbW, TPB>>>(b3, out);
}

// round 3
// speedup vs baseline: 1.1861x; 1.1861x over previous
#include <cuda_runtime.h>
#include <cuda_bf16.h>
#include <math.h>

#define NN   50000
#define EE   800000
#define ET   (EE + NN)      // 850000 edges incl. self loops
#define FDIM 128
#define NH   4
#define CH   32
#define NEG_SLOPE 0.2f

// ---------------- device scratch (module-load allocated, no cudaMalloc) ----
__device__ int   g_cnt[NN];
__device__ int   g_rowptr[NN + 1];
__device__ int   g_cursor[NN];
__device__ int   g_csr[ET];
__device__ int   g_bsums[256];

__device__ float g_hw[NN * FDIM];     // transformed features (current layer)
__device__ float g_f1[NN * FDIM];     // layer1 output
__device__ float g_f2[NN * FDIM];     // layer2 output
__device__ float g_alpha[NN * 2 * NH];// per-node alpha_src[0..3], alpha_dst[4..7]
__device__ float g_hw3[NN * 2];
__device__ float g_a3[NN * 2];

// ---------------- helpers ---------------------------------------------------
__device__ __forceinline__ float wmax(float v) {
    #pragma unroll
    for (int o = 16; o; o >>= 1) v = fmaxf(v, __shfl_xor_sync(0xffffffffu, v, o));
    return v;
}
__device__ __forceinline__ float wsum(float v) {
    #pragma unroll
    for (int o = 16; o; o >>= 1) v += __shfl_xor_sync(0xffffffffu, v, o);
    return v;
}

// ---------------- CSR construction ------------------------------------------
__global__ void k_zero_cnt() {
    int i = blockIdx.x * blockDim.x + threadIdx.x;
    if (i < NN) g_cnt[i] = 0;
}

__global__ void k_hist(const int* __restrict__ ei) {
    int e = blockIdx.x * blockDim.x + threadIdx.x;
    if (e >= ET) return;
    int dst = (e < EE) ? ei[EE + e] : (e - EE);
    atomicAdd(&g_cnt[dst], 1);
}

__global__ void k_scan_block() {
    __shared__ int sm[256];
    int i = blockIdx.x * 256 + threadIdx.x;
    int v = (i < NN) ? g_cnt[i] : 0;
    sm[threadIdx.x] = v;
    __syncthreads();
    #pragma unroll
    for (int o = 1; o < 256; o <<= 1) {
        int t = (threadIdx.x >= o) ? sm[threadIdx.x - o] : 0;
        __syncthreads();
        sm[threadIdx.x] += t;
        __syncthreads();
    }
    if (i < NN) g_rowptr[i] = sm[threadIdx.x] - v;       // exclusive, block-local
    if (threadIdx.x == 255) g_bsums[blockIdx.x] = sm[255];
}

__global__ void k_scan_tops(int nb) {
    __shared__ int sm[256];
    int v = (threadIdx.x < nb) ? g_bsums[threadIdx.x] : 0;
    sm[threadIdx.x] = v;
    __syncthreads();
    #pragma unroll
    for (int o = 1; o < 256; o <<= 1) {
        int t = (threadIdx.x >= o) ? sm[threadIdx.x - o] : 0;
        __syncthreads();
        sm[threadIdx.x] += t;
        __syncthreads();
    }
    g_bsums[threadIdx.x] = sm[threadIdx.x] - v;          // exclusive
}

__global__ void k_scan_finish() {
    int i = blockIdx.x * blockDim.x + threadIdx.x;
    if (i < NN) {
        int r = g_rowptr[i] + g_bsums[i >> 8];
        g_rowptr[i] = r;
        g_cursor[i] = r;
    }
    if (i == 0) g_rowptr[NN] = ET;
}

__global__ void k_scatter(const int* __restrict__ ei) {
    int e = blockIdx.x * blockDim.x + threadIdx.x;
    if (e >= ET) return;
    int src, dst;
    if (e < EE) { src = ei[e]; dst = ei[EE + e]; }
    else        { src = dst = e - EE; }
    int p = atomicAdd(&g_cursor[dst], 1);
    g_csr[p] = src;
}

// ---------------- GEMM: C[M,128] = A[M,128] @ W[128,128] --------------------
// 64x128 tile, 128 threads, 8x8 micro-tile per thread, scalar FFMA.
// A kept row-major [m][k] (pad 36 for aligned float4 stores + clean banks),
// W kept [k][n]. 10 LDS issues per 64 FFMAs per thread per kk.
__global__ void __launch_bounds__(128)
k_gemm128(const float* __restrict__ A, const float* __restrict__ W,
          float* __restrict__ C, int M) {
    __shared__ float As[64][36];     // [m][k] (+pad)   9 KB
    __shared__ float Ws[32][128];    // [k][n]         16 KB
    int t  = threadIdx.x;
    int tx = t & 15;                 // 8 cols each -> 128 cols
    int ty = t >> 4;                 // 8 rows each -> 64 rows
    int row0 = blockIdx.x * 64;

    float acc[8][8];
    #pragma unroll
    for (int r = 0; r < 8; r++)
        #pragma unroll
        for (int c = 0; c < 8; c++) acc[r][c] = 0.f;

    for (int k0 = 0; k0 < 128; k0 += 32) {
        #pragma unroll
        for (int i = 0; i < 4; i++) {
            int idx = i * 128 + t;           // 0..511 float4s of A tile
            int m = idx >> 3, kq = idx & 7;
            int gr = row0 + m;
            float4 v = (gr < M) ? *(const float4*)&A[gr * 128 + k0 + kq * 4]
                                : make_float4(0.f, 0.f, 0.f, 0.f);
            *(float4*)&As[m][kq * 4] = v;
        }
        #pragma unroll
        for (int i = 0; i < 8; i++) {
            int idx = i * 128 + t;           // 0..1023 float4s of W tile
            int r = idx >> 5, c4 = (idx & 31) * 4;
            *(float4*)&Ws[r][c4] = *(const float4*)&W[(k0 + r) * 128 + c4];
        }
        __syncthreads();
        #pragma unroll
        for (int kk = 0; kk < 32; kk++) {
            float a[8], b[8];
            #pragma unroll
            for (int r = 0; r < 8; r++) a[r] = As[ty * 8 + r][kk];
            float4 b0 = *(const float4*)&Ws[kk][tx * 8];
            float4 b1 = *(const float4*)&Ws[kk][tx * 8 + 4];
            b[0] = b0.x; b[1] = b0.y; b[2] = b0.z; b[3] = b0.w;
            b[4] = b1.x; b[5] = b1.y; b[6] = b1.z; b[7] = b1.w;
            #pragma unroll
            for (int r = 0; r < 8; r++)
                #pragma unroll
                for (int c = 0; c < 8; c++)
                    acc[r][c] += a[r] * b[c];
        }
        __syncthreads();
    }

    #pragma unroll
    for (int r = 0; r < 8; r++) {
        int gr = row0 + ty * 8 + r;
        if (gr < M) {
            *(float4*)&C[gr * 128 + tx * 8] =
                make_float4(acc[r][0], acc[r][1], acc[r][2], acc[r][3]);
            *(float4*)&C[gr * 128 + tx * 8 + 4] =
                make_float4(acc[r][4], acc[r][5], acc[r][6], acc[r][7]);
        }
    }
}

// ---------------- per-node alpha (H=4, C=32) --------------------------------
__global__ void k_alpha4(const float* __restrict__ hw,
                         const float* __restrict__ asrc,
                         const float* __restrict__ adst) {
    int n = (blockIdx.x * blockDim.x + threadIdx.x) >> 5;
    if (n >= NN) return;
    int lane = threadIdx.x & 31;
    #pragma unroll
    for (int h = 0; h < NH; h++) {
        float v  = hw[n * FDIM + h * CH + lane];
        float ps = wsum(v * asrc[h * CH + lane]);
        float pd = wsum(v * adst[h * CH + lane]);
        if (lane == 0) {
            g_alpha[n * 8 + h]     = ps;
            g_alpha[n * 8 + 4 + h] = pd;
        }
    }
}

// ---------------- edge softmax + aggregation (H=4, C=32) --------------------
// 2 passes: (1) lane-parallel max, (2) lane-parallel exp staged through smem,
// serially consumed with lane = channel. out = (sum_e e*h)/(sum_e e).
__global__ void k_aggregate4(const float* __restrict__ hw,
                             const float* __restrict__ bias,
                             float* __restrict__ out, int applyElu) {
    __shared__ float4 sm_e[8][32];
    __shared__ int    sm_s[8][32];
    int n = (blockIdx.x * blockDim.x + threadIdx.x) >> 5;
    if (n >= NN) return;
    int lane = threadIdx.x & 31;
    int wrp  = (threadIdx.x >> 5);
    int s0 = g_rowptr[n], s1 = g_rowptr[n + 1];
    float4 ad = *(const float4*)&g_alpha[n * 8 + 4];

    // pass 1: max of leakyrelu(alpha)
    float m0 = -3.4e38f, m1 = -3.4e38f, m2 = -3.4e38f, m3 = -3.4e38f;
    for (int i = s0 + lane; i < s1; i += 32) {
        int s = g_csr[i];
        float4 al = *(const float4*)&g_alpha[s * 8];
        float a;
        a = al.x + ad.x; a = (a > 0.f) ? a : NEG_SLOPE * a; m0 = fmaxf(m0, a);
        a = al.y + ad.y; a = (a > 0.f) ? a : NEG_SLOPE * a; m1 = fmaxf(m1, a);
        a = al.z + ad.z; a = (a > 0.f) ? a : NEG_SLOPE * a; m2 = fmaxf(m2, a);
        a = al.w + ad.w; a = (a > 0.f) ? a : NEG_SLOPE * a; m3 = fmaxf(m3, a);
    }
    m0 = wmax(m0); m1 = wmax(m1); m2 = wmax(m2); m3 = wmax(m3);

    // pass 2: exp (lane-parallel, staged in smem) + serial gather-accumulate
    float sum0 = 0.f, sum1 = 0.f, sum2 = 0.f, sum3 = 0.f;
    float acc0 = 0.f, acc1 = 0.f, acc2 = 0.f, acc3 = 0.f;
    for (int base = s0; base < s1; base += 32) {
        int i = base + lane;
        int s = 0;
        float4 e = make_float4(0.f, 0.f, 0.f, 0.f);
        if (i < s1) {
            s = g_csr[i];
            float4 al = *(const float4*)&g_alpha[s * 8];
            float a;
            a = al.x + ad.x; a = (a > 0.f) ? a : NEG_SLOPE * a; e.x = __expf(a - m0); sum0 += e.x;
            a = al.y + ad.y; a = (a > 0.f) ? a : NEG_SLOPE * a; e.y = __expf(a - m1); sum1 += e.y;
            a = al.z + ad.z; a = (a > 0.f) ? a : NEG_SLOPE * a; e.z = __expf(a - m2); sum2 += e.z;
            a = al.w + ad.w; a = (a > 0.f) ? a : NEG_SLOPE * a; e.w = __expf(a - m3); sum3 += e.w;
        }
        sm_s[wrp][lane] = s;
        sm_e[wrp][lane] = e;
        __syncwarp();
        int cnt = min(32, s1 - base);
        #pragma unroll 2
        for (int j = 0; j < cnt; j++) {
            int ss = sm_s[wrp][j];
            float4 ee = sm_e[wrp][j];
            const float* hp = hw + ss * FDIM + lane;
            acc0 += ee.x * hp[0];
            acc1 += ee.y * hp[32];
            acc2 += ee.z * hp[64];
            acc3 += ee.w * hp[96];
        }
        __syncwarp();
    }
    float inv0 = 1.f / wsum(sum0);
    float inv1 = 1.f / wsum(sum1);
    float inv2 = 1.f / wsum(sum2);
    float inv3 = 1.f / wsum(sum3);

    float v;
    v = acc0 * inv0 + bias[lane];
    if (applyElu) v = (v > 0.f) ? v : (__expf(v) - 1.f);
    out[n * FDIM + lane] = v;
    v = acc1 * inv1 + bias[32 + lane];
    if (applyElu) v = (v > 0.f) ? v : (__expf(v) - 1.f);
    out[n * FDIM + 32 + lane] = v;
    v = acc2 * inv2 + bias[64 + lane];
    if (applyElu) v = (v > 0.f) ? v : (__expf(v) - 1.f);
    out[n * FDIM + 64 + lane] = v;
    v = acc3 * inv3 + bias[96 + lane];
    if (applyElu) v = (v > 0.f) ? v : (__expf(v) - 1.f);
    out[n * FDIM + 96 + lane] = v;
}

// ---------------- layer 3: [N,128]@[128,2] + alphas -------------------------
__global__ void k_l3prep(const float* __restrict__ in, const float* __restrict__ W3,
                         const float* __restrict__ as3, const float* __restrict__ ad3) {
    int n = (blockIdx.x * blockDim.x + threadIdx.x) >> 5;
    if (n >= NN) return;
    int lane = threadIdx.x & 31;
    float4 v = *(const float4*)&in[n * FDIM + lane * 4];
    const float4 w0 = *(const float4*)&W3[2 * (lane * 4)];
    const float4 w1 = *(const float4*)&W3[2 * (lane * 4) + 4];
    float a0 = v.x * w0.x + v.y * w0.z + v.z * w1.x + v.w * w1.z;
    float a1 = v.x * w0.y + v.y * w0.w + v.z * w1.y + v.w * w1.w;
    a0 = wsum(a0); a1 = wsum(a1);
    if (lane == 0) {
        g_hw3[n * 2] = a0; g_hw3[n * 2 + 1] = a1;
        g_a3[n * 2]     = a0 * as3[0] + a1 * as3[1];
        g_a3[n * 2 + 1] = a0 * ad3[0] + a1 * ad3[1];
    }
}

// layer-3 aggregate (H=1,C=2) + bias + log_softmax (fully lane-parallel)
__global__ void k_aggregate1(const float* __restrict__ b3, float* __restrict__ out) {
    int n = (blockIdx.x * blockDim.x + threadIdx.x) >> 5;
    if (n >= NN) return;
    int lane = threadIdx.x & 31;
    int s0 = g_rowptr[n], s1 = g_rowptr[n + 1];
    float ad = g_a3[n * 2 + 1];

    float m = -3.4e38f;
    for (int i = s0 + lane; i < s1; i += 32) {
        int s = g_csr[i];
        float a = g_a3[s * 2] + ad;
        a = (a > 0.f) ? a : NEG_SLOPE * a;
        m = fmaxf(m, a);
    }
    m = wmax(m);

    float sum = 0.f, a0 = 0.f, a1 = 0.f;
    for (int i = s0 + lane; i < s1; i += 32) {
        int s = g_csr[i];
        float2 al = *(const float2*)&g_a3[s * 2];
        float a = al.x + ad;
        a = (a > 0.f) ? a : NEG_SLOPE * a;
        float e = __expf(a - m);
        sum += e;
        float2 h = *(const float2*)&g_hw3[s * 2];
        a0 += e * h.x;
        a1 += e * h.y;
    }
    sum = wsum(sum); a0 = wsum(a0); a1 = wsum(a1);

    if (lane == 0) {
        float inv = 1.f / sum;
        float z0 = a0 * inv + b3[0];
        float z1 = a1 * inv + b3[1];
        float mx = fmaxf(z0, z1);
        float l  = logf(__expf(z0 - mx) + __expf(z1 - mx));
        out[n * 2]     = z0 - mx - l;
        out[n * 2 + 1] = z1 - mx - l;
    }
}

// ---------------- host driver -----------------------------------------------
extern "C" void kernel_launch(void* const* d_in, const int* in_sizes, int n_in,
                              void* d_out, int out_size) {
    const float* x   = (const float*)d_in[0];
    const int*   ei  = (const int*)  d_in[1];
    const float* W1  = (const float*)d_in[2];
    const float* as1 = (const float*)d_in[3];
    const float* ad1 = (const float*)d_in[4];
    const float* b1  = (const float*)d_in[5];
    const float* W2  = (const float*)d_in[6];
    const float* as2 = (const float*)d_in[7];
    const float* ad2 = (const float*)d_in[8];
    const float* b2  = (const float*)d_in[9];
    const float* W3  = (const float*)d_in[10];
    const float* as3 = (const float*)d_in[11];
    const float* ad3 = (const float*)d_in[12];
    const float* b3  = (const float*)d_in[13];
    float* out = (float*)d_out;

    float *p_hw, *p_f1, *p_f2;
    cudaGetSymbolAddress((void**)&p_hw, g_hw);
    cudaGetSymbolAddress((void**)&p_f1, g_f1);
    cudaGetSymbolAddress((void**)&p_f2, g_f2);

    const int TPB = 256;
    int nbN  = (NN + TPB - 1) / TPB;          // 196
    int nbE  = (ET + TPB - 1) / TPB;          // 3321
    int nbW  = (NN * 32 + TPB - 1) / TPB;     // 6250 (warp per node)
    int nbG  = (NN + 63) / 64;                // 782 (gemm tiles)

    // CSR build interleaved with layer-1 GEMM/alpha (independent of CSR) so
    // the ncu -s window lands on an interesting kernel (positions 4..6).
    k_zero_cnt<<<nbN, TPB>>>();               // 1
    k_hist<<<nbE, TPB>>>(ei);                 // 2
    k_scan_block<<<nbN, TPB>>>();             // 3
    k_gemm128<<<nbG, 128>>>(x, W1, p_hw, NN); // 4   (needs only x, W1)
    k_scan_tops<<<1, 256>>>(nbN);             // 5
    k_alpha4<<<nbW, TPB>>>(p_hw, as1, ad1);   // 6   (needs gemm1)
    k_scan_finish<<<nbN, TPB>>>();            // 7
    k_scatter<<<nbE, TPB>>>(ei);              // 8

    // layer 1 aggregation (needs CSR + alpha)
    k_aggregate4<<<nbW, TPB>>>(p_hw, b1, p_f1, 1);

    // layer 2
    k_gemm128<<<nbG, 128>>>(p_f1, W2, p_hw, NN);
    k_alpha4<<<nbW, TPB>>>(p_hw, as2, ad2);
    k_aggregate4<<<nbW, TPB>>>(p_hw, b2, p_f2, 1);

    // layer 3
    k_l3prep<<<nbW, TPB>>>(p_f2, W3, as3, ad3);
    k_aggregate1<<<nbW, TPB>>>(b3, out);
}

// round 5
// speedup vs baseline: 1.3810x; 1.1643x over previous
#include <cuda_runtime.h>
#include <cuda_bf16.h>
#include <math.h>
#include <stdint.h>

#define NN   50000
#define EE   800000
#define ET   (EE + NN)      // 850000 edges incl. self loops
#define FDIM 128
#define NH   4
#define CH   32
#define NEG_SLOPE 0.2f

// ---------------- device scratch (module-load allocated, no cudaMalloc) ----
__device__ int   g_cnt[NN];
__device__ int   g_rowptr[NN + 1];
__device__ int   g_cursor[NN];
__device__ int   g_csr[ET];
__device__ int   g_bsums[256];

__device__ float g_hw[NN * FDIM];     // transformed features (current layer)
__device__ float g_f1[NN * FDIM];     // layer1 output
__device__ float g_f2[NN * FDIM];     // layer2 output
__device__ float g_alpha[NN * 2 * NH];// per-node alpha_src[0..3], alpha_dst[4..7]
__device__ float g_hw3[NN * 2];
__device__ float g_a3[NN * 2];

// pre-swizzled bf16 hi/lo planes of W, [n][k] layout (B operand), 32KB each
__device__ __align__(16) uint8_t g_wh[32768];
__device__ __align__(16) uint8_t g_wl[32768];

// ---------------- warp helpers ----------------------------------------------
__device__ __forceinline__ float wmax(float v) {
    #pragma unroll
    for (int o = 16; o; o >>= 1) v = fmaxf(v, __shfl_xor_sync(0xffffffffu, v, o));
    return v;
}
__device__ __forceinline__ float wsum(float v) {
    #pragma unroll
    for (int o = 16; o; o >>= 1) v += __shfl_xor_sync(0xffffffffu, v, o);
    return v;
}

// ---------------- mma helpers ------------------------------------------------
__device__ __forceinline__ uint32_t smem_u32(const void* p) {
    uint32_t a;
    asm("{ .reg .u64 tmp; cvta.to.shared.u64 tmp, %1; cvt.u32.u64 %0, tmp; }"
        : "=r"(a) : "l"(p));
    return a;
}
__device__ __forceinline__ void ldsm_x4(uint32_t& r0, uint32_t& r1,
                                        uint32_t& r2, uint32_t& r3, uint32_t addr) {
    asm volatile("ldmatrix.sync.aligned.m8n8.x4.shared.b16 {%0,%1,%2,%3}, [%4];"
                 : "=r"(r0), "=r"(r1), "=r"(r2), "=r"(r3) : "r"(addr));
}
__device__ __forceinline__ void mma16816(float* c, uint32_t a0, uint32_t a1,
                                         uint32_t a2, uint32_t a3,
                                         uint32_t b0, uint32_t b1) {
    asm volatile("mma.sync.aligned.m16n8k16.row.col.f32.bf16.bf16.f32 "
                 "{%0,%1,%2,%3}, {%4,%5,%6,%7}, {%8,%9}, {%0,%1,%2,%3};"
                 : "+f"(c[0]), "+f"(c[1]), "+f"(c[2]), "+f"(c[3])
                 : "r"(a0), "r"(a1), "r"(a2), "r"(a3), "r"(b0), "r"(b1));
}
// xor-swizzled byte offset: row r (256B rows of 128 bf16), 16B chunk kc (0..15)
__device__ __forceinline__ uint32_t soff(int r, int kc) {
    return (uint32_t)((r << 8) + ((kc ^ (r & 7)) << 4));
}
__device__ __forceinline__ uint32_t pkbf(float x, float y) {
    __nv_bfloat162 p;
    p.x = __float2bfloat16_rn(x);
    p.y = __float2bfloat16_rn(y);
    return *(uint32_t*)&p;
}

// ---------------- CSR construction ------------------------------------------
__global__ void k_zero_cnt() {
    int i = blockIdx.x * blockDim.x + threadIdx.x;
    if (i < NN) g_cnt[i] = 0;
}
__global__ void k_hist(const int* __restrict__ ei) {
    int e = blockIdx.x * blockDim.x + threadIdx.x;
    if (e >= ET) return;
    int dst = (e < EE) ? ei[EE + e] : (e - EE);
    atomicAdd(&g_cnt[dst], 1);
}
__global__ void k_scan_block() {
    __shared__ int sm[256];
    int i = blockIdx.x * 256 + threadIdx.x;
    int v = (i < NN) ? g_cnt[i] : 0;
    sm[threadIdx.x] = v;
    __syncthreads();
    #pragma unroll
    for (int o = 1; o < 256; o <<= 1) {
        int t = (threadIdx.x >= o) ? sm[threadIdx.x - o] : 0;
        __syncthreads();
        sm[threadIdx.x] += t;
        __syncthreads();
    }
    if (i < NN) g_rowptr[i] = sm[threadIdx.x] - v;
    if (threadIdx.x == 255) g_bsums[blockIdx.x] = sm[255];
}
__global__ void k_scan_tops(int nb) {
    __shared__ int sm[256];
    int v = (threadIdx.x < nb) ? g_bsums[threadIdx.x] : 0;
    sm[threadIdx.x] = v;
    __syncthreads();
    #pragma unroll
    for (int o = 1; o < 256; o <<= 1) {
        int t = (threadIdx.x >= o) ? sm[threadIdx.x - o] : 0;
        __syncthreads();
        sm[threadIdx.x] += t;
        __syncthreads();
    }
    g_bsums[threadIdx.x] = sm[threadIdx.x] - v;
}
__global__ void k_scan_finish() {
    int i = blockIdx.x * blockDim.x + threadIdx.x;
    if (i < NN) {
        int r = g_rowptr[i] + g_bsums[i >> 8];
        g_rowptr[i] = r;
        g_cursor[i] = r;
    }
    if (i == 0) g_rowptr[NN] = ET;
}
__global__ void k_scatter(const int* __restrict__ ei) {
    int e = blockIdx.x * blockDim.x + threadIdx.x;
    if (e >= ET) return;
    int src, dst;
    if (e < EE) { src = ei[e]; dst = ei[EE + e]; }
    else        { src = dst = e - EE; }
    int p = atomicAdd(&g_cursor[dst], 1);
    g_csr[p] = src;
}

// ---------------- W prep: fp32 [128k,128n] -> swizzled bf16 hi/lo [n][k] ----
__global__ void k_wprep(const float* __restrict__ W) {
    int i = blockIdx.x * blockDim.x + threadIdx.x;   // 2048 chunks
    if (i >= 2048) return;
    int n = i >> 4, kc = i & 15;
    uint32_t hp[4], lp[4];
    #pragma unroll
    for (int j = 0; j < 4; j++) {
        float w0 = W[(kc * 8 + 2 * j) * 128 + n];
        float w1 = W[(kc * 8 + 2 * j + 1) * 128 + n];
        __nv_bfloat16 h0 = __float2bfloat16_rn(w0);
        __nv_bfloat16 h1 = __float2bfloat16_rn(w1);
        __nv_bfloat162 hh; hh.x = h0; hh.y = h1;
        hp[j] = *(uint32_t*)&hh;
        lp[j] = pkbf(w0 - __bfloat162float(h0), w1 - __bfloat162float(h1));
    }
    uint32_t off = soff(n, kc);
    *(uint4*)(g_wh + off) = make_uint4(hp[0], hp[1], hp[2], hp[3]);
    *(uint4*)(g_wl + off) = make_uint4(lp[0], lp[1], lp[2], lp[3]);
}

// ---------------- tensor-core GEMM: C[M,128] = A[M,128] @ W ------------------
// fp32 via 3-term bf16 split: D = Ah*Wh + Al*Wh + Ah*Wl, mma.sync m16n8k16.
// 256 threads, 128x128 tile; warp (wm=wid&3, wn=wid>>2) -> 32 rows x 64 cols.
__global__ void __launch_bounds__(256)
k_gemm_mma(const float* __restrict__ A, float* __restrict__ C, int M) {
    extern __shared__ __align__(16) char smem[];
    const int S_AH = 0, S_AL = 32768, S_BH = 65536, S_BL = 98304;
    int t = threadIdx.x;
    int row0 = blockIdx.x * 128;
    uint32_t sb = smem_u32(smem);

    // copy pre-swizzled W planes (2 x 32KB)
    {
        const uint4* wh4 = (const uint4*)g_wh;
        const uint4* wl4 = (const uint4*)g_wl;
        uint4* bh = (uint4*)(smem + S_BH);
        uint4* bl = (uint4*)(smem + S_BL);
        #pragma unroll
        for (int i = 0; i < 8; i++) {
            bh[i * 256 + t] = wh4[i * 256 + t];
            bl[i * 256 + t] = wl4[i * 256 + t];
        }
    }
    // convert A rows -> bf16 hi/lo, swizzled [m][k]
    #pragma unroll
    for (int ii = 0; ii < 8; ii++) {
        int i = ii * 256 + t;
        int r = i >> 4, kc = i & 15;
        int gr = row0 + r;
        float4 v0 = make_float4(0.f, 0.f, 0.f, 0.f), v1 = v0;
        if (gr < M) {
            v0 = *(const float4*)&A[gr * 128 + kc * 8];
            v1 = *(const float4*)&A[gr * 128 + kc * 8 + 4];
        }
        __nv_bfloat162 h0, h1, h2, h3;
        h0.x = __float2bfloat16_rn(v0.x); h0.y = __float2bfloat16_rn(v0.y);
        h1.x = __float2bfloat16_rn(v0.z); h1.y = __float2bfloat16_rn(v0.w);
        h2.x = __float2bfloat16_rn(v1.x); h2.y = __float2bfloat16_rn(v1.y);
        h3.x = __float2bfloat16_rn(v1.z); h3.y = __float2bfloat16_rn(v1.w);
        uint32_t off = soff(r, kc);
        *(uint4*)(smem + S_AH + off) = make_uint4(*(uint32_t*)&h0, *(uint32_t*)&h1,
                                                  *(uint32_t*)&h2, *(uint32_t*)&h3);
        *(uint4*)(smem + S_AL + off) = make_uint4(
            pkbf(v0.x - __bfloat162float(h0.x), v0.y - __bfloat162float(h0.y)),
            pkbf(v0.z - __bfloat162float(h1.x), v0.w - __bfloat162float(h1.y)),
            pkbf(v1.x - __bfloat162float(h2.x), v1.y - __bfloat162float(h2.y)),
            pkbf(v1.z - __bfloat162float(h3.x), v1.w - __bfloat162float(h3.y)));
    }
    __syncthreads();

    int wid = t >> 5, lane = t & 31;
    int wm = wid & 3, wn = wid >> 2;

    float acc[2][8][4];
    #pragma unroll
    for (int mt = 0; mt < 2; mt++)
        #pragma unroll
        for (int nt = 0; nt < 8; nt++)
            #pragma unroll
            for (int q = 0; q < 4; q++) acc[mt][nt][q] = 0.f;

    // ldmatrix lane addressing
    int aRow = wm * 32 + (lane & 15);         // + mt*16
    int aSel = lane >> 4;                     // chunk +0/+1
    int bRow = wn * 64 + (lane & 7) + ((lane >> 4) << 3);   // + np*16
    int bSel = (lane >> 3) & 1;               // chunk +0/+1

    #pragma unroll
    for (int term = 0; term < 3; term++) {
        uint32_t aB = sb + ((term == 1) ? S_AL : S_AH);
        uint32_t bB = sb + ((term == 2) ? S_BL : S_BH);
        #pragma unroll
        for (int k16 = 0; k16 < 8; k16++) {
            int kc = k16 * 2;
            uint32_t a[2][4];
            #pragma unroll
            for (int mt = 0; mt < 2; mt++)
                ldsm_x4(a[mt][0], a[mt][1], a[mt][2], a[mt][3],
                        aB + soff(aRow + mt * 16, kc + aSel));
            #pragma unroll
            for (int np = 0; np < 4; np++) {
                uint32_t b0, b1, b2, b3;
                ldsm_x4(b0, b1, b2, b3, bB + soff(bRow + np * 16, kc + bSel));
                #pragma unroll
                for (int mt = 0; mt < 2; mt++) {
                    mma16816(acc[mt][np * 2],     a[mt][0], a[mt][1], a[mt][2], a[mt][3], b0, b1);
                    mma16816(acc[mt][np * 2 + 1], a[mt][0], a[mt][1], a[mt][2], a[mt][3], b2, b3);
                }
            }
        }
    }

    // epilogue: c0,c1 -> row groupID; c2,c3 -> row groupID+8
    #pragma unroll
    for (int mt = 0; mt < 2; mt++) {
        int rg = row0 + wm * 32 + mt * 16 + (lane >> 2);
        #pragma unroll
        for (int nt = 0; nt < 8; nt++) {
            int n = wn * 64 + nt * 8 + (lane & 3) * 2;
            if (rg < M)
                *(float2*)&C[rg * 128 + n] = make_float2(acc[mt][nt][0], acc[mt][nt][1]);
            if (rg + 8 < M)
                *(float2*)&C[(rg + 8) * 128 + n] = make_float2(acc[mt][nt][2], acc[mt][nt][3]);
        }
    }
}

// ---------------- per-node alpha (H=4, C=32) --------------------------------
__global__ void k_alpha4(const float* __restrict__ hw,
                         const float* __restrict__ asrc,
                         const float* __restrict__ adst) {
    int n = (blockIdx.x * blockDim.x + threadIdx.x) >> 5;
    if (n >= NN) return;
    int lane = threadIdx.x & 31;
    #pragma unroll
    for (int h = 0; h < NH; h++) {
        float v  = hw[n * FDIM + h * CH + lane];
        float ps = wsum(v * asrc[h * CH + lane]);
        float pd = wsum(v * adst[h * CH + lane]);
        if (lane == 0) {
            g_alpha[n * 8 + h]     = ps;
            g_alpha[n * 8 + 4 + h] = pd;
        }
    }
}

// ---------------- edge softmax + aggregation (H=4, C=32) --------------------
__global__ void k_aggregate4(const float* __restrict__ hw,
                             const float* __restrict__ bias,
                             float* __restrict__ out, int applyElu) {
    __shared__ float4 sm_e[8][32];
    __shared__ int    sm_s[8][32];
    int n = (blockIdx.x * blockDim.x + threadIdx.x) >> 5;
    if (n >= NN) return;
    int lane = threadIdx.x & 31;
    int wrp  = (threadIdx.x >> 5);
    int s0 = g_rowptr[n], s1 = g_rowptr[n + 1];
    float4 ad = *(const float4*)&g_alpha[n * 8 + 4];

    float m0 = -3.4e38f, m1 = -3.4e38f, m2 = -3.4e38f, m3 = -3.4e38f;
    for (int i = s0 + lane; i < s1; i += 32) {
        int s = g_csr[i];
        float4 al = *(const float4*)&g_alpha[s * 8];
        float a;
        a = al.x + ad.x; a = (a > 0.f) ? a : NEG_SLOPE * a; m0 = fmaxf(m0, a);
        a = al.y + ad.y; a = (a > 0.f) ? a : NEG_SLOPE * a; m1 = fmaxf(m1, a);
        a = al.z + ad.z; a = (a > 0.f) ? a : NEG_SLOPE * a; m2 = fmaxf(m2, a);
        a = al.w + ad.w; a = (a > 0.f) ? a : NEG_SLOPE * a; m3 = fmaxf(m3, a);
    }
    m0 = wmax(m0); m1 = wmax(m1); m2 = wmax(m2); m3 = wmax(m3);

    float sum0 = 0.f, sum1 = 0.f, sum2 = 0.f, sum3 = 0.f;
    float acc0 = 0.f, acc1 = 0.f, acc2 = 0.f, acc3 = 0.f;
    for (int base = s0; base < s1; base += 32) {
        int i = base + lane;
        int s = 0;
        float4 e = make_float4(0.f, 0.f, 0.f, 0.f);
        if (i < s1) {
            s = g_csr[i];
            float4 al = *(const float4*)&g_alpha[s * 8];
            float a;
            a = al.x + ad.x; a = (a > 0.f) ? a : NEG_SLOPE * a; e.x = __expf(a - m0); sum0 += e.x;
            a = al.y + ad.y; a = (a > 0.f) ? a : NEG_SLOPE * a; e.y = __expf(a - m1); sum1 += e.y;
            a = al.z + ad.z; a = (a > 0.f) ? a : NEG_SLOPE * a; e.z = __expf(a - m2); sum2 += e.z;
            a = al.w + ad.w; a = (a > 0.f) ? a : NEG_SLOPE * a; e.w = __expf(a - m3); sum3 += e.w;
        }
        sm_s[wrp][lane] = s;
        sm_e[wrp][lane] = e;
        __syncwarp();
        int cnt = min(32, s1 - base);
        #pragma unroll 2
        for (int j = 0; j < cnt; j++) {
            int ss = sm_s[wrp][j];
            float4 ee = sm_e[wrp][j];
            const float* hp = hw + ss * FDIM + lane;
            acc0 += ee.x * hp[0];
            acc1 += ee.y * hp[32];
            acc2 += ee.z * hp[64];
            acc3 += ee.w * hp[96];
        }
        __syncwarp();
    }
    float inv0 = 1.f / wsum(sum0);
    float inv1 = 1.f / wsum(sum1);
    float inv2 = 1.f / wsum(sum2);
    float inv3 = 1.f / wsum(sum3);

    float v;
    v = acc0 * inv0 + bias[lane];
    if (applyElu) v = (v > 0.f) ? v : (__expf(v) - 1.f);
    out[n * FDIM + lane] = v;
    v = acc1 * inv1 + bias[32 + lane];
    if (applyElu) v = (v > 0.f) ? v : (__expf(v) - 1.f);
    out[n * FDIM + 32 + lane] = v;
    v = acc2 * inv2 + bias[64 + lane];
    if (applyElu) v = (v > 0.f) ? v : (__expf(v) - 1.f);
    out[n * FDIM + 64 + lane] = v;
    v = acc3 * inv3 + bias[96 + lane];
    if (applyElu) v = (v > 0.f) ? v : (__expf(v) - 1.f);
    out[n * FDIM + 96 + lane] = v;
}

// ---------------- layer 3 ----------------------------------------------------
__global__ void k_l3prep(const float* __restrict__ in, const float* __restrict__ W3,
                         const float* __restrict__ as3, const float* __restrict__ ad3) {
    int n = (blockIdx.x * blockDim.x + threadIdx.x) >> 5;
    if (n >= NN) return;
    int lane = threadIdx.x & 31;
    float4 v = *(const float4*)&in[n * FDIM + lane * 4];
    const float4 w0 = *(const float4*)&W3[2 * (lane * 4)];
    const float4 w1 = *(const float4*)&W3[2 * (lane * 4) + 4];
    float a0 = v.x * w0.x + v.y * w0.z + v.z * w1.x + v.w * w1.z;
    float a1 = v.x * w0.y + v.y * w0.w + v.z * w1.y + v.w * w1.w;
    a0 = wsum(a0); a1 = wsum(a1);
    if (lane == 0) {
        g_hw3[n * 2] = a0; g_hw3[n * 2 + 1] = a1;
        g_a3[n * 2]     = a0 * as3[0] + a1 * as3[1];
        g_a3[n * 2 + 1] = a0 * ad3[0] + a1 * ad3[1];
    }
}

__global__ void k_aggregate1(const float* __restrict__ b3, float* __restrict__ out) {
    int n = (blockIdx.x * blockDim.x + threadIdx.x) >> 5;
    if (n >= NN) return;
    int lane = threadIdx.x & 31;
    int s0 = g_rowptr[n], s1 = g_rowptr[n + 1];
    float ad = g_a3[n * 2 + 1];

    float m = -3.4e38f;
    for (int i = s0 + lane; i < s1; i += 32) {
        int s = g_csr[i];
        float a = g_a3[s * 2] + ad;
        a = (a > 0.f) ? a : NEG_SLOPE * a;
        m = fmaxf(m, a);
    }
    m = wmax(m);

    float sum = 0.f, a0 = 0.f, a1 = 0.f;
    for (int i = s0 + lane; i < s1; i += 32) {
        int s = g_csr[i];
        float2 al = *(const float2*)&g_a3[s * 2];
        float a = al.x + ad;
        a = (a > 0.f) ? a : NEG_SLOPE * a;
        float e = __expf(a - m);
        sum += e;
        float2 h = *(const float2*)&g_hw3[s * 2];
        a0 += e * h.x;
        a1 += e * h.y;
    }
    sum = wsum(sum); a0 = wsum(a0); a1 = wsum(a1);

    if (lane == 0) {
        float inv = 1.f / sum;
        float z0 = a0 * inv + b3[0];
        float z1 = a1 * inv + b3[1];
        float mx = fmaxf(z0, z1);
        float l  = logf(__expf(z0 - mx) + __expf(z1 - mx));
        out[n * 2]     = z0 - mx - l;
        out[n * 2 + 1] = z1 - mx - l;
    }
}

// ---------------- host driver -----------------------------------------------
extern "C" void kernel_launch(void* const* d_in, const int* in_sizes, int n_in,
                              void* d_out, int out_size) {
    const float* x   = (const float*)d_in[0];
    const int*   ei  = (const int*)  d_in[1];
    const float* W1  = (const float*)d_in[2];
    const float* as1 = (const float*)d_in[3];
    const float* ad1 = (const float*)d_in[4];
    const float* b1  = (const float*)d_in[5];
    const float* W2  = (const float*)d_in[6];
    const float* as2 = (const float*)d_in[7];
    const float* ad2 = (const float*)d_in[8];
    const float* b2  = (const float*)d_in[9];
    const float* W3  = (const float*)d_in[10];
    const float* as3 = (const float*)d_in[11];
    const float* ad3 = (const float*)d_in[12];
    const float* b3  = (const float*)d_in[13];
    float* out = (float*)d_out;

    float *p_hw, *p_f1, *p_f2;
    cudaGetSymbolAddress((void**)&p_hw, g_hw);
    cudaGetSymbolAddress((void**)&p_f1, g_f1);
    cudaGetSymbolAddress((void**)&p_f2, g_f2);

    const int GEMM_SMEM = 131072;    // 4 x 32KB
    cudaFuncSetAttribute(k_gemm_mma, cudaFuncAttributeMaxDynamicSharedMemorySize, GEMM_SMEM);

    const int TPB = 256;
    int nbN = (NN + TPB - 1) / TPB;           // 196
    int nbE = (ET + TPB - 1) / TPB;           // 3321
    int nbW = (NN * 32 + TPB - 1) / TPB;      // 6250 (warp per node)
    int nbT = (NN + 127) / 128;               // 391 gemm tiles

    // CSR build interleaved so ncu -s window lands on k_gemm_mma (pos 5)
    k_zero_cnt<<<nbN, TPB>>>();                               // 1
    k_hist<<<nbE, TPB>>>(ei);                                 // 2
    k_scan_block<<<nbN, TPB>>>();                             // 3
    k_wprep<<<16, 128>>>(W1);                                 // 4
    k_gemm_mma<<<nbT, 256, GEMM_SMEM>>>(x, p_hw, NN);         // 5
    k_scan_tops<<<1, 256>>>(nbN);                             // 6
    k_alpha4<<<nbW, TPB>>>(p_hw, as1, ad1);                   // 7
    k_scan_finish<<<nbN, TPB>>>();                            // 8
    k_scatter<<<nbE, TPB>>>(ei);                              // 9

    // layer 1 aggregation
    k_aggregate4<<<nbW, TPB>>>(p_hw, b1, p_f1, 1);

    // layer 2
    k_wprep<<<16, 128>>>(W2);
    k_gemm_mma<<<nbT, 256, GEMM_SMEM>>>(p_f1, p_hw, NN);
    k_alpha4<<<nbW, TPB>>>(p_hw, as2, ad2);
    k_aggregate4<<<nbW, TPB>>>(p_hw, b2, p_f2, 1);

    // layer 3
    k_l3prep<<<nbW, TPB>>>(p_f2, W3, as3, ad3);
    k_aggregate1<<<nbW, TPB>>>(b3, out);
}

// round 6
// speedup vs baseline: 1.5970x; 1.1563x over previous
#include <cuda_runtime.h>
#include <cuda_bf16.h>
#include <math.h>
#include <stdint.h>

#define NN   50000
#define EE   800000
#define ET   (EE + NN)      // 850000 edges incl. self loops
#define FDIM 128
#define NH   4
#define CH   32
#define NEG_SLOPE 0.2f

// ---------------- device scratch (module-load allocated, no cudaMalloc) ----
__device__ int   g_cnt[NN];
__device__ int   g_rowptr[NN + 1];
__device__ int   g_cursor[NN];
__device__ int   g_csr[ET];
__device__ int   g_bsums[256];

__device__ float g_hw[NN * FDIM];     // transformed features (current layer)
__device__ float g_f1[NN * FDIM];     // layer1 output
__device__ float g_f2[NN * FDIM];     // layer2 output
__device__ float g_alpha[NN * 2 * NH];// per-node alpha_src[0..3], alpha_dst[4..7]
__device__ float g_hw3[NN * 2];
__device__ float g_a3[NN * 2];

// pre-swizzled bf16 hi/lo planes of W, [n][k] layout (B operand), 32KB each
__device__ __align__(16) uint8_t g_wh[32768];
__device__ __align__(16) uint8_t g_wl[32768];

// ---------------- warp helpers ----------------------------------------------
__device__ __forceinline__ float wsum(float v) {
    #pragma unroll
    for (int o = 16; o; o >>= 1) v += __shfl_xor_sync(0xffffffffu, v, o);
    return v;
}

// ---------------- mma helpers ------------------------------------------------
__device__ __forceinline__ uint32_t smem_u32(const void* p) {
    uint32_t a;
    asm("{ .reg .u64 tmp; cvta.to.shared.u64 tmp, %1; cvt.u32.u64 %0, tmp; }"
        : "=r"(a) : "l"(p));
    return a;
}
__device__ __forceinline__ void ldsm_x4(uint32_t& r0, uint32_t& r1,
                                        uint32_t& r2, uint32_t& r3, uint32_t addr) {
    asm volatile("ldmatrix.sync.aligned.m8n8.x4.shared.b16 {%0,%1,%2,%3}, [%4];"
                 : "=r"(r0), "=r"(r1), "=r"(r2), "=r"(r3) : "r"(addr));
}
__device__ __forceinline__ void mma16816(float* c, uint32_t a0, uint32_t a1,
                                         uint32_t a2, uint32_t a3,
                                         uint32_t b0, uint32_t b1) {
    asm volatile("mma.sync.aligned.m16n8k16.row.col.f32.bf16.bf16.f32 "
                 "{%0,%1,%2,%3}, {%4,%5,%6,%7}, {%8,%9}, {%0,%1,%2,%3};"
                 : "+f"(c[0]), "+f"(c[1]), "+f"(c[2]), "+f"(c[3])
                 : "r"(a0), "r"(a1), "r"(a2), "r"(a3), "r"(b0), "r"(b1));
}
// xor-swizzled byte offset: row r (256B rows of 128 bf16), 16B chunk kc (0..15)
__device__ __forceinline__ uint32_t soff(int r, int kc) {
    return (uint32_t)((r << 8) + ((kc ^ (r & 7)) << 4));
}
__device__ __forceinline__ uint32_t pkbf(float x, float y) {
    __nv_bfloat162 p;
    p.x = __float2bfloat16_rn(x);
    p.y = __float2bfloat16_rn(y);
    return *(uint32_t*)&p;
}

// ---------------- CSR construction ------------------------------------------
__global__ void k_zero_cnt() {
    int i = blockIdx.x * blockDim.x + threadIdx.x;
    if (i < NN) g_cnt[i] = 0;
}
__global__ void k_hist(const int* __restrict__ ei) {
    int e = blockIdx.x * blockDim.x + threadIdx.x;
    if (e >= ET) return;
    int dst = (e < EE) ? ei[EE + e] : (e - EE);
    atomicAdd(&g_cnt[dst], 1);
}
__global__ void k_scan_block() {
    __shared__ int sm[256];
    int i = blockIdx.x * 256 + threadIdx.x;
    int v = (i < NN) ? g_cnt[i] : 0;
    sm[threadIdx.x] = v;
    __syncthreads();
    #pragma unroll
    for (int o = 1; o < 256; o <<= 1) {
        int t = (threadIdx.x >= o) ? sm[threadIdx.x - o] : 0;
        __syncthreads();
        sm[threadIdx.x] += t;
        __syncthreads();
    }
    if (i < NN) g_rowptr[i] = sm[threadIdx.x] - v;
    if (threadIdx.x == 255) g_bsums[blockIdx.x] = sm[255];
}
__global__ void k_scan_tops(int nb) {
    __shared__ int sm[256];
    int v = (threadIdx.x < nb) ? g_bsums[threadIdx.x] : 0;
    sm[threadIdx.x] = v;
    __syncthreads();
    #pragma unroll
    for (int o = 1; o < 256; o <<= 1) {
        int t = (threadIdx.x >= o) ? sm[threadIdx.x - o] : 0;
        __syncthreads();
        sm[threadIdx.x] += t;
        __syncthreads();
    }
    g_bsums[threadIdx.x] = sm[threadIdx.x] - v;
}
__global__ void k_scan_finish() {
    int i = blockIdx.x * blockDim.x + threadIdx.x;
    if (i < NN) {
        int r = g_rowptr[i] + g_bsums[i >> 8];
        g_rowptr[i] = r;
        g_cursor[i] = r;
    }
    if (i == 0) g_rowptr[NN] = ET;
}
__global__ void k_scatter(const int* __restrict__ ei) {
    int e = blockIdx.x * blockDim.x + threadIdx.x;
    if (e >= ET) return;
    int src, dst;
    if (e < EE) { src = ei[e]; dst = ei[EE + e]; }
    else        { src = dst = e - EE; }
    int p = atomicAdd(&g_cursor[dst], 1);
    g_csr[p] = src;
}

// ---------------- W prep: fp32 [128k,128n] -> swizzled bf16 hi/lo [n][k] ----
__global__ void k_wprep(const float* __restrict__ W) {
    int i = blockIdx.x * blockDim.x + threadIdx.x;   // 2048 chunks
    if (i >= 2048) return;
    int n = i >> 4, kc = i & 15;
    uint32_t hp[4], lp[4];
    #pragma unroll
    for (int j = 0; j < 4; j++) {
        float w0 = W[(kc * 8 + 2 * j) * 128 + n];
        float w1 = W[(kc * 8 + 2 * j + 1) * 128 + n];
        __nv_bfloat16 h0 = __float2bfloat16_rn(w0);
        __nv_bfloat16 h1 = __float2bfloat16_rn(w1);
        __nv_bfloat162 hh; hh.x = h0; hh.y = h1;
        hp[j] = *(uint32_t*)&hh;
        lp[j] = pkbf(w0 - __bfloat162float(h0), w1 - __bfloat162float(h1));
    }
    uint32_t off = soff(n, kc);
    *(uint4*)(g_wh + off) = make_uint4(hp[0], hp[1], hp[2], hp[3]);
    *(uint4*)(g_wl + off) = make_uint4(lp[0], lp[1], lp[2], lp[3]);
}

// ---------------- tensor-core GEMM + fused per-node alpha -------------------
// C[M,128] = A[M,128] @ W; fp32 via 3-term bf16 split.
// Epilogue computes alpha_src/alpha_dst per head from register accumulators.
__global__ void __launch_bounds__(256)
k_gemm_mma(const float* __restrict__ A,
           const float* __restrict__ asrc, const float* __restrict__ adst,
           float* __restrict__ C, int M) {
    extern __shared__ __align__(16) char smem[];
    const int S_AH = 0, S_AL = 32768, S_BH = 65536, S_BL = 98304, S_ATT = 131072;
    int t = threadIdx.x;
    int row0 = blockIdx.x * 128;
    uint32_t sb = smem_u32(smem);
    float* att_s = (float*)(smem + S_ATT);      // [0..127] asrc, [128..255] adst

    if (t < 128)      att_s[t] = asrc[t];
    else              att_s[128 + (t - 128)] = adst[t - 128];

    // copy pre-swizzled W planes (2 x 32KB)
    {
        const uint4* wh4 = (const uint4*)g_wh;
        const uint4* wl4 = (const uint4*)g_wl;
        uint4* bh = (uint4*)(smem + S_BH);
        uint4* bl = (uint4*)(smem + S_BL);
        #pragma unroll
        for (int i = 0; i < 8; i++) {
            bh[i * 256 + t] = wh4[i * 256 + t];
            bl[i * 256 + t] = wl4[i * 256 + t];
        }
    }
    // convert A rows -> bf16 hi/lo, swizzled [m][k]
    #pragma unroll
    for (int ii = 0; ii < 8; ii++) {
        int i = ii * 256 + t;
        int r = i >> 4, kc = i & 15;
        int gr = row0 + r;
        float4 v0 = make_float4(0.f, 0.f, 0.f, 0.f), v1 = v0;
        if (gr < M) {
            v0 = *(const float4*)&A[gr * 128 + kc * 8];
            v1 = *(const float4*)&A[gr * 128 + kc * 8 + 4];
        }
        __nv_bfloat162 h0, h1, h2, h3;
        h0.x = __float2bfloat16_rn(v0.x); h0.y = __float2bfloat16_rn(v0.y);
        h1.x = __float2bfloat16_rn(v0.z); h1.y = __float2bfloat16_rn(v0.w);
        h2.x = __float2bfloat16_rn(v1.x); h2.y = __float2bfloat16_rn(v1.y);
        h3.x = __float2bfloat16_rn(v1.z); h3.y = __float2bfloat16_rn(v1.w);
        uint32_t off = soff(r, kc);
        *(uint4*)(smem + S_AH + off) = make_uint4(*(uint32_t*)&h0, *(uint32_t*)&h1,
                                                  *(uint32_t*)&h2, *(uint32_t*)&h3);
        *(uint4*)(smem + S_AL + off) = make_uint4(
            pkbf(v0.x - __bfloat162float(h0.x), v0.y - __bfloat162float(h0.y)),
            pkbf(v0.z - __bfloat162float(h1.x), v0.w - __bfloat162float(h1.y)),
            pkbf(v1.x - __bfloat162float(h2.x), v1.y - __bfloat162float(h2.y)),
            pkbf(v1.z - __bfloat162float(h3.x), v1.w - __bfloat162float(h3.y)));
    }
    __syncthreads();

    int wid = t >> 5, lane = t & 31;
    int wm = wid & 3, wn = wid >> 2;

    float acc[2][8][4];
    #pragma unroll
    for (int mt = 0; mt < 2; mt++)
        #pragma unroll
        for (int nt = 0; nt < 8; nt++)
            #pragma unroll
            for (int q = 0; q < 4; q++) acc[mt][nt][q] = 0.f;

    int aRow = wm * 32 + (lane & 15);
    int aSel = lane >> 4;
    int bRow = wn * 64 + (lane & 7) + ((lane >> 4) << 3);
    int bSel = (lane >> 3) & 1;

    #pragma unroll
    for (int term = 0; term < 3; term++) {
        uint32_t aB = sb + ((term == 1) ? S_AL : S_AH);
        uint32_t bB = sb + ((term == 2) ? S_BL : S_BH);
        #pragma unroll
        for (int k16 = 0; k16 < 8; k16++) {
            int kc = k16 * 2;
            uint32_t a[2][4];
            #pragma unroll
            for (int mt = 0; mt < 2; mt++)
                ldsm_x4(a[mt][0], a[mt][1], a[mt][2], a[mt][3],
                        aB + soff(aRow + mt * 16, kc + aSel));
            #pragma unroll
            for (int np = 0; np < 4; np++) {
                uint32_t b0, b1, b2, b3;
                ldsm_x4(b0, b1, b2, b3, bB + soff(bRow + np * 16, kc + bSel));
                #pragma unroll
                for (int mt = 0; mt < 2; mt++) {
                    mma16816(acc[mt][np * 2],     a[mt][0], a[mt][1], a[mt][2], a[mt][3], b0, b1);
                    mma16816(acc[mt][np * 2 + 1], a[mt][0], a[mt][1], a[mt][2], a[mt][3], b2, b3);
                }
            }
        }
    }

    // epilogue: store C + fused alpha (each head fully inside this warp's cols)
    #pragma unroll
    for (int mt = 0; mt < 2; mt++) {
        int rg = row0 + wm * 32 + mt * 16 + (lane >> 2);
        #pragma unroll
        for (int nt = 0; nt < 8; nt++) {
            int n = wn * 64 + nt * 8 + (lane & 3) * 2;
            if (rg < M)
                *(float2*)&C[rg * 128 + n] = make_float2(acc[mt][nt][0], acc[mt][nt][1]);
            if (rg + 8 < M)
                *(float2*)&C[(rg + 8) * 128 + n] = make_float2(acc[mt][nt][2], acc[mt][nt][3]);
        }
        #pragma unroll
        for (int hh = 0; hh < 2; hh++) {
            float ps0 = 0.f, pd0 = 0.f, ps1 = 0.f, pd1 = 0.f;
            #pragma unroll
            for (int j = 0; j < 4; j++) {
                int nt = hh * 4 + j;
                int n = wn * 64 + nt * 8 + (lane & 3) * 2;
                float w0s = att_s[n], w1s = att_s[n + 1];
                float w0d = att_s[128 + n], w1d = att_s[128 + n + 1];
                ps0 += acc[mt][nt][0] * w0s + acc[mt][nt][1] * w1s;
                pd0 += acc[mt][nt][0] * w0d + acc[mt][nt][1] * w1d;
                ps1 += acc[mt][nt][2] * w0s + acc[mt][nt][3] * w1s;
                pd1 += acc[mt][nt][2] * w0d + acc[mt][nt][3] * w1d;
            }
            #pragma unroll
            for (int o = 1; o <= 2; o <<= 1) {
                ps0 += __shfl_xor_sync(0xffffffffu, ps0, o);
                pd0 += __shfl_xor_sync(0xffffffffu, pd0, o);
                ps1 += __shfl_xor_sync(0xffffffffu, ps1, o);
                pd1 += __shfl_xor_sync(0xffffffffu, pd1, o);
            }
            if ((lane & 3) == 0) {
                int h = 2 * wn + hh;
                if (rg < M) {
                    g_alpha[rg * 8 + h]     = ps0;
                    g_alpha[rg * 8 + 4 + h] = pd0;
                }
                if (rg + 8 < M) {
                    g_alpha[(rg + 8) * 8 + h]     = ps1;
                    g_alpha[(rg + 8) * 8 + 4 + h] = pd1;
                }
            }
        }
    }
}

// ---------------- edge softmax + aggregation (H=4, C=32) --------------------
// Single edge pass (no max-shift: alphas are O(1), exp cannot overflow).
// out = (sum_e e*h)/(sum_e e); exp lane-parallel, gather serially via smem.
__global__ void k_aggregate4(const float* __restrict__ hw,
                             const float* __restrict__ bias,
                             float* __restrict__ out, int applyElu) {
    __shared__ float4 sm_e[8][32];
    __shared__ int    sm_s[8][32];
    int n = (blockIdx.x * blockDim.x + threadIdx.x) >> 5;
    if (n >= NN) return;
    int lane = threadIdx.x & 31;
    int wrp  = (threadIdx.x >> 5);
    int s0 = g_rowptr[n], s1 = g_rowptr[n + 1];
    float4 ad = *(const float4*)&g_alpha[n * 8 + 4];

    float sum0 = 0.f, sum1 = 0.f, sum2 = 0.f, sum3 = 0.f;
    float acc0 = 0.f, acc1 = 0.f, acc2 = 0.f, acc3 = 0.f;
    for (int base = s0; base < s1; base += 32) {
        int i = base + lane;
        int s = 0;
        float4 e = make_float4(0.f, 0.f, 0.f, 0.f);
        if (i < s1) {
            s = g_csr[i];
            float4 al = *(const float4*)&g_alpha[s * 8];
            float a;
            a = al.x + ad.x; a = (a > 0.f) ? a : NEG_SLOPE * a; e.x = __expf(a); sum0 += e.x;
            a = al.y + ad.y; a = (a > 0.f) ? a : NEG_SLOPE * a; e.y = __expf(a); sum1 += e.y;
            a = al.z + ad.z; a = (a > 0.f) ? a : NEG_SLOPE * a; e.z = __expf(a); sum2 += e.z;
            a = al.w + ad.w; a = (a > 0.f) ? a : NEG_SLOPE * a; e.w = __expf(a); sum3 += e.w;
        }
        sm_s[wrp][lane] = s;
        sm_e[wrp][lane] = e;
        __syncwarp();
        int cnt = min(32, s1 - base);
        #pragma unroll 2
        for (int j = 0; j < cnt; j++) {
            int ss = sm_s[wrp][j];
            float4 ee = sm_e[wrp][j];
            const float* hp = hw + ss * FDIM + lane;
            acc0 += ee.x * hp[0];
            acc1 += ee.y * hp[32];
            acc2 += ee.z * hp[64];
            acc3 += ee.w * hp[96];
        }
        __syncwarp();
    }
    float inv0 = 1.f / wsum(sum0);
    float inv1 = 1.f / wsum(sum1);
    float inv2 = 1.f / wsum(sum2);
    float inv3 = 1.f / wsum(sum3);

    float v;
    v = acc0 * inv0 + bias[lane];
    if (applyElu) v = (v > 0.f) ? v : (__expf(v) - 1.f);
    out[n * FDIM + lane] = v;
    v = acc1 * inv1 + bias[32 + lane];
    if (applyElu) v = (v > 0.f) ? v : (__expf(v) - 1.f);
    out[n * FDIM + 32 + lane] = v;
    v = acc2 * inv2 + bias[64 + lane];
    if (applyElu) v = (v > 0.f) ? v : (__expf(v) - 1.f);
    out[n * FDIM + 64 + lane] = v;
    v = acc3 * inv3 + bias[96 + lane];
    if (applyElu) v = (v > 0.f) ? v : (__expf(v) - 1.f);
    out[n * FDIM + 96 + lane] = v;
}

// ---------------- layer 3 ----------------------------------------------------
__global__ void k_l3prep(const float* __restrict__ in, const float* __restrict__ W3,
                         const float* __restrict__ as3, const float* __restrict__ ad3) {
    int n = (blockIdx.x * blockDim.x + threadIdx.x) >> 5;
    if (n >= NN) return;
    int lane = threadIdx.x & 31;
    float4 v = *(const float4*)&in[n * FDIM + lane * 4];
    const float4 w0 = *(const float4*)&W3[2 * (lane * 4)];
    const float4 w1 = *(const float4*)&W3[2 * (lane * 4) + 4];
    float a0 = v.x * w0.x + v.y * w0.z + v.z * w1.x + v.w * w1.z;
    float a1 = v.x * w0.y + v.y * w0.w + v.z * w1.y + v.w * w1.w;
    a0 = wsum(a0); a1 = wsum(a1);
    if (lane == 0) {
        g_hw3[n * 2] = a0; g_hw3[n * 2 + 1] = a1;
        g_a3[n * 2]     = a0 * as3[0] + a1 * as3[1];
        g_a3[n * 2 + 1] = a0 * ad3[0] + a1 * ad3[1];
    }
}

// layer-3 aggregate (H=1,C=2) + bias + log_softmax, single edge pass
__global__ void k_aggregate1(const float* __restrict__ b3, float* __restrict__ out) {
    int n = (blockIdx.x * blockDim.x + threadIdx.x) >> 5;
    if (n >= NN) return;
    int lane = threadIdx.x & 31;
    int s0 = g_rowptr[n], s1 = g_rowptr[n + 1];
    float ad = g_a3[n * 2 + 1];

    float sum = 0.f, a0 = 0.f, a1 = 0.f;
    for (int i = s0 + lane; i < s1; i += 32) {
        int s = g_csr[i];
        float2 al = *(const float2*)&g_a3[s * 2];
        float a = al.x + ad;
        a = (a > 0.f) ? a : NEG_SLOPE * a;
        float e = __expf(a);
        sum += e;
        float2 h = *(const float2*)&g_hw3[s * 2];
        a0 += e * h.x;
        a1 += e * h.y;
    }
    sum = wsum(sum); a0 = wsum(a0); a1 = wsum(a1);

    if (lane == 0) {
        float inv = 1.f / sum;
        float z0 = a0 * inv + b3[0];
        float z1 = a1 * inv + b3[1];
        float mx = fmaxf(z0, z1);
        float l  = logf(__expf(z0 - mx) + __expf(z1 - mx));
        out[n * 2]     = z0 - mx - l;
        out[n * 2 + 1] = z1 - mx - l;
    }
}

// ---------------- host driver -----------------------------------------------
extern "C" void kernel_launch(void* const* d_in, const int* in_sizes, int n_in,
                              void* d_out, int out_size) {
    const float* x   = (const float*)d_in[0];
    const int*   ei  = (const int*)  d_in[1];
    const float* W1  = (const float*)d_in[2];
    const float* as1 = (const float*)d_in[3];
    const float* ad1 = (const float*)d_in[4];
    const float* b1  = (const float*)d_in[5];
    const float* W2  = (const float*)d_in[6];
    const float* as2 = (const float*)d_in[7];
    const float* ad2 = (const float*)d_in[8];
    const float* b2  = (const float*)d_in[9];
    const float* W3  = (const float*)d_in[10];
    const float* as3 = (const float*)d_in[11];
    const float* ad3 = (const float*)d_in[12];
    const float* b3  = (const float*)d_in[13];
    float* out = (float*)d_out;

    float *p_hw, *p_f1, *p_f2;
    cudaGetSymbolAddress((void**)&p_hw, g_hw);
    cudaGetSymbolAddress((void**)&p_f1, g_f1);
    cudaGetSymbolAddress((void**)&p_f2, g_f2);

    const int GEMM_SMEM = 131072 + 1024;    // 4 x 32KB + att vectors
    cudaFuncSetAttribute(k_gemm_mma, cudaFuncAttributeMaxDynamicSharedMemorySize, GEMM_SMEM);

    const int TPB = 256;
    int nbN = (NN + TPB - 1) / TPB;           // 196
    int nbE = (ET + TPB - 1) / TPB;           // 3321
    int nbW = (NN * 32 + TPB - 1) / TPB;      // 6250 (warp per node)
    int nbT = (NN + 127) / 128;               // 391 gemm tiles

    // order chosen so the profiled launch (0-based index 3) is k_gemm_mma
    k_wprep<<<16, 128>>>(W1);                                    // 0
    k_zero_cnt<<<nbN, TPB>>>();                                  // 1
    k_hist<<<nbE, TPB>>>(ei);                                    // 2
    k_gemm_mma<<<nbT, 256, GEMM_SMEM>>>(x, as1, ad1, p_hw, NN);  // 3  <- profiled
    k_scan_block<<<nbN, TPB>>>();                                // 4
    k_scan_tops<<<1, 256>>>(nbN);                                // 5
    k_scan_finish<<<nbN, TPB>>>();                               // 6
    k_scatter<<<nbE, TPB>>>(ei);                                 // 7

    // layer 1 aggregation
    k_aggregate4<<<nbW, TPB>>>(p_hw, b1, p_f1, 1);

    // layer 2
    k_wprep<<<16, 128>>>(W2);
    k_gemm_mma<<<nbT, 256, GEMM_SMEM>>>(p_f1, as2, ad2, p_hw, NN);
    k_aggregate4<<<nbW, TPB>>>(p_hw, b2, p_f2, 1);

    // layer 3
    k_l3prep<<<nbW, TPB>>>(p_f2, W3, as3, ad3);
    k_aggregate1<<<nbW, TPB>>>(b3, out);
}

// round 7
// speedup vs baseline: 1.6586x; 1.0386x over previous
#include <cuda_runtime.h>
#include <cuda_bf16.h>
#include <cuda_fp16.h>
#include <math.h>
#include <stdint.h>

#define NN   50000
#define EE   800000
#define ET   (EE + NN)      // 850000 edges incl. self loops
#define FDIM 128
#define NH   4
#define CH   32
#define NEG_SLOPE 0.2f

// ---------------- device scratch (module-load allocated, no cudaMalloc) ----
__device__ int   g_cnt[NN];
__device__ int   g_rowptr[NN + 1];
__device__ int   g_cursor[NN];
__device__ int   g_csr[ET];
__device__ int   g_bsums[256];

__device__ float g_hw[NN * FDIM];     // transformed features (current layer)
__device__ __half g_h2[NN * FDIM];    // same, fp16 (for edge gather)
__device__ float g_f1[NN * FDIM];     // layer1 output
__device__ float g_f2[NN * FDIM];     // layer2 output
__device__ float g_alpha[NN * 2 * NH];// per-node alpha_src[0..3], alpha_dst[4..7]
__device__ float g_hw3[NN * 2];
__device__ float g_a3[NN * 2];

// pre-swizzled bf16 hi/lo planes of W, [n][k] layout (B operand), 32KB each
__device__ __align__(16) uint8_t g_wh[32768];
__device__ __align__(16) uint8_t g_wl[32768];

// ---------------- warp helpers ----------------------------------------------
__device__ __forceinline__ float wsum(float v) {
    #pragma unroll
    for (int o = 16; o; o >>= 1) v += __shfl_xor_sync(0xffffffffu, v, o);
    return v;
}

// ---------------- mma helpers ------------------------------------------------
__device__ __forceinline__ uint32_t smem_u32(const void* p) {
    uint32_t a;
    asm("{ .reg .u64 tmp; cvta.to.shared.u64 tmp, %1; cvt.u32.u64 %0, tmp; }"
        : "=r"(a) : "l"(p));
    return a;
}
__device__ __forceinline__ void ldsm_x4(uint32_t& r0, uint32_t& r1,
                                        uint32_t& r2, uint32_t& r3, uint32_t addr) {
    asm volatile("ldmatrix.sync.aligned.m8n8.x4.shared.b16 {%0,%1,%2,%3}, [%4];"
                 : "=r"(r0), "=r"(r1), "=r"(r2), "=r"(r3) : "r"(addr));
}
__device__ __forceinline__ void mma16816(float* c, uint32_t a0, uint32_t a1,
                                         uint32_t a2, uint32_t a3,
                                         uint32_t b0, uint32_t b1) {
    asm volatile("mma.sync.aligned.m16n8k16.row.col.f32.bf16.bf16.f32 "
                 "{%0,%1,%2,%3}, {%4,%5,%6,%7}, {%8,%9}, {%0,%1,%2,%3};"
                 : "+f"(c[0]), "+f"(c[1]), "+f"(c[2]), "+f"(c[3])
                 : "r"(a0), "r"(a1), "r"(a2), "r"(a3), "r"(b0), "r"(b1));
}
// xor-swizzled byte offset: row r (256B rows of 128 bf16), 16B chunk kc (0..15)
__device__ __forceinline__ uint32_t soff(int r, int kc) {
    return (uint32_t)((r << 8) + ((kc ^ (r & 7)) << 4));
}
__device__ __forceinline__ uint32_t pkbf(float x, float y) {
    __nv_bfloat162 p;
    p.x = __float2bfloat16_rn(x);
    p.y = __float2bfloat16_rn(y);
    return *(uint32_t*)&p;
}

// ---------------- CSR construction ------------------------------------------
__global__ void k_zero_cnt() {
    int i = blockIdx.x * blockDim.x + threadIdx.x;
    if (i < NN) g_cnt[i] = 0;
}
__global__ void k_hist(const int* __restrict__ ei) {
    int e = blockIdx.x * blockDim.x + threadIdx.x;
    if (e >= ET) return;
    int dst = (e < EE) ? ei[EE + e] : (e - EE);
    atomicAdd(&g_cnt[dst], 1);
}
__global__ void k_scan_block() {
    __shared__ int sm[256];
    int i = blockIdx.x * 256 + threadIdx.x;
    int v = (i < NN) ? g_cnt[i] : 0;
    sm[threadIdx.x] = v;
    __syncthreads();
    #pragma unroll
    for (int o = 1; o < 256; o <<= 1) {
        int t = (threadIdx.x >= o) ? sm[threadIdx.x - o] : 0;
        __syncthreads();
        sm[threadIdx.x] += t;
        __syncthreads();
    }
    if (i < NN) g_rowptr[i] = sm[threadIdx.x] - v;
    if (threadIdx.x == 255) g_bsums[blockIdx.x] = sm[255];
}
__global__ void k_scan_tops(int nb) {
    __shared__ int sm[256];
    int v = (threadIdx.x < nb) ? g_bsums[threadIdx.x] : 0;
    sm[threadIdx.x] = v;
    __syncthreads();
    #pragma unroll
    for (int o = 1; o < 256; o <<= 1) {
        int t = (threadIdx.x >= o) ? sm[threadIdx.x - o] : 0;
        __syncthreads();
        sm[threadIdx.x] += t;
        __syncthreads();
    }
    g_bsums[threadIdx.x] = sm[threadIdx.x] - v;
}
__global__ void k_scan_finish() {
    int i = blockIdx.x * blockDim.x + threadIdx.x;
    if (i < NN) {
        int r = g_rowptr[i] + g_bsums[i >> 8];
        g_rowptr[i] = r;
        g_cursor[i] = r;
    }
    if (i == 0) g_rowptr[NN] = ET;
}
__global__ void k_scatter(const int* __restrict__ ei) {
    int e = blockIdx.x * blockDim.x + threadIdx.x;
    if (e >= ET) return;
    int src, dst;
    if (e < EE) { src = ei[e]; dst = ei[EE + e]; }
    else        { src = dst = e - EE; }
    int p = atomicAdd(&g_cursor[dst], 1);
    g_csr[p] = src;
}

// ---------------- W prep: fp32 [128k,128n] -> swizzled bf16 hi/lo [n][k] ----
__global__ void k_wprep(const float* __restrict__ W) {
    int i = blockIdx.x * blockDim.x + threadIdx.x;   // 2048 chunks
    if (i >= 2048) return;
    int n = i >> 4, kc = i & 15;
    uint32_t hp[4], lp[4];
    #pragma unroll
    for (int j = 0; j < 4; j++) {
        float w0 = W[(kc * 8 + 2 * j) * 128 + n];
        float w1 = W[(kc * 8 + 2 * j + 1) * 128 + n];
        __nv_bfloat16 h0 = __float2bfloat16_rn(w0);
        __nv_bfloat16 h1 = __float2bfloat16_rn(w1);
        __nv_bfloat162 hh; hh.x = h0; hh.y = h1;
        hp[j] = *(uint32_t*)&hh;
        lp[j] = pkbf(w0 - __bfloat162float(h0), w1 - __bfloat162float(h1));
    }
    uint32_t off = soff(n, kc);
    *(uint4*)(g_wh + off) = make_uint4(hp[0], hp[1], hp[2], hp[3]);
    *(uint4*)(g_wl + off) = make_uint4(lp[0], lp[1], lp[2], lp[3]);
}

// ---------------- tensor-core GEMM + fused per-node alpha -------------------
// 64x128 tile (2 CTAs/SM), fp32 via 3-term bf16 split.
// Epilogue: C fp32, C fp16 copy, alpha_src/alpha_dst per head.
__global__ void __launch_bounds__(256)
k_gemm_mma(const float* __restrict__ A,
           const float* __restrict__ asrc, const float* __restrict__ adst,
           float* __restrict__ C, __half* __restrict__ H2, int M) {
    extern __shared__ __align__(16) char smem[];
    const int S_AH = 0, S_AL = 16384, S_BH = 32768, S_BL = 65536, S_ATT = 98304;
    int t = threadIdx.x;
    int row0 = blockIdx.x * 64;
    uint32_t sb = smem_u32(smem);
    float* att_s = (float*)(smem + S_ATT);      // [0..127] asrc, [128..255] adst

    if (t < 128) att_s[t] = asrc[t];
    else         att_s[t] = adst[t - 128];

    // copy pre-swizzled W planes (2 x 32KB)
    {
        const uint4* wh4 = (const uint4*)g_wh;
        const uint4* wl4 = (const uint4*)g_wl;
        uint4* bh = (uint4*)(smem + S_BH);
        uint4* bl = (uint4*)(smem + S_BL);
        #pragma unroll
        for (int i = 0; i < 8; i++) {
            bh[i * 256 + t] = wh4[i * 256 + t];
            bl[i * 256 + t] = wl4[i * 256 + t];
        }
    }
    // convert A rows -> bf16 hi/lo, swizzled [m][k] (64 rows x 16 chunks)
    #pragma unroll
    for (int ii = 0; ii < 4; ii++) {
        int i = ii * 256 + t;
        int r = i >> 4, kc = i & 15;
        int gr = row0 + r;
        float4 v0 = make_float4(0.f, 0.f, 0.f, 0.f), v1 = v0;
        if (gr < M) {
            v0 = *(const float4*)&A[gr * 128 + kc * 8];
            v1 = *(const float4*)&A[gr * 128 + kc * 8 + 4];
        }
        __nv_bfloat162 h0, h1, h2, h3;
        h0.x = __float2bfloat16_rn(v0.x); h0.y = __float2bfloat16_rn(v0.y);
        h1.x = __float2bfloat16_rn(v0.z); h1.y = __float2bfloat16_rn(v0.w);
        h2.x = __float2bfloat16_rn(v1.x); h2.y = __float2bfloat16_rn(v1.y);
        h3.x = __float2bfloat16_rn(v1.z); h3.y = __float2bfloat16_rn(v1.w);
        uint32_t off = soff(r, kc);
        *(uint4*)(smem + S_AH + off) = make_uint4(*(uint32_t*)&h0, *(uint32_t*)&h1,
                                                  *(uint32_t*)&h2, *(uint32_t*)&h3);
        *(uint4*)(smem + S_AL + off) = make_uint4(
            pkbf(v0.x - __bfloat162float(h0.x), v0.y - __bfloat162float(h0.y)),
            pkbf(v0.z - __bfloat162float(h1.x), v0.w - __bfloat162float(h1.y)),
            pkbf(v1.x - __bfloat162float(h2.x), v1.y - __bfloat162float(h2.y)),
            pkbf(v1.z - __bfloat162float(h3.x), v1.w - __bfloat162float(h3.y)));
    }
    __syncthreads();

    int wid = t >> 5, lane = t & 31;
    int wm = wid & 3, wn = wid >> 2;   // warp tile: 16 rows x 64 cols

    float acc[8][4];
    #pragma unroll
    for (int nt = 0; nt < 8; nt++)
        #pragma unroll
        for (int q = 0; q < 4; q++) acc[nt][q] = 0.f;

    int aRow = wm * 16 + (lane & 15);
    int aSel = lane >> 4;
    int bRow = wn * 64 + (lane & 7) + ((lane >> 4) << 3);
    int bSel = (lane >> 3) & 1;

    #pragma unroll
    for (int term = 0; term < 3; term++) {
        uint32_t aB = sb + ((term == 1) ? S_AL : S_AH);
        uint32_t bB = sb + ((term == 2) ? S_BL : S_BH);
        #pragma unroll
        for (int k16 = 0; k16 < 8; k16++) {
            int kc = k16 * 2;
            uint32_t a0, a1, a2, a3;
            ldsm_x4(a0, a1, a2, a3, aB + soff(aRow, kc + aSel));
            #pragma unroll
            for (int np = 0; np < 4; np++) {
                uint32_t b0, b1, b2, b3;
                ldsm_x4(b0, b1, b2, b3, bB + soff(bRow + np * 16, kc + bSel));
                mma16816(acc[np * 2],     a0, a1, a2, a3, b0, b1);
                mma16816(acc[np * 2 + 1], a0, a1, a2, a3, b2, b3);
            }
        }
    }

    // epilogue: C fp32 + fp16, fused alpha
    int rg = row0 + wm * 16 + (lane >> 2);
    #pragma unroll
    for (int nt = 0; nt < 8; nt++) {
        int n = wn * 64 + nt * 8 + (lane & 3) * 2;
        if (rg < M) {
            *(float2*)&C[rg * 128 + n] = make_float2(acc[nt][0], acc[nt][1]);
            __half2 hv; hv.x = __float2half(acc[nt][0]); hv.y = __float2half(acc[nt][1]);
            *(__half2*)&H2[rg * 128 + n] = hv;
        }
        if (rg + 8 < M) {
            *(float2*)&C[(rg + 8) * 128 + n] = make_float2(acc[nt][2], acc[nt][3]);
            __half2 hv; hv.x = __float2half(acc[nt][2]); hv.y = __float2half(acc[nt][3]);
            *(__half2*)&H2[(rg + 8) * 128 + n] = hv;
        }
    }
    #pragma unroll
    for (int hh = 0; hh < 2; hh++) {
        float ps0 = 0.f, pd0 = 0.f, ps1 = 0.f, pd1 = 0.f;
        #pragma unroll
        for (int j = 0; j < 4; j++) {
            int nt = hh * 4 + j;
            int n = wn * 64 + nt * 8 + (lane & 3) * 2;
            float w0s = att_s[n], w1s = att_s[n + 1];
            float w0d = att_s[128 + n], w1d = att_s[128 + n + 1];
            ps0 += acc[nt][0] * w0s + acc[nt][1] * w1s;
            pd0 += acc[nt][0] * w0d + acc[nt][1] * w1d;
            ps1 += acc[nt][2] * w0s + acc[nt][3] * w1s;
            pd1 += acc[nt][2] * w0d + acc[nt][3] * w1d;
        }
        #pragma unroll
        for (int o = 1; o <= 2; o <<= 1) {
            ps0 += __shfl_xor_sync(0xffffffffu, ps0, o);
            pd0 += __shfl_xor_sync(0xffffffffu, pd0, o);
            ps1 += __shfl_xor_sync(0xffffffffu, ps1, o);
            pd1 += __shfl_xor_sync(0xffffffffu, pd1, o);
        }
        if ((lane & 3) == 0) {
            int h = 2 * wn + hh;
            if (rg < M) {
                g_alpha[rg * 8 + h]     = ps0;
                g_alpha[rg * 8 + 4 + h] = pd0;
            }
            if (rg + 8 < M) {
                g_alpha[(rg + 8) * 8 + h]     = ps1;
                g_alpha[(rg + 8) * 8 + 4 + h] = pd1;
            }
        }
    }
}

// ---------------- edge softmax + aggregation (H=4, C=32) --------------------
// Single edge pass; features gathered in fp16 (2 x 128B lines per edge).
// lane covers channel pairs (2l,2l+1) head l>>4, and (64+2l,..) head 2+(l>>4).
__global__ void k_aggregate4(const __half* __restrict__ h2,
                             const float* __restrict__ bias,
                             float* __restrict__ out, int applyElu) {
    __shared__ float4 sm_e[8][32];
    __shared__ int    sm_s[8][32];
    int n = (blockIdx.x * blockDim.x + threadIdx.x) >> 5;
    if (n >= NN) return;
    int lane = threadIdx.x & 31;
    int wrp  = (threadIdx.x >> 5);
    int hsel = lane >> 4;
    int s0 = g_rowptr[n], s1 = g_rowptr[n + 1];
    float4 ad = *(const float4*)&g_alpha[n * 8 + 4];

    float sum0 = 0.f, sum1 = 0.f, sum2 = 0.f, sum3 = 0.f;
    float2 accA = make_float2(0.f, 0.f), accB = make_float2(0.f, 0.f);
    for (int base = s0; base < s1; base += 32) {
        int i = base + lane;
        int s = 0;
        float4 e = make_float4(0.f, 0.f, 0.f, 0.f);
        if (i < s1) {
            s = g_csr[i];
            float4 al = *(const float4*)&g_alpha[s * 8];
            float a;
            a = al.x + ad.x; a = (a > 0.f) ? a : NEG_SLOPE * a; e.x = __expf(a); sum0 += e.x;
            a = al.y + ad.y; a = (a > 0.f) ? a : NEG_SLOPE * a; e.y = __expf(a); sum1 += e.y;
            a = al.z + ad.z; a = (a > 0.f) ? a : NEG_SLOPE * a; e.z = __expf(a); sum2 += e.z;
            a = al.w + ad.w; a = (a > 0.f) ? a : NEG_SLOPE * a; e.w = __expf(a); sum3 += e.w;
        }
        sm_s[wrp][lane] = s;
        sm_e[wrp][lane] = e;
        __syncwarp();
        int cnt = min(32, s1 - base);
        #pragma unroll 2
        for (int j = 0; j < cnt; j++) {
            int ss = sm_s[wrp][j];
            float4 ee = sm_e[wrp][j];
            const __half2* hp = (const __half2*)(h2 + ss * FDIM);
            float2 fa = __half22float2(hp[lane]);
            float2 fb = __half22float2(hp[32 + lane]);
            float wA = hsel ? ee.y : ee.x;
            float wB = hsel ? ee.w : ee.z;
            accA.x += wA * fa.x; accA.y += wA * fa.y;
            accB.x += wB * fb.x; accB.y += wB * fb.y;
        }
        __syncwarp();
    }
    float inv0 = 1.f / wsum(sum0);
    float inv1 = 1.f / wsum(sum1);
    float inv2 = 1.f / wsum(sum2);
    float inv3 = 1.f / wsum(sum3);
    float invA = hsel ? inv1 : inv0;
    float invB = hsel ? inv3 : inv2;

    int c = 2 * lane;
    float v0 = accA.x * invA + bias[c];
    float v1 = accA.y * invA + bias[c + 1];
    float v2 = accB.x * invB + bias[64 + c];
    float v3 = accB.y * invB + bias[64 + c + 1];
    if (applyElu) {
        v0 = (v0 > 0.f) ? v0 : (__expf(v0) - 1.f);
        v1 = (v1 > 0.f) ? v1 : (__expf(v1) - 1.f);
        v2 = (v2 > 0.f) ? v2 : (__expf(v2) - 1.f);
        v3 = (v3 > 0.f) ? v3 : (__expf(v3) - 1.f);
    }
    *(float2*)&out[n * FDIM + c]      = make_float2(v0, v1);
    *(float2*)&out[n * FDIM + 64 + c] = make_float2(v2, v3);
}

// ---------------- layer 3 ----------------------------------------------------
__global__ void k_l3prep(const float* __restrict__ in, const float* __restrict__ W3,
                         const float* __restrict__ as3, const float* __restrict__ ad3) {
    int n = (blockIdx.x * blockDim.x + threadIdx.x) >> 5;
    if (n >= NN) return;
    int lane = threadIdx.x & 31;
    float4 v = *(const float4*)&in[n * FDIM + lane * 4];
    const float4 w0 = *(const float4*)&W3[2 * (lane * 4)];
    const float4 w1 = *(const float4*)&W3[2 * (lane * 4) + 4];
    float a0 = v.x * w0.x + v.y * w0.z + v.z * w1.x + v.w * w1.z;
    float a1 = v.x * w0.y + v.y * w0.w + v.z * w1.y + v.w * w1.w;
    a0 = wsum(a0); a1 = wsum(a1);
    if (lane == 0) {
        g_hw3[n * 2] = a0; g_hw3[n * 2 + 1] = a1;
        g_a3[n * 2]     = a0 * as3[0] + a1 * as3[1];
        g_a3[n * 2 + 1] = a0 * ad3[0] + a1 * ad3[1];
    }
}

// layer-3 aggregate (H=1,C=2) + bias + log_softmax, single edge pass
__global__ void k_aggregate1(const float* __restrict__ b3, float* __restrict__ out) {
    int n = (blockIdx.x * blockDim.x + threadIdx.x) >> 5;
    if (n >= NN) return;
    int lane = threadIdx.x & 31;
    int s0 = g_rowptr[n], s1 = g_rowptr[n + 1];
    float ad = g_a3[n * 2 + 1];

    float sum = 0.f, a0 = 0.f, a1 = 0.f;
    for (int i = s0 + lane; i < s1; i += 32) {
        int s = g_csr[i];
        float2 al = *(const float2*)&g_a3[s * 2];
        float a = al.x + ad;
        a = (a > 0.f) ? a : NEG_SLOPE * a;
        float e = __expf(a);
        sum += e;
        float2 h = *(const float2*)&g_hw3[s * 2];
        a0 += e * h.x;
        a1 += e * h.y;
    }
    sum = wsum(sum); a0 = wsum(a0); a1 = wsum(a1);

    if (lane == 0) {
        float inv = 1.f / sum;
        float z0 = a0 * inv + b3[0];
        float z1 = a1 * inv + b3[1];
        float mx = fmaxf(z0, z1);
        float l  = logf(__expf(z0 - mx) + __expf(z1 - mx));
        out[n * 2]     = z0 - mx - l;
        out[n * 2 + 1] = z1 - mx - l;
    }
}

// ---------------- host driver -----------------------------------------------
extern "C" void kernel_launch(void* const* d_in, const int* in_sizes, int n_in,
                              void* d_out, int out_size) {
    const float* x   = (const float*)d_in[0];
    const int*   ei  = (const int*)  d_in[1];
    const float* W1  = (const float*)d_in[2];
    const float* as1 = (const float*)d_in[3];
    const float* ad1 = (const float*)d_in[4];
    const float* b1  = (const float*)d_in[5];
    const float* W2  = (const float*)d_in[6];
    const float* as2 = (const float*)d_in[7];
    const float* ad2 = (const float*)d_in[8];
    const float* b2  = (const float*)d_in[9];
    const float* W3  = (const float*)d_in[10];
    const float* as3 = (const float*)d_in[11];
    const float* ad3 = (const float*)d_in[12];
    const float* b3  = (const float*)d_in[13];
    float* out = (float*)d_out;

    float *p_hw, *p_f1, *p_f2;
    __half* p_h2;
    cudaGetSymbolAddress((void**)&p_hw, g_hw);
    cudaGetSymbolAddress((void**)&p_f1, g_f1);
    cudaGetSymbolAddress((void**)&p_f2, g_f2);
    cudaGetSymbolAddress((void**)&p_h2, g_h2);

    const int GEMM_SMEM = 98304 + 1024;    // A 2x16KB + W 2x32KB + att
    cudaFuncSetAttribute(k_gemm_mma, cudaFuncAttributeMaxDynamicSharedMemorySize, GEMM_SMEM);

    const int TPB = 256;
    int nbN = (NN + TPB - 1) / TPB;           // 196
    int nbE = (ET + TPB - 1) / TPB;           // 3321
    int nbW = (NN * 32 + TPB - 1) / TPB;      // 6250 (warp per node)
    int nbT = (NN + 63) / 64;                 // 782 gemm tiles

    // order chosen so the profiled launch (0-based index 3) is k_gemm_mma
    k_wprep<<<16, 128>>>(W1);                                           // 0
    k_zero_cnt<<<nbN, TPB>>>();                                         // 1
    k_hist<<<nbE, TPB>>>(ei);                                           // 2
    k_gemm_mma<<<nbT, 256, GEMM_SMEM>>>(x, as1, ad1, p_hw, p_h2, NN);   // 3  <- profiled
    k_scan_block<<<nbN, TPB>>>();                                       // 4
    k_scan_tops<<<1, 256>>>(nbN);                                       // 5
    k_scan_finish<<<nbN, TPB>>>();                                      // 6
    k_scatter<<<nbE, TPB>>>(ei);                                        // 7

    // layer 1 aggregation
    k_aggregate4<<<nbW, TPB>>>(p_h2, b1, p_f1, 1);

    // layer 2
    k_wprep<<<16, 128>>>(W2);
    k_gemm_mma<<<nbT, 256, GEMM_SMEM>>>(p_f1, as2, ad2, p_hw, p_h2, NN);
    k_aggregate4<<<nbW, TPB>>>(p_h2, b2, p_f2, 1);

    // layer 3
    k_l3prep<<<nbW, TPB>>>(p_f2, W3, as3, ad3);
    k_aggregate1<<<nbW, TPB>>>(b3, out);
}

// round 8
// speedup vs baseline: 1.8598x; 1.1213x over previous
#include <cuda_runtime.h>
#include <cuda_bf16.h>
#include <cuda_fp16.h>
#include <math.h>
#include <stdint.h>

#define NN   50000
#define EE   800000
#define ET   (EE + NN)      // 850000 edges incl. self loops
#define FDIM 128
#define NH   4
#define CH   32
#define NEG_SLOPE 0.2f

// ---------------- device scratch (module-load allocated, no cudaMalloc) ----
__device__ int   g_cnt[NN];
__device__ int   g_rowptr[NN + 1];
__device__ int   g_cursor[NN];
__device__ int   g_csr[ET];
__device__ int   g_bsums[256];

__device__ __half g_h2[NN * FDIM];    // transformed features, fp16 (edge gather)
__device__ float g_f1[NN * FDIM];     // layer1 output (fp32, feeds GEMM2)
__device__ float g_alpha[NN * 2 * NH];// per-node alpha_src[0..3], alpha_dst[4..7]
__device__ float g_hw3[NN * 2];
__device__ float g_a3[NN * 2];

// pre-swizzled bf16 hi/lo planes of W, [n][k] layout (B operand), 32KB each
__device__ __align__(16) uint8_t g_wh[32768];
__device__ __align__(16) uint8_t g_wl[32768];

// ---------------- warp helpers ----------------------------------------------
__device__ __forceinline__ float wsum(float v) {
    #pragma unroll
    for (int o = 16; o; o >>= 1) v += __shfl_xor_sync(0xffffffffu, v, o);
    return v;
}

// ---------------- mma helpers ------------------------------------------------
__device__ __forceinline__ uint32_t smem_u32(const void* p) {
    uint32_t a;
    asm("{ .reg .u64 tmp; cvta.to.shared.u64 tmp, %1; cvt.u32.u64 %0, tmp; }"
        : "=r"(a) : "l"(p));
    return a;
}
__device__ __forceinline__ void ldsm_x4(uint32_t& r0, uint32_t& r1,
                                        uint32_t& r2, uint32_t& r3, uint32_t addr) {
    asm volatile("ldmatrix.sync.aligned.m8n8.x4.shared.b16 {%0,%1,%2,%3}, [%4];"
                 : "=r"(r0), "=r"(r1), "=r"(r2), "=r"(r3) : "r"(addr));
}
__device__ __forceinline__ void mma16816(float* c, uint32_t a0, uint32_t a1,
                                         uint32_t a2, uint32_t a3,
                                         uint32_t b0, uint32_t b1) {
    asm volatile("mma.sync.aligned.m16n8k16.row.col.f32.bf16.bf16.f32 "
                 "{%0,%1,%2,%3}, {%4,%5,%6,%7}, {%8,%9}, {%0,%1,%2,%3};"
                 : "+f"(c[0]), "+f"(c[1]), "+f"(c[2]), "+f"(c[3])
                 : "r"(a0), "r"(a1), "r"(a2), "r"(a3), "r"(b0), "r"(b1));
}
// xor-swizzled byte offset: row r (256B rows of 128 bf16), 16B chunk kc (0..15)
__device__ __forceinline__ uint32_t soff(int r, int kc) {
    return (uint32_t)((r << 8) + ((kc ^ (r & 7)) << 4));
}
__device__ __forceinline__ uint32_t pkbf(float x, float y) {
    __nv_bfloat162 p;
    p.x = __float2bfloat16_rn(x);
    p.y = __float2bfloat16_rn(y);
    return *(uint32_t*)&p;
}

// ---------------- CSR construction ------------------------------------------
__global__ void k_zero_cnt() {
    int i = blockIdx.x * blockDim.x + threadIdx.x;
    if (i < NN) g_cnt[i] = 0;
}
__global__ void k_hist(const int* __restrict__ ei) {
    int e = blockIdx.x * blockDim.x + threadIdx.x;
    if (e >= ET) return;
    int dst = (e < EE) ? ei[EE + e] : (e - EE);
    atomicAdd(&g_cnt[dst], 1);
}
__global__ void k_scan_block() {
    __shared__ int sm[256];
    int i = blockIdx.x * 256 + threadIdx.x;
    int v = (i < NN) ? g_cnt[i] : 0;
    sm[threadIdx.x] = v;
    __syncthreads();
    #pragma unroll
    for (int o = 1; o < 256; o <<= 1) {
        int t = (threadIdx.x >= o) ? sm[threadIdx.x - o] : 0;
        __syncthreads();
        sm[threadIdx.x] += t;
        __syncthreads();
    }
    if (i < NN) g_rowptr[i] = sm[threadIdx.x] - v;
    if (threadIdx.x == 255) g_bsums[blockIdx.x] = sm[255];
}
__global__ void k_scan_tops(int nb) {
    __shared__ int sm[256];
    int v = (threadIdx.x < nb) ? g_bsums[threadIdx.x] : 0;
    sm[threadIdx.x] = v;
    __syncthreads();
    #pragma unroll
    for (int o = 1; o < 256; o <<= 1) {
        int t = (threadIdx.x >= o) ? sm[threadIdx.x - o] : 0;
        __syncthreads();
        sm[threadIdx.x] += t;
        __syncthreads();
    }
    g_bsums[threadIdx.x] = sm[threadIdx.x] - v;
}
__global__ void k_scan_finish() {
    int i = blockIdx.x * blockDim.x + threadIdx.x;
    if (i < NN) {
        int r = g_rowptr[i] + g_bsums[i >> 8];
        g_rowptr[i] = r;
        g_cursor[i] = r;
    }
    if (i == 0) g_rowptr[NN] = ET;
}
__global__ void k_scatter(const int* __restrict__ ei) {
    int e = blockIdx.x * blockDim.x + threadIdx.x;
    if (e >= ET) return;
    int src, dst;
    if (e < EE) { src = ei[e]; dst = ei[EE + e]; }
    else        { src = dst = e - EE; }
    int p = atomicAdd(&g_cursor[dst], 1);
    g_csr[p] = src;
}

// ---------------- W prep: fp32 [128k,128n] -> swizzled bf16 hi/lo [n][k] ----
__global__ void k_wprep(const float* __restrict__ W) {
    int i = blockIdx.x * blockDim.x + threadIdx.x;   // 2048 chunks
    if (i >= 2048) return;
    int n = i >> 4, kc = i & 15;
    uint32_t hp[4], lp[4];
    #pragma unroll
    for (int j = 0; j < 4; j++) {
        float w0 = W[(kc * 8 + 2 * j) * 128 + n];
        float w1 = W[(kc * 8 + 2 * j + 1) * 128 + n];
        __nv_bfloat16 h0 = __float2bfloat16_rn(w0);
        __nv_bfloat16 h1 = __float2bfloat16_rn(w1);
        __nv_bfloat162 hh; hh.x = h0; hh.y = h1;
        hp[j] = *(uint32_t*)&hh;
        lp[j] = pkbf(w0 - __bfloat162float(h0), w1 - __bfloat162float(h1));
    }
    uint32_t off = soff(n, kc);
    *(uint4*)(g_wh + off) = make_uint4(hp[0], hp[1], hp[2], hp[3]);
    *(uint4*)(g_wl + off) = make_uint4(lp[0], lp[1], lp[2], lp[3]);
}

// ---------------- tensor-core GEMM + fused per-node alpha -------------------
// 128x128 tile, fp32 via 3-term bf16 split: D = Ah*Wh + Al*Wh + Ah*Wl.
// Epilogue: fp16 feature store + per-head alpha_src/alpha_dst. No fp32 C.
__global__ void __launch_bounds__(256)
k_gemm_mma(const float* __restrict__ A,
           const float* __restrict__ asrc, const float* __restrict__ adst,
           __half* __restrict__ H2, int M) {
    extern __shared__ __align__(16) char smem[];
    const int S_AH = 0, S_AL = 32768, S_BH = 65536, S_BL = 98304, S_ATT = 131072;
    int t = threadIdx.x;
    int row0 = blockIdx.x * 128;
    uint32_t sb = smem_u32(smem);
    float* att_s = (float*)(smem + S_ATT);      // [0..127] asrc, [128..255] adst

    if (t < 128) att_s[t] = asrc[t];
    else         att_s[t] = adst[t - 128];

    // copy pre-swizzled W planes (2 x 32KB)
    {
        const uint4* wh4 = (const uint4*)g_wh;
        const uint4* wl4 = (const uint4*)g_wl;
        uint4* bh = (uint4*)(smem + S_BH);
        uint4* bl = (uint4*)(smem + S_BL);
        #pragma unroll
        for (int i = 0; i < 8; i++) {
            bh[i * 256 + t] = wh4[i * 256 + t];
            bl[i * 256 + t] = wl4[i * 256 + t];
        }
    }
    // convert A rows -> bf16 hi/lo, swizzled [m][k]
    #pragma unroll
    for (int ii = 0; ii < 8; ii++) {
        int i = ii * 256 + t;
        int r = i >> 4, kc = i & 15;
        int gr = row0 + r;
        float4 v0 = make_float4(0.f, 0.f, 0.f, 0.f), v1 = v0;
        if (gr < M) {
            v0 = *(const float4*)&A[gr * 128 + kc * 8];
            v1 = *(const float4*)&A[gr * 128 + kc * 8 + 4];
        }
        __nv_bfloat162 h0, h1, h2, h3;
        h0.x = __float2bfloat16_rn(v0.x); h0.y = __float2bfloat16_rn(v0.y);
        h1.x = __float2bfloat16_rn(v0.z); h1.y = __float2bfloat16_rn(v0.w);
        h2.x = __float2bfloat16_rn(v1.x); h2.y = __float2bfloat16_rn(v1.y);
        h3.x = __float2bfloat16_rn(v1.z); h3.y = __float2bfloat16_rn(v1.w);
        uint32_t off = soff(r, kc);
        *(uint4*)(smem + S_AH + off) = make_uint4(*(uint32_t*)&h0, *(uint32_t*)&h1,
                                                  *(uint32_t*)&h2, *(uint32_t*)&h3);
        *(uint4*)(smem + S_AL + off) = make_uint4(
            pkbf(v0.x - __bfloat162float(h0.x), v0.y - __bfloat162float(h0.y)),
            pkbf(v0.z - __bfloat162float(h1.x), v0.w - __bfloat162float(h1.y)),
            pkbf(v1.x - __bfloat162float(h2.x), v1.y - __bfloat162float(h2.y)),
            pkbf(v1.z - __bfloat162float(h3.x), v1.w - __bfloat162float(h3.y)));
    }
    __syncthreads();

    int wid = t >> 5, lane = t & 31;
    int wm = wid & 3, wn = wid >> 2;

    float acc[2][8][4];
    #pragma unroll
    for (int mt = 0; mt < 2; mt++)
        #pragma unroll
        for (int nt = 0; nt < 8; nt++)
            #pragma unroll
            for (int q = 0; q < 4; q++) acc[mt][nt][q] = 0.f;

    int aRow = wm * 32 + (lane & 15);
    int aSel = lane >> 4;
    int bRow = wn * 64 + (lane & 7) + ((lane >> 4) << 3);
    int bSel = (lane >> 3) & 1;

    #pragma unroll
    for (int term = 0; term < 3; term++) {
        uint32_t aB = sb + ((term == 1) ? S_AL : S_AH);
        uint32_t bB = sb + ((term == 2) ? S_BL : S_BH);
        #pragma unroll
        for (int k16 = 0; k16 < 8; k16++) {
            int kc = k16 * 2;
            uint32_t a[2][4];
            #pragma unroll
            for (int mt = 0; mt < 2; mt++)
                ldsm_x4(a[mt][0], a[mt][1], a[mt][2], a[mt][3],
                        aB + soff(aRow + mt * 16, kc + aSel));
            #pragma unroll
            for (int np = 0; np < 4; np++) {
                uint32_t b0, b1, b2, b3;
                ldsm_x4(b0, b1, b2, b3, bB + soff(bRow + np * 16, kc + bSel));
                #pragma unroll
                for (int mt = 0; mt < 2; mt++) {
                    mma16816(acc[mt][np * 2],     a[mt][0], a[mt][1], a[mt][2], a[mt][3], b0, b1);
                    mma16816(acc[mt][np * 2 + 1], a[mt][0], a[mt][1], a[mt][2], a[mt][3], b2, b3);
                }
            }
        }
    }

    // epilogue: fp16 feature store + fused alpha
    #pragma unroll
    for (int mt = 0; mt < 2; mt++) {
        int rg = row0 + wm * 32 + mt * 16 + (lane >> 2);
        #pragma unroll
        for (int nt = 0; nt < 8; nt++) {
            int n = wn * 64 + nt * 8 + (lane & 3) * 2;
            if (rg < M) {
                __half2 hv; hv.x = __float2half(acc[mt][nt][0]); hv.y = __float2half(acc[mt][nt][1]);
                *(__half2*)&H2[rg * 128 + n] = hv;
            }
            if (rg + 8 < M) {
                __half2 hv; hv.x = __float2half(acc[mt][nt][2]); hv.y = __float2half(acc[mt][nt][3]);
                *(__half2*)&H2[(rg + 8) * 128 + n] = hv;
            }
        }
        #pragma unroll
        for (int hh = 0; hh < 2; hh++) {
            float ps0 = 0.f, pd0 = 0.f, ps1 = 0.f, pd1 = 0.f;
            #pragma unroll
            for (int j = 0; j < 4; j++) {
                int nt = hh * 4 + j;
                int n = wn * 64 + nt * 8 + (lane & 3) * 2;
                float w0s = att_s[n], w1s = att_s[n + 1];
                float w0d = att_s[128 + n], w1d = att_s[128 + n + 1];
                ps0 += acc[mt][nt][0] * w0s + acc[mt][nt][1] * w1s;
                pd0 += acc[mt][nt][0] * w0d + acc[mt][nt][1] * w1d;
                ps1 += acc[mt][nt][2] * w0s + acc[mt][nt][3] * w1s;
                pd1 += acc[mt][nt][2] * w0d + acc[mt][nt][3] * w1d;
            }
            #pragma unroll
            for (int o = 1; o <= 2; o <<= 1) {
                ps0 += __shfl_xor_sync(0xffffffffu, ps0, o);
                pd0 += __shfl_xor_sync(0xffffffffu, pd0, o);
                ps1 += __shfl_xor_sync(0xffffffffu, ps1, o);
                pd1 += __shfl_xor_sync(0xffffffffu, pd1, o);
            }
            if ((lane & 3) == 0) {
                int h = 2 * wn + hh;
                int rg2 = row0 + wm * 32 + mt * 16 + (lane >> 2);
                if (rg2 < M) {
                    g_alpha[rg2 * 8 + h]     = ps0;
                    g_alpha[rg2 * 8 + 4 + h] = pd0;
                }
                if (rg2 + 8 < M) {
                    g_alpha[(rg2 + 8) * 8 + h]     = ps1;
                    g_alpha[(rg2 + 8) * 8 + 4 + h] = pd1;
                }
            }
        }
    }
}

// ---------------- edge softmax + aggregation (H=4, C=32) --------------------
// Single edge pass; features gathered in fp16 (2 x 128B lines per edge).
// mode 0: write ELU(out) fp32 to `out` (feeds next GEMM).
// mode 1: fuse layer-3 prep — dot ELU(out) with W3 -> g_hw3, alphas -> g_a3.
__global__ void k_aggregate4(const __half* __restrict__ h2,
                             const float* __restrict__ bias,
                             float* __restrict__ out, int mode,
                             const float* __restrict__ W3,
                             const float* __restrict__ as3,
                             const float* __restrict__ ad3) {
    __shared__ float4 sm_e[8][32];
    __shared__ int    sm_s[8][32];
    int n = (blockIdx.x * blockDim.x + threadIdx.x) >> 5;
    if (n >= NN) return;
    int lane = threadIdx.x & 31;
    int wrp  = (threadIdx.x >> 5);
    int hsel = lane >> 4;
    int s0 = g_rowptr[n], s1 = g_rowptr[n + 1];
    float4 ad = *(const float4*)&g_alpha[n * 8 + 4];

    float sum0 = 0.f, sum1 = 0.f, sum2 = 0.f, sum3 = 0.f;
    float2 accA = make_float2(0.f, 0.f), accB = make_float2(0.f, 0.f);
    for (int base = s0; base < s1; base += 32) {
        int i = base + lane;
        int s = 0;
        float4 e = make_float4(0.f, 0.f, 0.f, 0.f);
        if (i < s1) {
            s = g_csr[i];
            float4 al = *(const float4*)&g_alpha[s * 8];
            float a;
            a = al.x + ad.x; a = (a > 0.f) ? a : NEG_SLOPE * a; e.x = __expf(a); sum0 += e.x;
            a = al.y + ad.y; a = (a > 0.f) ? a : NEG_SLOPE * a; e.y = __expf(a); sum1 += e.y;
            a = al.z + ad.z; a = (a > 0.f) ? a : NEG_SLOPE * a; e.z = __expf(a); sum2 += e.z;
            a = al.w + ad.w; a = (a > 0.f) ? a : NEG_SLOPE * a; e.w = __expf(a); sum3 += e.w;
        }
        sm_s[wrp][lane] = s;
        sm_e[wrp][lane] = e;
        __syncwarp();
        int cnt = min(32, s1 - base);
        #pragma unroll 2
        for (int j = 0; j < cnt; j++) {
            int ss = sm_s[wrp][j];
            float4 ee = sm_e[wrp][j];
            const __half2* hp = (const __half2*)(h2 + ss * FDIM);
            float2 fa = __half22float2(hp[lane]);
            float2 fb = __half22float2(hp[32 + lane]);
            float wA = hsel ? ee.y : ee.x;
            float wB = hsel ? ee.w : ee.z;
            accA.x += wA * fa.x; accA.y += wA * fa.y;
            accB.x += wB * fb.x; accB.y += wB * fb.y;
        }
        __syncwarp();
    }
    float inv0 = 1.f / wsum(sum0);
    float inv1 = 1.f / wsum(sum1);
    float inv2 = 1.f / wsum(sum2);
    float inv3 = 1.f / wsum(sum3);
    float invA = hsel ? inv1 : inv0;
    float invB = hsel ? inv3 : inv2;

    int c = 2 * lane;
    float v0 = accA.x * invA + bias[c];
    float v1 = accA.y * invA + bias[c + 1];
    float v2 = accB.x * invB + bias[64 + c];
    float v3 = accB.y * invB + bias[64 + c + 1];
    v0 = (v0 > 0.f) ? v0 : (__expf(v0) - 1.f);
    v1 = (v1 > 0.f) ? v1 : (__expf(v1) - 1.f);
    v2 = (v2 > 0.f) ? v2 : (__expf(v2) - 1.f);
    v3 = (v3 > 0.f) ? v3 : (__expf(v3) - 1.f);

    if (mode == 0) {
        *(float2*)&out[n * FDIM + c]      = make_float2(v0, v1);
        *(float2*)&out[n * FDIM + 64 + c] = make_float2(v2, v3);
    } else {
        // layer-3 prep: hw3 = f2 @ W3 ([128,2]); a3 from as3/ad3
        float4 wA4 = *(const float4*)&W3[2 * c];          // W3[c][0..1], W3[c+1][0..1]
        float4 wB4 = *(const float4*)&W3[128 + 2 * c];    // W3[64+c][..], W3[65+c][..]
        float p0 = v0 * wA4.x + v1 * wA4.z + v2 * wB4.x + v3 * wB4.z;
        float p1 = v0 * wA4.y + v1 * wA4.w + v2 * wB4.y + v3 * wB4.w;
        p0 = wsum(p0); p1 = wsum(p1);
        if (lane == 0) {
            g_hw3[n * 2] = p0; g_hw3[n * 2 + 1] = p1;
            g_a3[n * 2]     = p0 * as3[0] + p1 * as3[1];
            g_a3[n * 2 + 1] = p0 * ad3[0] + p1 * ad3[1];
        }
    }
}

// layer-3 aggregate (H=1,C=2) + bias + log_softmax, single edge pass
__global__ void k_aggregate1(const float* __restrict__ b3, float* __restrict__ out) {
    int n = (blockIdx.x * blockDim.x + threadIdx.x) >> 5;
    if (n >= NN) return;
    int lane = threadIdx.x & 31;
    int s0 = g_rowptr[n], s1 = g_rowptr[n + 1];
    float ad = g_a3[n * 2 + 1];

    float sum = 0.f, a0 = 0.f, a1 = 0.f;
    for (int i = s0 + lane; i < s1; i += 32) {
        int s = g_csr[i];
        float2 al = *(const float2*)&g_a3[s * 2];
        float a = al.x + ad;
        a = (a > 0.f) ? a : NEG_SLOPE * a;
        float e = __expf(a);
        sum += e;
        float2 h = *(const float2*)&g_hw3[s * 2];
        a0 += e * h.x;
        a1 += e * h.y;
    }
    sum = wsum(sum); a0 = wsum(a0); a1 = wsum(a1);

    if (lane == 0) {
        float inv = 1.f / sum;
        float z0 = a0 * inv + b3[0];
        float z1 = a1 * inv + b3[1];
        float mx = fmaxf(z0, z1);
        float l  = logf(__expf(z0 - mx) + __expf(z1 - mx));
        out[n * 2]     = z0 - mx - l;
        out[n * 2 + 1] = z1 - mx - l;
    }
}

// ---------------- host driver -----------------------------------------------
extern "C" void kernel_launch(void* const* d_in, const int* in_sizes, int n_in,
                              void* d_out, int out_size) {
    const float* x   = (const float*)d_in[0];
    const int*   ei  = (const int*)  d_in[1];
    const float* W1  = (const float*)d_in[2];
    const float* as1 = (const float*)d_in[3];
    const float* ad1 = (const float*)d_in[4];
    const float* b1  = (const float*)d_in[5];
    const float* W2  = (const float*)d_in[6];
    const float* as2 = (const float*)d_in[7];
    const float* ad2 = (const float*)d_in[8];
    const float* b2  = (const float*)d_in[9];
    const float* W3  = (const float*)d_in[10];
    const float* as3 = (const float*)d_in[11];
    const float* ad3 = (const float*)d_in[12];
    const float* b3  = (const float*)d_in[13];
    float* out = (float*)d_out;

    float* p_f1;
    __half* p_h2;
    cudaGetSymbolAddress((void**)&p_f1, g_f1);
    cudaGetSymbolAddress((void**)&p_h2, g_h2);

    const int GEMM_SMEM = 131072 + 1024;    // A 2x32KB + W 2x32KB + att
    cudaFuncSetAttribute(k_gemm_mma, cudaFuncAttributeMaxDynamicSharedMemorySize, GEMM_SMEM);

    const int TPB = 256;
    int nbN = (NN + TPB - 1) / TPB;           // 196
    int nbE = (ET + TPB - 1) / TPB;           // 3321
    int nbW = (NN * 32 + TPB - 1) / TPB;      // 6250 (warp per node)
    int nbT = (NN + 127) / 128;               // 391 gemm tiles

    // order chosen so the profiled launch (0-based index 3) is k_gemm_mma
    k_wprep<<<16, 128>>>(W1);                                        // 0
    k_zero_cnt<<<nbN, TPB>>>();                                      // 1
    k_hist<<<nbE, TPB>>>(ei);                                        // 2
    k_gemm_mma<<<nbT, 256, GEMM_SMEM>>>(x, as1, ad1, p_h2, NN);      // 3  <- profiled
    k_scan_block<<<nbN, TPB>>>();                                    // 4
    k_scan_tops<<<1, 256>>>(nbN);                                    // 5
    k_scan_finish<<<nbN, TPB>>>();                                   // 6
    k_scatter<<<nbE, TPB>>>(ei);                                     // 7

    // layer 1 aggregation (writes fp32 f1)
    k_aggregate4<<<nbW, TPB>>>(p_h2, b1, p_f1, 0, W3, as3, ad3);

    // layer 2 (+ fused layer-3 prep in aggregation)
    k_wprep<<<16, 128>>>(W2);
    k_gemm_mma<<<nbT, 256, GEMM_SMEM>>>(p_f1, as2, ad2, p_h2, NN);
    k_aggregate4<<<nbW, TPB>>>(p_h2, b2, p_f1, 1, W3, as3, ad3);

    // layer 3 final aggregate + log_softmax
    k_aggregate1<<<nbW, TPB>>>(b3, out);
}

// round 9
// speedup vs baseline: 1.9902x; 1.0701x over previous
#include <cuda_runtime.h>
#include <cuda_bf16.h>
#include <cuda_fp16.h>
#include <math.h>
#include <stdint.h>

#define NN   50000
#define EE   800000
#define ET   (EE + NN)      // 850000 edges incl. self loops
#define FDIM 128
#define NH   4
#define CH   32
#define NEG_SLOPE 0.2f

// ---------------- device scratch (module-load allocated, no cudaMalloc) ----
__device__ int   g_cnt[NN];
__device__ int   g_rowptr[NN + 1];
__device__ int   g_cursor[NN];
__device__ int   g_csr[ET];
__device__ int   g_bsums[256];

__device__ __half g_h2[NN * FDIM];    // transformed features, fp16 (edge gather)
__device__ float g_f1[NN * FDIM];     // layer1 output (fp32, feeds GEMM2)
__device__ float g_alpha[NN * 2 * NH];// per-node alpha_src[0..3], alpha_dst[4..7]
__device__ float g_hw3[NN * 2];
__device__ float g_a3[NN * 2];

// pre-swizzled bf16 hi/lo planes of W, [n][k] layout (B operand), 32KB each
__device__ __align__(16) uint8_t g_wh[32768];
__device__ __align__(16) uint8_t g_wl[32768];

// ---------------- warp helpers ----------------------------------------------
__device__ __forceinline__ float wsum(float v) {
    #pragma unroll
    for (int o = 16; o; o >>= 1) v += __shfl_xor_sync(0xffffffffu, v, o);
    return v;
}

// ---------------- mma helpers ------------------------------------------------
__device__ __forceinline__ uint32_t smem_u32(const void* p) {
    uint32_t a;
    asm("{ .reg .u64 tmp; cvta.to.shared.u64 tmp, %1; cvt.u32.u64 %0, tmp; }"
        : "=r"(a) : "l"(p));
    return a;
}
__device__ __forceinline__ void ldsm_x4(uint32_t& r0, uint32_t& r1,
                                        uint32_t& r2, uint32_t& r3, uint32_t addr) {
    asm volatile("ldmatrix.sync.aligned.m8n8.x4.shared.b16 {%0,%1,%2,%3}, [%4];"
                 : "=r"(r0), "=r"(r1), "=r"(r2), "=r"(r3) : "r"(addr));
}
__device__ __forceinline__ void mma16816(float* c, uint32_t a0, uint32_t a1,
                                         uint32_t a2, uint32_t a3,
                                         uint32_t b0, uint32_t b1) {
    asm volatile("mma.sync.aligned.m16n8k16.row.col.f32.bf16.bf16.f32 "
                 "{%0,%1,%2,%3}, {%4,%5,%6,%7}, {%8,%9}, {%0,%1,%2,%3};"
                 : "+f"(c[0]), "+f"(c[1]), "+f"(c[2]), "+f"(c[3])
                 : "r"(a0), "r"(a1), "r"(a2), "r"(a3), "r"(b0), "r"(b1));
}
// xor-swizzled byte offset: row r (256B rows of 128 bf16), 16B chunk kc (0..15)
__device__ __forceinline__ uint32_t soff(int r, int kc) {
    return (uint32_t)((r << 8) + ((kc ^ (r & 7)) << 4));
}
__device__ __forceinline__ uint32_t pkbf(float x, float y) {
    __nv_bfloat162 p;
    p.x = __float2bfloat16_rn(x);
    p.y = __float2bfloat16_rn(y);
    return *(uint32_t*)&p;
}

// ---------------- CSR construction ------------------------------------------
__global__ void k_zero_cnt() {
    int i = blockIdx.x * blockDim.x + threadIdx.x;
    if (i < NN) g_cnt[i] = 0;
}
__global__ void k_hist(const int* __restrict__ ei) {
    int e = blockIdx.x * blockDim.x + threadIdx.x;
    if (e >= ET) return;
    int dst = (e < EE) ? ei[EE + e] : (e - EE);
    atomicAdd(&g_cnt[dst], 1);
}
__global__ void k_scan_block() {
    __shared__ int sm[256];
    int i = blockIdx.x * 256 + threadIdx.x;
    int v = (i < NN) ? g_cnt[i] : 0;
    sm[threadIdx.x] = v;
    __syncthreads();
    #pragma unroll
    for (int o = 1; o < 256; o <<= 1) {
        int t = (threadIdx.x >= o) ? sm[threadIdx.x - o] : 0;
        __syncthreads();
        sm[threadIdx.x] += t;
        __syncthreads();
    }
    if (i < NN) g_rowptr[i] = sm[threadIdx.x] - v;
    if (threadIdx.x == 255) g_bsums[blockIdx.x] = sm[255];
}
__global__ void k_scan_tops(int nb) {
    __shared__ int sm[256];
    int v = (threadIdx.x < nb) ? g_bsums[threadIdx.x] : 0;
    sm[threadIdx.x] = v;
    __syncthreads();
    #pragma unroll
    for (int o = 1; o < 256; o <<= 1) {
        int t = (threadIdx.x >= o) ? sm[threadIdx.x - o] : 0;
        __syncthreads();
        sm[threadIdx.x] += t;
        __syncthreads();
    }
    g_bsums[threadIdx.x] = sm[threadIdx.x] - v;
}
__global__ void k_scan_finish() {
    int i = blockIdx.x * blockDim.x + threadIdx.x;
    if (i < NN) {
        int r = g_rowptr[i] + g_bsums[i >> 8];
        g_rowptr[i] = r;
        g_cursor[i] = r;
    }
    if (i == 0) g_rowptr[NN] = ET;
}
__global__ void k_scatter(const int* __restrict__ ei) {
    int e = blockIdx.x * blockDim.x + threadIdx.x;
    if (e >= ET) return;
    int src, dst;
    if (e < EE) { src = ei[e]; dst = ei[EE + e]; }
    else        { src = dst = e - EE; }
    int p = atomicAdd(&g_cursor[dst], 1);
    g_csr[p] = src;
}

// ---------------- W prep: fp32 [128k,128n] -> swizzled bf16 hi/lo [n][k] ----
__global__ void k_wprep(const float* __restrict__ W) {
    int i = blockIdx.x * blockDim.x + threadIdx.x;   // 2048 chunks
    if (i >= 2048) return;
    int n = i >> 4, kc = i & 15;
    uint32_t hp[4], lp[4];
    #pragma unroll
    for (int j = 0; j < 4; j++) {
        float w0 = W[(kc * 8 + 2 * j) * 128 + n];
        float w1 = W[(kc * 8 + 2 * j + 1) * 128 + n];
        __nv_bfloat16 h0 = __float2bfloat16_rn(w0);
        __nv_bfloat16 h1 = __float2bfloat16_rn(w1);
        __nv_bfloat162 hh; hh.x = h0; hh.y = h1;
        hp[j] = *(uint32_t*)&hh;
        lp[j] = pkbf(w0 - __bfloat162float(h0), w1 - __bfloat162float(h1));
    }
    uint32_t off = soff(n, kc);
    *(uint4*)(g_wh + off) = make_uint4(hp[0], hp[1], hp[2], hp[3]);
    *(uint4*)(g_wl + off) = make_uint4(lp[0], lp[1], lp[2], lp[3]);
}

// ---------------- tensor-core GEMM + fused per-node alpha -------------------
// 128x128 tile, 512 threads (16 warps, warp tile 16x64), 1 CTA/SM.
// fp32 via 3-term bf16 split: D = Ah*Wh + Al*Wh + Ah*Wl.
// Epilogue: fp16 feature store + per-head alpha_src/alpha_dst.
__global__ void __launch_bounds__(512)
k_gemm_mma(const float* __restrict__ A,
           const float* __restrict__ asrc, const float* __restrict__ adst,
           __half* __restrict__ H2, int M) {
    extern __shared__ __align__(16) char smem[];
    const int S_AH = 0, S_AL = 32768, S_BH = 65536, S_BL = 98304, S_ATT = 131072;
    int t = threadIdx.x;
    int row0 = blockIdx.x * 128;
    uint32_t sb = smem_u32(smem);
    float* att_s = (float*)(smem + S_ATT);      // [0..127] asrc, [128..255] adst

    if (t < 128)              att_s[t] = asrc[t];
    else if (t < 256)         att_s[t] = adst[t - 128];

    // copy pre-swizzled W planes (2 x 32KB = 2 x 2048 uint4)
    {
        const uint4* wh4 = (const uint4*)g_wh;
        const uint4* wl4 = (const uint4*)g_wl;
        uint4* bh = (uint4*)(smem + S_BH);
        uint4* bl = (uint4*)(smem + S_BL);
        #pragma unroll
        for (int i = 0; i < 4; i++) {
            bh[i * 512 + t] = wh4[i * 512 + t];
            bl[i * 512 + t] = wl4[i * 512 + t];
        }
    }
    // convert A rows -> bf16 hi/lo, swizzled [m][k] (2048 chunks of 8 floats)
    #pragma unroll
    for (int ii = 0; ii < 4; ii++) {
        int i = ii * 512 + t;
        int r = i >> 4, kc = i & 15;
        int gr = row0 + r;
        float4 v0 = make_float4(0.f, 0.f, 0.f, 0.f), v1 = v0;
        if (gr < M) {
            v0 = *(const float4*)&A[gr * 128 + kc * 8];
            v1 = *(const float4*)&A[gr * 128 + kc * 8 + 4];
        }
        __nv_bfloat162 h0, h1, h2, h3;
        h0.x = __float2bfloat16_rn(v0.x); h0.y = __float2bfloat16_rn(v0.y);
        h1.x = __float2bfloat16_rn(v0.z); h1.y = __float2bfloat16_rn(v0.w);
        h2.x = __float2bfloat16_rn(v1.x); h2.y = __float2bfloat16_rn(v1.y);
        h3.x = __float2bfloat16_rn(v1.z); h3.y = __float2bfloat16_rn(v1.w);
        uint32_t off = soff(r, kc);
        *(uint4*)(smem + S_AH + off) = make_uint4(*(uint32_t*)&h0, *(uint32_t*)&h1,
                                                  *(uint32_t*)&h2, *(uint32_t*)&h3);
        *(uint4*)(smem + S_AL + off) = make_uint4(
            pkbf(v0.x - __bfloat162float(h0.x), v0.y - __bfloat162float(h0.y)),
            pkbf(v0.z - __bfloat162float(h1.x), v0.w - __bfloat162float(h1.y)),
            pkbf(v1.x - __bfloat162float(h2.x), v1.y - __bfloat162float(h2.y)),
            pkbf(v1.z - __bfloat162float(h3.x), v1.w - __bfloat162float(h3.y)));
    }
    __syncthreads();

    int wid = t >> 5, lane = t & 31;
    int wm = wid & 7;          // 8 row groups x 16 rows
    int wn = wid >> 3;         // 2 col groups x 64 cols

    float acc[8][4];
    #pragma unroll
    for (int nt = 0; nt < 8; nt++)
        #pragma unroll
        for (int q = 0; q < 4; q++) acc[nt][q] = 0.f;

    int aRow = wm * 16 + (lane & 15);
    int aSel = lane >> 4;
    int bRow = wn * 64 + (lane & 7) + ((lane >> 4) << 3);
    int bSel = (lane >> 3) & 1;

    #pragma unroll
    for (int term = 0; term < 3; term++) {
        uint32_t aB = sb + ((term == 1) ? S_AL : S_AH);
        uint32_t bB = sb + ((term == 2) ? S_BL : S_BH);
        #pragma unroll
        for (int k16 = 0; k16 < 8; k16++) {
            int kc = k16 * 2;
            uint32_t a0, a1, a2, a3;
            ldsm_x4(a0, a1, a2, a3, aB + soff(aRow, kc + aSel));
            #pragma unroll
            for (int np = 0; np < 4; np++) {
                uint32_t b0, b1, b2, b3;
                ldsm_x4(b0, b1, b2, b3, bB + soff(bRow + np * 16, kc + bSel));
                mma16816(acc[np * 2],     a0, a1, a2, a3, b0, b1);
                mma16816(acc[np * 2 + 1], a0, a1, a2, a3, b2, b3);
            }
        }
    }

    // epilogue: fp16 feature store + fused alpha
    int rg = row0 + wm * 16 + (lane >> 2);
    #pragma unroll
    for (int nt = 0; nt < 8; nt++) {
        int n = wn * 64 + nt * 8 + (lane & 3) * 2;
        if (rg < M) {
            __half2 hv; hv.x = __float2half(acc[nt][0]); hv.y = __float2half(acc[nt][1]);
            *(__half2*)&H2[rg * 128 + n] = hv;
        }
        if (rg + 8 < M) {
            __half2 hv; hv.x = __float2half(acc[nt][2]); hv.y = __float2half(acc[nt][3]);
            *(__half2*)&H2[(rg + 8) * 128 + n] = hv;
        }
    }
    #pragma unroll
    for (int hh = 0; hh < 2; hh++) {
        float ps0 = 0.f, pd0 = 0.f, ps1 = 0.f, pd1 = 0.f;
        #pragma unroll
        for (int j = 0; j < 4; j++) {
            int nt = hh * 4 + j;
            int n = wn * 64 + nt * 8 + (lane & 3) * 2;
            float w0s = att_s[n], w1s = att_s[n + 1];
            float w0d = att_s[128 + n], w1d = att_s[128 + n + 1];
            ps0 += acc[nt][0] * w0s + acc[nt][1] * w1s;
            pd0 += acc[nt][0] * w0d + acc[nt][1] * w1d;
            ps1 += acc[nt][2] * w0s + acc[nt][3] * w1s;
            pd1 += acc[nt][2] * w0d + acc[nt][3] * w1d;
        }
        #pragma unroll
        for (int o = 1; o <= 2; o <<= 1) {
            ps0 += __shfl_xor_sync(0xffffffffu, ps0, o);
            pd0 += __shfl_xor_sync(0xffffffffu, pd0, o);
            ps1 += __shfl_xor_sync(0xffffffffu, ps1, o);
            pd1 += __shfl_xor_sync(0xffffffffu, pd1, o);
        }
        if ((lane & 3) == 0) {
            int h = 2 * wn + hh;
            if (rg < M) {
                g_alpha[rg * 8 + h]     = ps0;
                g_alpha[rg * 8 + 4 + h] = pd0;
            }
            if (rg + 8 < M) {
                g_alpha[(rg + 8) * 8 + h]     = ps1;
                g_alpha[(rg + 8) * 8 + 4 + h] = pd1;
            }
        }
    }
}

// ---------------- edge softmax + aggregation (H=4, C=32) --------------------
// Single edge pass; features gathered in fp16 (2 x 128B lines per edge).
// mode 0: write ELU(out) fp32 to `out` (feeds next GEMM).
// mode 1: fuse layer-3 prep — dot ELU(out) with W3 -> g_hw3, alphas -> g_a3.
__global__ void k_aggregate4(const __half* __restrict__ h2,
                             const float* __restrict__ bias,
                             float* __restrict__ out, int mode,
                             const float* __restrict__ W3,
                             const float* __restrict__ as3,
                             const float* __restrict__ ad3) {
    __shared__ float4 sm_e[8][32];
    __shared__ int    sm_s[8][32];
    int n = (blockIdx.x * blockDim.x + threadIdx.x) >> 5;
    if (n >= NN) return;
    int lane = threadIdx.x & 31;
    int wrp  = (threadIdx.x >> 5);
    int hsel = lane >> 4;
    int s0 = g_rowptr[n], s1 = g_rowptr[n + 1];
    float4 ad = *(const float4*)&g_alpha[n * 8 + 4];

    float sum0 = 0.f, sum1 = 0.f, sum2 = 0.f, sum3 = 0.f;
    float2 accA = make_float2(0.f, 0.f), accB = make_float2(0.f, 0.f);
    for (int base = s0; base < s1; base += 32) {
        int i = base + lane;
        int s = 0;
        float4 e = make_float4(0.f, 0.f, 0.f, 0.f);
        if (i < s1) {
            s = g_csr[i];
            float4 al = *(const float4*)&g_alpha[s * 8];
            float a;
            a = al.x + ad.x; a = (a > 0.f) ? a : NEG_SLOPE * a; e.x = __expf(a); sum0 += e.x;
            a = al.y + ad.y; a = (a > 0.f) ? a : NEG_SLOPE * a; e.y = __expf(a); sum1 += e.y;
            a = al.z + ad.z; a = (a > 0.f) ? a : NEG_SLOPE * a; e.z = __expf(a); sum2 += e.z;
            a = al.w + ad.w; a = (a > 0.f) ? a : NEG_SLOPE * a; e.w = __expf(a); sum3 += e.w;
        }
        sm_s[wrp][lane] = s;
        sm_e[wrp][lane] = e;
        __syncwarp();
        int cnt = min(32, s1 - base);
        #pragma unroll 4
        for (int j = 0; j < cnt; j++) {
            int ss = sm_s[wrp][j];
            float4 ee = sm_e[wrp][j];
            const __half2* hp = (const __half2*)(h2 + ss * FDIM);
            float2 fa = __half22float2(hp[lane]);
            float2 fb = __half22float2(hp[32 + lane]);
            float wA = hsel ? ee.y : ee.x;
            float wB = hsel ? ee.w : ee.z;
            accA.x += wA * fa.x; accA.y += wA * fa.y;
            accB.x += wB * fb.x; accB.y += wB * fb.y;
        }
        __syncwarp();
    }
    float inv0 = 1.f / wsum(sum0);
    float inv1 = 1.f / wsum(sum1);
    float inv2 = 1.f / wsum(sum2);
    float inv3 = 1.f / wsum(sum3);
    float invA = hsel ? inv1 : inv0;
    float invB = hsel ? inv3 : inv2;

    int c = 2 * lane;
    float v0 = accA.x * invA + bias[c];
    float v1 = accA.y * invA + bias[c + 1];
    float v2 = accB.x * invB + bias[64 + c];
    float v3 = accB.y * invB + bias[64 + c + 1];
    v0 = (v0 > 0.f) ? v0 : (__expf(v0) - 1.f);
    v1 = (v1 > 0.f) ? v1 : (__expf(v1) - 1.f);
    v2 = (v2 > 0.f) ? v2 : (__expf(v2) - 1.f);
    v3 = (v3 > 0.f) ? v3 : (__expf(v3) - 1.f);

    if (mode == 0) {
        *(float2*)&out[n * FDIM + c]      = make_float2(v0, v1);
        *(float2*)&out[n * FDIM + 64 + c] = make_float2(v2, v3);
    } else {
        // layer-3 prep: hw3 = f2 @ W3 ([128,2]); a3 from as3/ad3
        float4 wA4 = *(const float4*)&W3[2 * c];
        float4 wB4 = *(const float4*)&W3[128 + 2 * c];
        float p0 = v0 * wA4.x + v1 * wA4.z + v2 * wB4.x + v3 * wB4.z;
        float p1 = v0 * wA4.y + v1 * wA4.w + v2 * wB4.y + v3 * wB4.w;
        p0 = wsum(p0); p1 = wsum(p1);
        if (lane == 0) {
            g_hw3[n * 2] = p0; g_hw3[n * 2 + 1] = p1;
            g_a3[n * 2]     = p0 * as3[0] + p1 * as3[1];
            g_a3[n * 2 + 1] = p0 * ad3[0] + p1 * ad3[1];
        }
    }
}

// layer-3 aggregate (H=1,C=2) + bias + log_softmax, single edge pass
__global__ void k_aggregate1(const float* __restrict__ b3, float* __restrict__ out) {
    int n = (blockIdx.x * blockDim.x + threadIdx.x) >> 5;
    if (n >= NN) return;
    int lane = threadIdx.x & 31;
    int s0 = g_rowptr[n], s1 = g_rowptr[n + 1];
    float ad = g_a3[n * 2 + 1];

    float sum = 0.f, a0 = 0.f, a1 = 0.f;
    for (int i = s0 + lane; i < s1; i += 32) {
        int s = g_csr[i];
        float2 al = *(const float2*)&g_a3[s * 2];
        float a = al.x + ad;
        a = (a > 0.f) ? a : NEG_SLOPE * a;
        float e = __expf(a);
        sum += e;
        float2 h = *(const float2*)&g_hw3[s * 2];
        a0 += e * h.x;
        a1 += e * h.y;
    }
    sum = wsum(sum); a0 = wsum(a0); a1 = wsum(a1);

    if (lane == 0) {
        float inv = 1.f / sum;
        float z0 = a0 * inv + b3[0];
        float z1 = a1 * inv + b3[1];
        float mx = fmaxf(z0, z1);
        float l  = logf(__expf(z0 - mx) + __expf(z1 - mx));
        out[n * 2]     = z0 - mx - l;
        out[n * 2 + 1] = z1 - mx - l;
    }
}

// ---------------- host driver -----------------------------------------------
extern "C" void kernel_launch(void* const* d_in, const int* in_sizes, int n_in,
                              void* d_out, int out_size) {
    const float* x   = (const float*)d_in[0];
    const int*   ei  = (const int*)  d_in[1];
    const float* W1  = (const float*)d_in[2];
    const float* as1 = (const float*)d_in[3];
    const float* ad1 = (const float*)d_in[4];
    const float* b1  = (const float*)d_in[5];
    const float* W2  = (const float*)d_in[6];
    const float* as2 = (const float*)d_in[7];
    const float* ad2 = (const float*)d_in[8];
    const float* b2  = (const float*)d_in[9];
    const float* W3  = (const float*)d_in[10];
    const float* as3 = (const float*)d_in[11];
    const float* ad3 = (const float*)d_in[12];
    const float* b3  = (const float*)d_in[13];
    float* out = (float*)d_out;

    float* p_f1;
    __half* p_h2;
    cudaGetSymbolAddress((void**)&p_f1, g_f1);
    cudaGetSymbolAddress((void**)&p_h2, g_h2);

    const int GEMM_SMEM = 131072 + 1024;    // A 2x32KB + W 2x32KB + att
    cudaFuncSetAttribute(k_gemm_mma, cudaFuncAttributeMaxDynamicSharedMemorySize, GEMM_SMEM);

    const int TPB = 256;
    int nbN = (NN + TPB - 1) / TPB;           // 196
    int nbE = (ET + TPB - 1) / TPB;           // 3321
    int nbW = (NN * 32 + TPB - 1) / TPB;      // 6250 (warp per node)
    int nbT = (NN + 127) / 128;               // 391 gemm tiles

    // order chosen so the profiled launch (0-based index 3) is k_gemm_mma
    k_wprep<<<16, 128>>>(W1);                                        // 0
    k_zero_cnt<<<nbN, TPB>>>();                                      // 1
    k_hist<<<nbE, TPB>>>(ei);                                        // 2
    k_gemm_mma<<<nbT, 512, GEMM_SMEM>>>(x, as1, ad1, p_h2, NN);      // 3  <- profiled
    k_scan_block<<<nbN, TPB>>>();                                    // 4
    k_scan_tops<<<1, 256>>>(nbN);                                    // 5
    k_scan_finish<<<nbN, TPB>>>();                                   // 6
    k_scatter<<<nbE, TPB>>>(ei);                                     // 7

    // layer 1 aggregation (writes fp32 f1)
    k_aggregate4<<<nbW, TPB>>>(p_h2, b1, p_f1, 0, W3, as3, ad3);

    // layer 2 (+ fused layer-3 prep in aggregation)
    k_wprep<<<16, 128>>>(W2);
    k_gemm_mma<<<nbT, 512, GEMM_SMEM>>>(p_f1, as2, ad2, p_h2, NN);
    k_aggregate4<<<nbW, TPB>>>(p_h2, b2, p_f1, 1, W3, as3, ad3);

    // layer 3 final aggregate + log_softmax
    k_aggregate1<<<nbW, TPB>>>(b3, out);
}

// round 10
// speedup vs baseline: 2.0625x; 1.0363x over previous
#include <cuda_runtime.h>
#include <cuda_bf16.h>
#include <cuda_fp16.h>
#include <math.h>
#include <stdint.h>

#define NN   50000
#define EE   800000
#define ET   (EE + NN)      // 850000 edges incl. self loops
#define FDIM 128
#define NH   4
#define CH   32
#define NEG_SLOPE 0.2f

// ---------------- device scratch (module-load allocated, no cudaMalloc) ----
__device__ int   g_cnt[NN];
__device__ int   g_rowptr[NN + 1];
__device__ int   g_cursor[NN];
__device__ int   g_csr[ET];
__device__ int   g_bsums[256];

__device__ __half g_h2[NN * FDIM];    // transformed features, fp16 (edge gather)
__device__ __half g_f1h[NN * FDIM];   // layer1 output, fp16 (feeds GEMM2)
__device__ float g_alpha[NN * 2 * NH];// per-node alpha_src[0..3], alpha_dst[4..7]
__device__ float g_hw3[NN * 2];
__device__ float g_a3[NN * 2];

// pre-swizzled bf16 hi/lo planes of W, [n][k] layout (B operand), 32KB each
__device__ __align__(16) uint8_t g_wh[32768];
__device__ __align__(16) uint8_t g_wl[32768];

// ---------------- warp helpers ----------------------------------------------
__device__ __forceinline__ float wsum(float v) {
    #pragma unroll
    for (int o = 16; o; o >>= 1) v += __shfl_xor_sync(0xffffffffu, v, o);
    return v;
}

// ---------------- mma helpers ------------------------------------------------
__device__ __forceinline__ uint32_t smem_u32(const void* p) {
    uint32_t a;
    asm("{ .reg .u64 tmp; cvta.to.shared.u64 tmp, %1; cvt.u32.u64 %0, tmp; }"
        : "=r"(a) : "l"(p));
    return a;
}
__device__ __forceinline__ void ldsm_x4(uint32_t& r0, uint32_t& r1,
                                        uint32_t& r2, uint32_t& r3, uint32_t addr) {
    asm volatile("ldmatrix.sync.aligned.m8n8.x4.shared.b16 {%0,%1,%2,%3}, [%4];"
                 : "=r"(r0), "=r"(r1), "=r"(r2), "=r"(r3) : "r"(addr));
}
__device__ __forceinline__ void mma16816(float* c, uint32_t a0, uint32_t a1,
                                         uint32_t a2, uint32_t a3,
                                         uint32_t b0, uint32_t b1) {
    asm volatile("mma.sync.aligned.m16n8k16.row.col.f32.bf16.bf16.f32 "
                 "{%0,%1,%2,%3}, {%4,%5,%6,%7}, {%8,%9}, {%0,%1,%2,%3};"
                 : "+f"(c[0]), "+f"(c[1]), "+f"(c[2]), "+f"(c[3])
                 : "r"(a0), "r"(a1), "r"(a2), "r"(a3), "r"(b0), "r"(b1));
}
// xor-swizzled byte offset: row r (256B rows of 128 bf16), 16B chunk kc (0..15)
__device__ __forceinline__ uint32_t soff(int r, int kc) {
    return (uint32_t)((r << 8) + ((kc ^ (r & 7)) << 4));
}
__device__ __forceinline__ uint32_t pkbf(float x, float y) {
    __nv_bfloat162 p;
    p.x = __float2bfloat16_rn(x);
    p.y = __float2bfloat16_rn(y);
    return *(uint32_t*)&p;
}

// ---------------- CSR construction ------------------------------------------
__global__ void k_zero_cnt() {
    int i = blockIdx.x * blockDim.x + threadIdx.x;
    if (i < NN) g_cnt[i] = 0;
}
__global__ void k_hist(const int* __restrict__ ei) {
    int e = blockIdx.x * blockDim.x + threadIdx.x;
    if (e >= ET) return;
    int dst = (e < EE) ? ei[EE + e] : (e - EE);
    atomicAdd(&g_cnt[dst], 1);
}
__global__ void k_scan_block() {
    __shared__ int sm[256];
    int i = blockIdx.x * 256 + threadIdx.x;
    int v = (i < NN) ? g_cnt[i] : 0;
    sm[threadIdx.x] = v;
    __syncthreads();
    #pragma unroll
    for (int o = 1; o < 256; o <<= 1) {
        int t = (threadIdx.x >= o) ? sm[threadIdx.x - o] : 0;
        __syncthreads();
        sm[threadIdx.x] += t;
        __syncthreads();
    }
    if (i < NN) g_rowptr[i] = sm[threadIdx.x] - v;
    if (threadIdx.x == 255) g_bsums[blockIdx.x] = sm[255];
}
__global__ void k_scan_tops(int nb) {
    __shared__ int sm[256];
    int v = (threadIdx.x < nb) ? g_bsums[threadIdx.x] : 0;
    sm[threadIdx.x] = v;
    __syncthreads();
    #pragma unroll
    for (int o = 1; o < 256; o <<= 1) {
        int t = (threadIdx.x >= o) ? sm[threadIdx.x - o] : 0;
        __syncthreads();
        sm[threadIdx.x] += t;
        __syncthreads();
    }
    g_bsums[threadIdx.x] = sm[threadIdx.x] - v;
}
__global__ void k_scan_finish() {
    int i = blockIdx.x * blockDim.x + threadIdx.x;
    if (i < NN) {
        int r = g_rowptr[i] + g_bsums[i >> 8];
        g_rowptr[i] = r;
        g_cursor[i] = r;
    }
    if (i == 0) g_rowptr[NN] = ET;
}
__global__ void k_scatter(const int* __restrict__ ei) {
    int e = blockIdx.x * blockDim.x + threadIdx.x;
    if (e >= ET) return;
    int src, dst;
    if (e < EE) { src = ei[e]; dst = ei[EE + e]; }
    else        { src = dst = e - EE; }
    int p = atomicAdd(&g_cursor[dst], 1);
    g_csr[p] = src;
}

// ---------------- W prep: fp32 [128k,128n] -> swizzled bf16 hi/lo [n][k] ----
__global__ void k_wprep(const float* __restrict__ W) {
    int i = blockIdx.x * blockDim.x + threadIdx.x;   // 2048 chunks
    if (i >= 2048) return;
    int n = i >> 4, kc = i & 15;
    uint32_t hp[4], lp[4];
    #pragma unroll
    for (int j = 0; j < 4; j++) {
        float w0 = W[(kc * 8 + 2 * j) * 128 + n];
        float w1 = W[(kc * 8 + 2 * j + 1) * 128 + n];
        __nv_bfloat16 h0 = __float2bfloat16_rn(w0);
        __nv_bfloat16 h1 = __float2bfloat16_rn(w1);
        __nv_bfloat162 hh; hh.x = h0; hh.y = h1;
        hp[j] = *(uint32_t*)&hh;
        lp[j] = pkbf(w0 - __bfloat162float(h0), w1 - __bfloat162float(h1));
    }
    uint32_t off = soff(n, kc);
    *(uint4*)(g_wh + off) = make_uint4(hp[0], hp[1], hp[2], hp[3]);
    *(uint4*)(g_wl + off) = make_uint4(lp[0], lp[1], lp[2], lp[3]);
}

// ---------------- tensor-core GEMM + fused per-node alpha -------------------
// 128x128 tile, 512 threads (16 warps, warp tile 16x64), 1 CTA/SM.
// fp32 via 3-term bf16 split: D = Ah*Wh + Al*Wh + Ah*Wl.
// A source: fp32 (Af) or fp16 (Ahalf, exact hi/lo split).
// Fragment-sharing mainloop: ah/al/bh/bl loaded once per (k16,np), 6 MMAs.
__global__ void __launch_bounds__(512)
k_gemm_mma(const float* __restrict__ Af, const __half* __restrict__ Ahalf,
           const float* __restrict__ asrc, const float* __restrict__ adst,
           __half* __restrict__ H2, int M) {
    extern __shared__ __align__(16) char smem[];
    const int S_AH = 0, S_AL = 32768, S_BH = 65536, S_BL = 98304, S_ATT = 131072;
    int t = threadIdx.x;
    int row0 = blockIdx.x * 128;
    uint32_t sb = smem_u32(smem);
    float* att_s = (float*)(smem + S_ATT);      // [0..127] asrc, [128..255] adst

    if (t < 128)              att_s[t] = asrc[t];
    else if (t < 256)         att_s[t] = adst[t - 128];

    // copy pre-swizzled W planes (2 x 32KB = 2 x 2048 uint4)
    {
        const uint4* wh4 = (const uint4*)g_wh;
        const uint4* wl4 = (const uint4*)g_wl;
        uint4* bh = (uint4*)(smem + S_BH);
        uint4* bl = (uint4*)(smem + S_BL);
        #pragma unroll
        for (int i = 0; i < 4; i++) {
            bh[i * 512 + t] = wh4[i * 512 + t];
            bl[i * 512 + t] = wl4[i * 512 + t];
        }
    }
    // convert A rows -> bf16 hi/lo, swizzled [m][k] (2048 chunks of 8 values)
    #pragma unroll
    for (int ii = 0; ii < 4; ii++) {
        int i = ii * 512 + t;
        int r = i >> 4, kc = i & 15;
        int gr = row0 + r;
        float4 v0 = make_float4(0.f, 0.f, 0.f, 0.f), v1 = v0;
        if (gr < M) {
            if (Ahalf) {
                uint4 raw = *(const uint4*)&Ahalf[gr * 128 + kc * 8];
                float2 f0 = __half22float2(*(__half2*)&raw.x);
                float2 f1p = __half22float2(*(__half2*)&raw.y);
                float2 f2 = __half22float2(*(__half2*)&raw.z);
                float2 f3 = __half22float2(*(__half2*)&raw.w);
                v0 = make_float4(f0.x, f0.y, f1p.x, f1p.y);
                v1 = make_float4(f2.x, f2.y, f3.x, f3.y);
            } else {
                v0 = *(const float4*)&Af[gr * 128 + kc * 8];
                v1 = *(const float4*)&Af[gr * 128 + kc * 8 + 4];
            }
        }
        __nv_bfloat162 h0, h1, h2, h3;
        h0.x = __float2bfloat16_rn(v0.x); h0.y = __float2bfloat16_rn(v0.y);
        h1.x = __float2bfloat16_rn(v0.z); h1.y = __float2bfloat16_rn(v0.w);
        h2.x = __float2bfloat16_rn(v1.x); h2.y = __float2bfloat16_rn(v1.y);
        h3.x = __float2bfloat16_rn(v1.z); h3.y = __float2bfloat16_rn(v1.w);
        uint32_t off = soff(r, kc);
        *(uint4*)(smem + S_AH + off) = make_uint4(*(uint32_t*)&h0, *(uint32_t*)&h1,
                                                  *(uint32_t*)&h2, *(uint32_t*)&h3);
        *(uint4*)(smem + S_AL + off) = make_uint4(
            pkbf(v0.x - __bfloat162float(h0.x), v0.y - __bfloat162float(h0.y)),
            pkbf(v0.z - __bfloat162float(h1.x), v0.w - __bfloat162float(h1.y)),
            pkbf(v1.x - __bfloat162float(h2.x), v1.y - __bfloat162float(h2.y)),
            pkbf(v1.z - __bfloat162float(h3.x), v1.w - __bfloat162float(h3.y)));
    }
    __syncthreads();

    int wid = t >> 5, lane = t & 31;
    int wm = wid & 7;          // 8 row groups x 16 rows
    int wn = wid >> 3;         // 2 col groups x 64 cols

    float acc[8][4];
    #pragma unroll
    for (int nt = 0; nt < 8; nt++)
        #pragma unroll
        for (int q = 0; q < 4; q++) acc[nt][q] = 0.f;

    int aRow = wm * 16 + (lane & 15);
    int aSel = lane >> 4;
    int bRow = wn * 64 + (lane & 7) + ((lane >> 4) << 3);
    int bSel = (lane >> 3) & 1;

    #pragma unroll
    for (int k16 = 0; k16 < 8; k16++) {
        int kc = k16 * 2;
        uint32_t ah0, ah1, ah2, ah3, al0, al1, al2, al3;
        ldsm_x4(ah0, ah1, ah2, ah3, sb + S_AH + soff(aRow, kc + aSel));
        ldsm_x4(al0, al1, al2, al3, sb + S_AL + soff(aRow, kc + aSel));
        #pragma unroll
        for (int np = 0; np < 4; np++) {
            uint32_t bh0, bh1, bh2, bh3, bl0, bl1, bl2, bl3;
            ldsm_x4(bh0, bh1, bh2, bh3, sb + S_BH + soff(bRow + np * 16, kc + bSel));
            ldsm_x4(bl0, bl1, bl2, bl3, sb + S_BL + soff(bRow + np * 16, kc + bSel));
            // 6 MMAs, alternating acc targets (dep distance 2)
            mma16816(acc[np * 2],     ah0, ah1, ah2, ah3, bh0, bh1);
            mma16816(acc[np * 2 + 1], ah0, ah1, ah2, ah3, bh2, bh3);
            mma16816(acc[np * 2],     al0, al1, al2, al3, bh0, bh1);
            mma16816(acc[np * 2 + 1], al0, al1, al2, al3, bh2, bh3);
            mma16816(acc[np * 2],     ah0, ah1, ah2, ah3, bl0, bl1);
            mma16816(acc[np * 2 + 1], ah0, ah1, ah2, ah3, bl2, bl3);
        }
    }

    // epilogue: fp16 feature store + fused alpha
    int rg = row0 + wm * 16 + (lane >> 2);
    #pragma unroll
    for (int nt = 0; nt < 8; nt++) {
        int n = wn * 64 + nt * 8 + (lane & 3) * 2;
        if (rg < M) {
            __half2 hv; hv.x = __float2half(acc[nt][0]); hv.y = __float2half(acc[nt][1]);
            *(__half2*)&H2[rg * 128 + n] = hv;
        }
        if (rg + 8 < M) {
            __half2 hv; hv.x = __float2half(acc[nt][2]); hv.y = __float2half(acc[nt][3]);
            *(__half2*)&H2[(rg + 8) * 128 + n] = hv;
        }
    }
    #pragma unroll
    for (int hh = 0; hh < 2; hh++) {
        float ps0 = 0.f, pd0 = 0.f, ps1 = 0.f, pd1 = 0.f;
        #pragma unroll
        for (int j = 0; j < 4; j++) {
            int nt = hh * 4 + j;
            int n = wn * 64 + nt * 8 + (lane & 3) * 2;
            float w0s = att_s[n], w1s = att_s[n + 1];
            float w0d = att_s[128 + n], w1d = att_s[128 + n + 1];
            ps0 += acc[nt][0] * w0s + acc[nt][1] * w1s;
            pd0 += acc[nt][0] * w0d + acc[nt][1] * w1d;
            ps1 += acc[nt][2] * w0s + acc[nt][3] * w1s;
            pd1 += acc[nt][2] * w0d + acc[nt][3] * w1d;
        }
        #pragma unroll
        for (int o = 1; o <= 2; o <<= 1) {
            ps0 += __shfl_xor_sync(0xffffffffu, ps0, o);
            pd0 += __shfl_xor_sync(0xffffffffu, pd0, o);
            ps1 += __shfl_xor_sync(0xffffffffu, ps1, o);
            pd1 += __shfl_xor_sync(0xffffffffu, pd1, o);
        }
        if ((lane & 3) == 0) {
            int h = 2 * wn + hh;
            if (rg < M) {
                g_alpha[rg * 8 + h]     = ps0;
                g_alpha[rg * 8 + 4 + h] = pd0;
            }
            if (rg + 8 < M) {
                g_alpha[(rg + 8) * 8 + h]     = ps1;
                g_alpha[(rg + 8) * 8 + 4 + h] = pd1;
            }
        }
    }
}

// ---------------- edge softmax + aggregation (H=4, C=32) --------------------
// Single edge pass; features gathered in fp16 (2 x 128B lines per edge).
// mode 0: write ELU(out) fp16 to `outh` (feeds next GEMM).
// mode 1: fuse layer-3 prep — dot ELU(out) with W3 -> g_hw3, alphas -> g_a3.
__global__ void k_aggregate4(const __half* __restrict__ h2,
                             const float* __restrict__ bias,
                             __half* __restrict__ outh, int mode,
                             const float* __restrict__ W3,
                             const float* __restrict__ as3,
                             const float* __restrict__ ad3) {
    __shared__ float4 sm_e[8][32];
    __shared__ int    sm_s[8][32];
    int n = (blockIdx.x * blockDim.x + threadIdx.x) >> 5;
    if (n >= NN) return;
    int lane = threadIdx.x & 31;
    int wrp  = (threadIdx.x >> 5);
    int hsel = lane >> 4;
    int s0 = g_rowptr[n], s1 = g_rowptr[n + 1];
    float4 ad = *(const float4*)&g_alpha[n * 8 + 4];

    float sum0 = 0.f, sum1 = 0.f, sum2 = 0.f, sum3 = 0.f;
    float2 accA = make_float2(0.f, 0.f), accB = make_float2(0.f, 0.f);
    for (int base = s0; base < s1; base += 32) {
        int i = base + lane;
        int s = 0;
        float4 e = make_float4(0.f, 0.f, 0.f, 0.f);
        if (i < s1) {
            s = g_csr[i];
            float4 al = *(const float4*)&g_alpha[s * 8];
            float a;
            a = al.x + ad.x; a = (a > 0.f) ? a : NEG_SLOPE * a; e.x = __expf(a); sum0 += e.x;
            a = al.y + ad.y; a = (a > 0.f) ? a : NEG_SLOPE * a; e.y = __expf(a); sum1 += e.y;
            a = al.z + ad.z; a = (a > 0.f) ? a : NEG_SLOPE * a; e.z = __expf(a); sum2 += e.z;
            a = al.w + ad.w; a = (a > 0.f) ? a : NEG_SLOPE * a; e.w = __expf(a); sum3 += e.w;
        }
        sm_s[wrp][lane] = s;
        sm_e[wrp][lane] = e;
        __syncwarp();
        int cnt = min(32, s1 - base);
        #pragma unroll 4
        for (int j = 0; j < cnt; j++) {
            int ss = sm_s[wrp][j];
            float4 ee = sm_e[wrp][j];
            const __half2* hp = (const __half2*)(h2 + ss * FDIM);
            float2 fa = __half22float2(hp[lane]);
            float2 fb = __half22float2(hp[32 + lane]);
            float wA = hsel ? ee.y : ee.x;
            float wB = hsel ? ee.w : ee.z;
            accA.x += wA * fa.x; accA.y += wA * fa.y;
            accB.x += wB * fb.x; accB.y += wB * fb.y;
        }
        __syncwarp();
    }
    float inv0 = 1.f / wsum(sum0);
    float inv1 = 1.f / wsum(sum1);
    float inv2 = 1.f / wsum(sum2);
    float inv3 = 1.f / wsum(sum3);
    float invA = hsel ? inv1 : inv0;
    float invB = hsel ? inv3 : inv2;

    int c = 2 * lane;
    float v0 = accA.x * invA + bias[c];
    float v1 = accA.y * invA + bias[c + 1];
    float v2 = accB.x * invB + bias[64 + c];
    float v3 = accB.y * invB + bias[64 + c + 1];
    v0 = (v0 > 0.f) ? v0 : (__expf(v0) - 1.f);
    v1 = (v1 > 0.f) ? v1 : (__expf(v1) - 1.f);
    v2 = (v2 > 0.f) ? v2 : (__expf(v2) - 1.f);
    v3 = (v3 > 0.f) ? v3 : (__expf(v3) - 1.f);

    if (mode == 0) {
        __half2 o0; o0.x = __float2half(v0); o0.y = __float2half(v1);
        __half2 o1; o1.x = __float2half(v2); o1.y = __float2half(v3);
        *(__half2*)&outh[n * FDIM + c]      = o0;
        *(__half2*)&outh[n * FDIM + 64 + c] = o1;
    } else {
        // layer-3 prep: hw3 = f2 @ W3 ([128,2]); a3 from as3/ad3
        float4 wA4 = *(const float4*)&W3[2 * c];
        float4 wB4 = *(const float4*)&W3[128 + 2 * c];
        float p0 = v0 * wA4.x + v1 * wA4.z + v2 * wB4.x + v3 * wB4.z;
        float p1 = v0 * wA4.y + v1 * wA4.w + v2 * wB4.y + v3 * wB4.w;
        p0 = wsum(p0); p1 = wsum(p1);
        if (lane == 0) {
            g_hw3[n * 2] = p0; g_hw3[n * 2 + 1] = p1;
            g_a3[n * 2]     = p0 * as3[0] + p1 * as3[1];
            g_a3[n * 2 + 1] = p0 * ad3[0] + p1 * ad3[1];
        }
    }
}

// layer-3 aggregate (H=1,C=2) + bias + log_softmax, single edge pass
__global__ void k_aggregate1(const float* __restrict__ b3, float* __restrict__ out) {
    int n = (blockIdx.x * blockDim.x + threadIdx.x) >> 5;
    if (n >= NN) return;
    int lane = threadIdx.x & 31;
    int s0 = g_rowptr[n], s1 = g_rowptr[n + 1];
    float ad = g_a3[n * 2 + 1];

    float sum = 0.f, a0 = 0.f, a1 = 0.f;
    for (int i = s0 + lane; i < s1; i += 32) {
        int s = g_csr[i];
        float2 al = *(const float2*)&g_a3[s * 2];
        float a = al.x + ad;
        a = (a > 0.f) ? a : NEG_SLOPE * a;
        float e = __expf(a);
        sum += e;
        float2 h = *(const float2*)&g_hw3[s * 2];
        a0 += e * h.x;
        a1 += e * h.y;
    }
    sum = wsum(sum); a0 = wsum(a0); a1 = wsum(a1);

    if (lane == 0) {
        float inv = 1.f / sum;
        float z0 = a0 * inv + b3[0];
        float z1 = a1 * inv + b3[1];
        float mx = fmaxf(z0, z1);
        float l  = logf(__expf(z0 - mx) + __expf(z1 - mx));
        out[n * 2]     = z0 - mx - l;
        out[n * 2 + 1] = z1 - mx - l;
    }
}

// ---------------- host driver -----------------------------------------------
extern "C" void kernel_launch(void* const* d_in, const int* in_sizes, int n_in,
                              void* d_out, int out_size) {
    const float* x   = (const float*)d_in[0];
    const int*   ei  = (const int*)  d_in[1];
    const float* W1  = (const float*)d_in[2];
    const float* as1 = (const float*)d_in[3];
    const float* ad1 = (const float*)d_in[4];
    const float* b1  = (const float*)d_in[5];
    const float* W2  = (const float*)d_in[6];
    const float* as2 = (const float*)d_in[7];
    const float* ad2 = (const float*)d_in[8];
    const float* b2  = (const float*)d_in[9];
    const float* W3  = (const float*)d_in[10];
    const float* as3 = (const float*)d_in[11];
    const float* ad3 = (const float*)d_in[12];
    const float* b3  = (const float*)d_in[13];
    float* out = (float*)d_out;

    __half *p_h2, *p_f1h;
    cudaGetSymbolAddress((void**)&p_h2, g_h2);
    cudaGetSymbolAddress((void**)&p_f1h, g_f1h);

    const int GEMM_SMEM = 131072 + 1024;    // A 2x32KB + W 2x32KB + att
    cudaFuncSetAttribute(k_gemm_mma, cudaFuncAttributeMaxDynamicSharedMemorySize, GEMM_SMEM);

    const int TPB = 256;
    int nbN = (NN + TPB - 1) / TPB;           // 196
    int nbE = (ET + TPB - 1) / TPB;           // 3321
    int nbW = (NN * 32 + TPB - 1) / TPB;      // 6250 (warp per node)
    int nbT = (NN + 127) / 128;               // 391 gemm tiles

    // order chosen so the profiled launch (0-based index 3) is k_gemm_mma
    k_wprep<<<16, 128>>>(W1);                                                 // 0
    k_zero_cnt<<<nbN, TPB>>>();                                               // 1
    k_hist<<<nbE, TPB>>>(ei);                                                 // 2
    k_gemm_mma<<<nbT, 512, GEMM_SMEM>>>(x, nullptr, as1, ad1, p_h2, NN);      // 3  <- profiled
    k_scan_block<<<nbN, TPB>>>();                                             // 4
    k_scan_tops<<<1, 256>>>(nbN);                                             // 5
    k_scan_finish<<<nbN, TPB>>>();                                            // 6
    k_scatter<<<nbE, TPB>>>(ei);                                              // 7

    // layer 1 aggregation (writes fp16 f1)
    k_aggregate4<<<nbW, TPB>>>(p_h2, b1, p_f1h, 0, W3, as3, ad3);

    // layer 2 (+ fused layer-3 prep in aggregation)
    k_wprep<<<16, 128>>>(W2);
    k_gemm_mma<<<nbT, 512, GEMM_SMEM>>>(nullptr, p_f1h, as2, ad2, p_h2, NN);
    k_aggregate4<<<nbW, TPB>>>(p_h2, b2, nullptr, 1, W3, as3, ad3);

    // layer 3 final aggregate + log_softmax
    k_aggregate1<<<nbW, TPB>>>(b3, out);
}

// round 11
// speedup vs baseline: 2.1045x; 1.0204x over previous
#include <cuda_runtime.h>
#include <cuda_bf16.h>
#include <cuda_fp16.h>
#include <math.h>
#include <stdint.h>

#define NN   50000
#define EE   800000
#define ET   (EE + NN)      // 850000 edges incl. self loops
#define FDIM 128
#define NH   4
#define CH   32
#define NEG_SLOPE 0.2f

// ---------------- device scratch (module-load allocated, no cudaMalloc) ----
__device__ int   g_cnt[NN];
__device__ int   g_rowptr[NN + 1];
__device__ int   g_cursor[NN];
__device__ int   g_csr[ET];
__device__ int   g_bsums[256];

__device__ __half g_h2[NN * FDIM];    // transformed features, fp16 (edge gather)
__device__ __half g_f1h[NN * FDIM];   // layer1 output, fp16 (feeds GEMM2)
__device__ float g_alpha[NN * 2 * NH];// per-node alpha_src[0..3], alpha_dst[4..7]
__device__ float g_hw3[NN * 2];
__device__ float g_a3[NN * 2];

// pre-swizzled bf16 hi/lo planes of W, per-half layout:
// [half(0/1)][16KB: rows n=0..127 x 8 chunks of 16B, xor-swizzled]
__device__ __align__(16) uint8_t g_wh[32768];
__device__ __align__(16) uint8_t g_wl[32768];

// ---------------- warp helpers ----------------------------------------------
__device__ __forceinline__ float wsum(float v) {
    #pragma unroll
    for (int o = 16; o; o >>= 1) v += __shfl_xor_sync(0xffffffffu, v, o);
    return v;
}

// ---------------- mma helpers ------------------------------------------------
__device__ __forceinline__ uint32_t smem_u32(const void* p) {
    uint32_t a;
    asm("{ .reg .u64 tmp; cvta.to.shared.u64 tmp, %1; cvt.u32.u64 %0, tmp; }"
        : "=r"(a) : "l"(p));
    return a;
}
__device__ __forceinline__ void ldsm_x4(uint32_t& r0, uint32_t& r1,
                                        uint32_t& r2, uint32_t& r3, uint32_t addr) {
    asm volatile("ldmatrix.sync.aligned.m8n8.x4.shared.b16 {%0,%1,%2,%3}, [%4];"
                 : "=r"(r0), "=r"(r1), "=r"(r2), "=r"(r3) : "r"(addr));
}
__device__ __forceinline__ void mma16816(float* c, uint32_t a0, uint32_t a1,
                                         uint32_t a2, uint32_t a3,
                                         uint32_t b0, uint32_t b1) {
    asm volatile("mma.sync.aligned.m16n8k16.row.col.f32.bf16.bf16.f32 "
                 "{%0,%1,%2,%3}, {%4,%5,%6,%7}, {%8,%9}, {%0,%1,%2,%3};"
                 : "+f"(c[0]), "+f"(c[1]), "+f"(c[2]), "+f"(c[3])
                 : "r"(a0), "r"(a1), "r"(a2), "r"(a3), "r"(b0), "r"(b1));
}
// half-K plane: 128 rows x 64 bf16 (128B rows, 8 chunks of 16B), xor swizzle
__device__ __forceinline__ uint32_t soff64(int r, int kc) {
    return (uint32_t)((r << 7) + (((kc ^ r) & 7) << 4));
}
__device__ __forceinline__ uint32_t pkbf(float x, float y) {
    __nv_bfloat162 p;
    p.x = __float2bfloat16_rn(x);
    p.y = __float2bfloat16_rn(y);
    return *(uint32_t*)&p;
}

// ---------------- CSR construction ------------------------------------------
__global__ void k_zero_cnt() {
    int i = blockIdx.x * blockDim.x + threadIdx.x;
    if (i < NN) g_cnt[i] = 0;
}
__global__ void k_hist(const int* __restrict__ ei) {
    int e = blockIdx.x * blockDim.x + threadIdx.x;
    if (e >= ET) return;
    int dst = (e < EE) ? ei[EE + e] : (e - EE);
    atomicAdd(&g_cnt[dst], 1);
}
__global__ void k_scan_block() {
    __shared__ int sm[256];
    int i = blockIdx.x * 256 + threadIdx.x;
    int v = (i < NN) ? g_cnt[i] : 0;
    sm[threadIdx.x] = v;
    __syncthreads();
    #pragma unroll
    for (int o = 1; o < 256; o <<= 1) {
        int t = (threadIdx.x >= o) ? sm[threadIdx.x - o] : 0;
        __syncthreads();
        sm[threadIdx.x] += t;
        __syncthreads();
    }
    if (i < NN) g_rowptr[i] = sm[threadIdx.x] - v;
    if (threadIdx.x == 255) g_bsums[blockIdx.x] = sm[255];
}
__global__ void k_scan_tops(int nb) {
    __shared__ int sm[256];
    int v = (threadIdx.x < nb) ? g_bsums[threadIdx.x] : 0;
    sm[threadIdx.x] = v;
    __syncthreads();
    #pragma unroll
    for (int o = 1; o < 256; o <<= 1) {
        int t = (threadIdx.x >= o) ? sm[threadIdx.x - o] : 0;
        __syncthreads();
        sm[threadIdx.x] += t;
        __syncthreads();
    }
    g_bsums[threadIdx.x] = sm[threadIdx.x] - v;
}
__global__ void k_scan_finish() {
    int i = blockIdx.x * blockDim.x + threadIdx.x;
    if (i < NN) {
        int r = g_rowptr[i] + g_bsums[i >> 8];
        g_rowptr[i] = r;
        g_cursor[i] = r;
    }
    if (i == 0) g_rowptr[NN] = ET;
}
__global__ void k_scatter(const int* __restrict__ ei) {
    int e = blockIdx.x * blockDim.x + threadIdx.x;
    if (e >= ET) return;
    int src, dst;
    if (e < EE) { src = ei[e]; dst = ei[EE + e]; }
    else        { src = dst = e - EE; }
    int p = atomicAdd(&g_cursor[dst], 1);
    g_csr[p] = src;
}

// ---------------- W prep: fp32 [128k,128n] -> 2 half-K swizzled planes ------
__global__ void k_wprep(const float* __restrict__ W) {
    int i = blockIdx.x * blockDim.x + threadIdx.x;   // 2048 chunks
    if (i >= 2048) return;
    int n = i >> 4, kc = i & 15;                     // kc: 16B chunk in full K
    uint32_t hp[4], lp[4];
    #pragma unroll
    for (int j = 0; j < 4; j++) {
        float w0 = W[(kc * 8 + 2 * j) * 128 + n];
        float w1 = W[(kc * 8 + 2 * j + 1) * 128 + n];
        __nv_bfloat16 h0 = __float2bfloat16_rn(w0);
        __nv_bfloat16 h1 = __float2bfloat16_rn(w1);
        __nv_bfloat162 hh; hh.x = h0; hh.y = h1;
        hp[j] = *(uint32_t*)&hh;
        lp[j] = pkbf(w0 - __bfloat162float(h0), w1 - __bfloat162float(h1));
    }
    int half = kc >> 3;
    uint32_t off = half * 16384 + soff64(n, kc & 7);
    *(uint4*)(g_wh + off) = make_uint4(hp[0], hp[1], hp[2], hp[3]);
    *(uint4*)(g_wl + off) = make_uint4(lp[0], lp[1], lp[2], lp[3]);
}

// ---------------- tensor-core GEMM + fused per-node alpha -------------------
// 128x128 tile, 512 threads, K processed in two 64-wide halves reusing
// 4 x 16KB smem planes -> 65KB smem -> 2 CTAs/SM.
// fp32 via 3-term bf16 split: D = Ah*Wh + Al*Wh + Ah*Wl (accum across halves).
__global__ void __launch_bounds__(512, 2)
k_gemm_mma(const float* __restrict__ Af, const __half* __restrict__ Ahalf,
           const float* __restrict__ asrc, const float* __restrict__ adst,
           __half* __restrict__ H2, int M) {
    extern __shared__ __align__(16) char smem[];
    const int S_AH = 0, S_AL = 16384, S_BH = 32768, S_BL = 49152, S_ATT = 65536;
    int t = threadIdx.x;
    int row0 = blockIdx.x * 128;
    uint32_t sb = smem_u32(smem);
    float* att_s = (float*)(smem + S_ATT);      // [0..127] asrc, [128..255] adst

    if (t < 128)              att_s[t] = asrc[t];
    else if (t < 256)         att_s[t] = adst[t - 128];

    int wid = t >> 5, lane = t & 31;
    int wm = wid & 7;          // 8 row groups x 16 rows
    int wn = wid >> 3;         // 2 col groups x 64 cols

    float acc[8][4];
    #pragma unroll
    for (int nt = 0; nt < 8; nt++)
        #pragma unroll
        for (int q = 0; q < 4; q++) acc[nt][q] = 0.f;

    int aRow = wm * 16 + (lane & 15);
    int aSel = lane >> 4;
    int bRow = wn * 64 + (lane & 7) + ((lane >> 4) << 3);
    int bSel = (lane >> 3) & 1;

    #pragma unroll
    for (int ks = 0; ks < 2; ks++) {
        if (ks) __syncthreads();     // previous mainloop must finish reading
        // copy pre-swizzled W half planes (2 x 16KB = 2 x 1024 uint4)
        {
            const uint4* wh4 = (const uint4*)g_wh + ks * 1024;
            const uint4* wl4 = (const uint4*)g_wl + ks * 1024;
            uint4* bh = (uint4*)(smem + S_BH);
            uint4* bl = (uint4*)(smem + S_BL);
            #pragma unroll
            for (int i = 0; i < 2; i++) {
                bh[i * 512 + t] = wh4[i * 512 + t];
                bl[i * 512 + t] = wl4[i * 512 + t];
            }
        }
        // convert A rows -> bf16 hi/lo (128 rows x 8 chunks = 1024 chunks)
        #pragma unroll
        for (int ii = 0; ii < 2; ii++) {
            int i = ii * 512 + t;
            int r = i >> 3, kc = i & 7;
            int gr = row0 + r;
            int col = ks * 64 + kc * 8;
            float4 v0 = make_float4(0.f, 0.f, 0.f, 0.f), v1 = v0;
            if (gr < M) {
                if (Ahalf) {
                    uint4 raw = *(const uint4*)&Ahalf[gr * 128 + col];
                    float2 f0 = __half22float2(*(__half2*)&raw.x);
                    float2 f1p = __half22float2(*(__half2*)&raw.y);
                    float2 f2 = __half22float2(*(__half2*)&raw.z);
                    float2 f3 = __half22float2(*(__half2*)&raw.w);
                    v0 = make_float4(f0.x, f0.y, f1p.x, f1p.y);
                    v1 = make_float4(f2.x, f2.y, f3.x, f3.y);
                } else {
                    v0 = *(const float4*)&Af[gr * 128 + col];
                    v1 = *(const float4*)&Af[gr * 128 + col + 4];
                }
            }
            __nv_bfloat162 h0, h1, h2, h3;
            h0.x = __float2bfloat16_rn(v0.x); h0.y = __float2bfloat16_rn(v0.y);
            h1.x = __float2bfloat16_rn(v0.z); h1.y = __float2bfloat16_rn(v0.w);
            h2.x = __float2bfloat16_rn(v1.x); h2.y = __float2bfloat16_rn(v1.y);
            h3.x = __float2bfloat16_rn(v1.z); h3.y = __float2bfloat16_rn(v1.w);
            uint32_t off = soff64(r, kc);
            *(uint4*)(smem + S_AH + off) = make_uint4(*(uint32_t*)&h0, *(uint32_t*)&h1,
                                                      *(uint32_t*)&h2, *(uint32_t*)&h3);
            *(uint4*)(smem + S_AL + off) = make_uint4(
                pkbf(v0.x - __bfloat162float(h0.x), v0.y - __bfloat162float(h0.y)),
                pkbf(v0.z - __bfloat162float(h1.x), v0.w - __bfloat162float(h1.y)),
                pkbf(v1.x - __bfloat162float(h2.x), v1.y - __bfloat162float(h2.y)),
                pkbf(v1.z - __bfloat162float(h3.x), v1.w - __bfloat162float(h3.y)));
        }
        __syncthreads();

        // mainloop over this K half (4 x k16)
        #pragma unroll
        for (int k16 = 0; k16 < 4; k16++) {
            int kc = k16 * 2;
            uint32_t ah0, ah1, ah2, ah3, al0, al1, al2, al3;
            ldsm_x4(ah0, ah1, ah2, ah3, sb + S_AH + soff64(aRow, kc + aSel));
            ldsm_x4(al0, al1, al2, al3, sb + S_AL + soff64(aRow, kc + aSel));
            #pragma unroll
            for (int np = 0; np < 4; np++) {
                uint32_t bh0, bh1, bh2, bh3, bl0, bl1, bl2, bl3;
                ldsm_x4(bh0, bh1, bh2, bh3, sb + S_BH + soff64(bRow + np * 16, kc + bSel));
                ldsm_x4(bl0, bl1, bl2, bl3, sb + S_BL + soff64(bRow + np * 16, kc + bSel));
                mma16816(acc[np * 2],     ah0, ah1, ah2, ah3, bh0, bh1);
                mma16816(acc[np * 2 + 1], ah0, ah1, ah2, ah3, bh2, bh3);
                mma16816(acc[np * 2],     al0, al1, al2, al3, bh0, bh1);
                mma16816(acc[np * 2 + 1], al0, al1, al2, al3, bh2, bh3);
                mma16816(acc[np * 2],     ah0, ah1, ah2, ah3, bl0, bl1);
                mma16816(acc[np * 2 + 1], ah0, ah1, ah2, ah3, bl2, bl3);
            }
        }
    }

    // epilogue: fp16 feature store + fused alpha
    int rg = row0 + wm * 16 + (lane >> 2);
    #pragma unroll
    for (int nt = 0; nt < 8; nt++) {
        int n = wn * 64 + nt * 8 + (lane & 3) * 2;
        if (rg < M) {
            __half2 hv; hv.x = __float2half(acc[nt][0]); hv.y = __float2half(acc[nt][1]);
            *(__half2*)&H2[rg * 128 + n] = hv;
        }
        if (rg + 8 < M) {
            __half2 hv; hv.x = __float2half(acc[nt][2]); hv.y = __float2half(acc[nt][3]);
            *(__half2*)&H2[(rg + 8) * 128 + n] = hv;
        }
    }
    #pragma unroll
    for (int hh = 0; hh < 2; hh++) {
        float ps0 = 0.f, pd0 = 0.f, ps1 = 0.f, pd1 = 0.f;
        #pragma unroll
        for (int j = 0; j < 4; j++) {
            int nt = hh * 4 + j;
            int n = wn * 64 + nt * 8 + (lane & 3) * 2;
            float w0s = att_s[n], w1s = att_s[n + 1];
            float w0d = att_s[128 + n], w1d = att_s[128 + n + 1];
            ps0 += acc[nt][0] * w0s + acc[nt][1] * w1s;
            pd0 += acc[nt][0] * w0d + acc[nt][1] * w1d;
            ps1 += acc[nt][2] * w0s + acc[nt][3] * w1s;
            pd1 += acc[nt][2] * w0d + acc[nt][3] * w1d;
        }
        #pragma unroll
        for (int o = 1; o <= 2; o <<= 1) {
            ps0 += __shfl_xor_sync(0xffffffffu, ps0, o);
            pd0 += __shfl_xor_sync(0xffffffffu, pd0, o);
            ps1 += __shfl_xor_sync(0xffffffffu, ps1, o);
            pd1 += __shfl_xor_sync(0xffffffffu, pd1, o);
        }
        if ((lane & 3) == 0) {
            int h = 2 * wn + hh;
            if (rg < M) {
                g_alpha[rg * 8 + h]     = ps0;
                g_alpha[rg * 8 + 4 + h] = pd0;
            }
            if (rg + 8 < M) {
                g_alpha[(rg + 8) * 8 + h]     = ps1;
                g_alpha[(rg + 8) * 8 + 4 + h] = pd1;
            }
        }
    }
}

// ---------------- edge softmax + aggregation (H=4, C=32) --------------------
// Single edge pass; features gathered in fp16 (2 x 128B lines per edge).
// mode 0: write ELU(out) fp16 to `outh` (feeds next GEMM).
// mode 1: fuse layer-3 prep — dot ELU(out) with W3 -> g_hw3, alphas -> g_a3.
__global__ void k_aggregate4(const __half* __restrict__ h2,
                             const float* __restrict__ bias,
                             __half* __restrict__ outh, int mode,
                             const float* __restrict__ W3,
                             const float* __restrict__ as3,
                             const float* __restrict__ ad3) {
    __shared__ float4 sm_e[8][32];
    __shared__ int    sm_s[8][32];
    int n = (blockIdx.x * blockDim.x + threadIdx.x) >> 5;
    if (n >= NN) return;
    int lane = threadIdx.x & 31;
    int wrp  = (threadIdx.x >> 5);
    int hsel = lane >> 4;
    int s0 = g_rowptr[n], s1 = g_rowptr[n + 1];
    float4 ad = *(const float4*)&g_alpha[n * 8 + 4];

    float sum0 = 0.f, sum1 = 0.f, sum2 = 0.f, sum3 = 0.f;
    float2 accA = make_float2(0.f, 0.f), accB = make_float2(0.f, 0.f);
    for (int base = s0; base < s1; base += 32) {
        int i = base + lane;
        int s = 0;
        float4 e = make_float4(0.f, 0.f, 0.f, 0.f);
        if (i < s1) {
            s = g_csr[i];
            float4 al = *(const float4*)&g_alpha[s * 8];
            float a;
            a = al.x + ad.x; a = (a > 0.f) ? a : NEG_SLOPE * a; e.x = __expf(a); sum0 += e.x;
            a = al.y + ad.y; a = (a > 0.f) ? a : NEG_SLOPE * a; e.y = __expf(a); sum1 += e.y;
            a = al.z + ad.z; a = (a > 0.f) ? a : NEG_SLOPE * a; e.z = __expf(a); sum2 += e.z;
            a = al.w + ad.w; a = (a > 0.f) ? a : NEG_SLOPE * a; e.w = __expf(a); sum3 += e.w;
        }
        sm_s[wrp][lane] = s;
        sm_e[wrp][lane] = e;
        __syncwarp();
        int cnt = min(32, s1 - base);
        #pragma unroll 4
        for (int j = 0; j < cnt; j++) {
            int ss = sm_s[wrp][j];
            float4 ee = sm_e[wrp][j];
            const __half2* hp = (const __half2*)(h2 + ss * FDIM);
            float2 fa = __half22float2(hp[lane]);
            float2 fb = __half22float2(hp[32 + lane]);
            float wA = hsel ? ee.y : ee.x;
            float wB = hsel ? ee.w : ee.z;
            accA.x += wA * fa.x; accA.y += wA * fa.y;
            accB.x += wB * fb.x; accB.y += wB * fb.y;
        }
        __syncwarp();
    }
    float inv0 = 1.f / wsum(sum0);
    float inv1 = 1.f / wsum(sum1);
    float inv2 = 1.f / wsum(sum2);
    float inv3 = 1.f / wsum(sum3);
    float invA = hsel ? inv1 : inv0;
    float invB = hsel ? inv3 : inv2;

    int c = 2 * lane;
    float v0 = accA.x * invA + bias[c];
    float v1 = accA.y * invA + bias[c + 1];
    float v2 = accB.x * invB + bias[64 + c];
    float v3 = accB.y * invB + bias[64 + c + 1];
    v0 = (v0 > 0.f) ? v0 : (__expf(v0) - 1.f);
    v1 = (v1 > 0.f) ? v1 : (__expf(v1) - 1.f);
    v2 = (v2 > 0.f) ? v2 : (__expf(v2) - 1.f);
    v3 = (v3 > 0.f) ? v3 : (__expf(v3) - 1.f);

    if (mode == 0) {
        __half2 o0; o0.x = __float2half(v0); o0.y = __float2half(v1);
        __half2 o1; o1.x = __float2half(v2); o1.y = __float2half(v3);
        *(__half2*)&outh[n * FDIM + c]      = o0;
        *(__half2*)&outh[n * FDIM + 64 + c] = o1;
    } else {
        // layer-3 prep: hw3 = f2 @ W3 ([128,2]); a3 from as3/ad3
        float4 wA4 = *(const float4*)&W3[2 * c];
        float4 wB4 = *(const float4*)&W3[128 + 2 * c];
        float p0 = v0 * wA4.x + v1 * wA4.z + v2 * wB4.x + v3 * wB4.z;
        float p1 = v0 * wA4.y + v1 * wA4.w + v2 * wB4.y + v3 * wB4.w;
        p0 = wsum(p0); p1 = wsum(p1);
        if (lane == 0) {
            g_hw3[n * 2] = p0; g_hw3[n * 2 + 1] = p1;
            g_a3[n * 2]     = p0 * as3[0] + p1 * as3[1];
            g_a3[n * 2 + 1] = p0 * ad3[0] + p1 * ad3[1];
        }
    }
}

// layer-3 aggregate (H=1,C=2) + bias + log_softmax, single edge pass
__global__ void k_aggregate1(const float* __restrict__ b3, float* __restrict__ out) {
    int n = (blockIdx.x * blockDim.x + threadIdx.x) >> 5;
    if (n >= NN) return;
    int lane = threadIdx.x & 31;
    int s0 = g_rowptr[n], s1 = g_rowptr[n + 1];
    float ad = g_a3[n * 2 + 1];

    float sum = 0.f, a0 = 0.f, a1 = 0.f;
    for (int i = s0 + lane; i < s1; i += 32) {
        int s = g_csr[i];
        float2 al = *(const float2*)&g_a3[s * 2];
        float a = al.x + ad;
        a = (a > 0.f) ? a : NEG_SLOPE * a;
        float e = __expf(a);
        sum += e;
        float2 h = *(const float2*)&g_hw3[s * 2];
        a0 += e * h.x;
        a1 += e * h.y;
    }
    sum = wsum(sum); a0 = wsum(a0); a1 = wsum(a1);

    if (lane == 0) {
        float inv = 1.f / sum;
        float z0 = a0 * inv + b3[0];
        float z1 = a1 * inv + b3[1];
        float mx = fmaxf(z0, z1);
        float l  = logf(__expf(z0 - mx) + __expf(z1 - mx));
        out[n * 2]     = z0 - mx - l;
        out[n * 2 + 1] = z1 - mx - l;
    }
}

// ---------------- host driver -----------------------------------------------
extern "C" void kernel_launch(void* const* d_in, const int* in_sizes, int n_in,
                              void* d_out, int out_size) {
    const float* x   = (const float*)d_in[0];
    const int*   ei  = (const int*)  d_in[1];
    const float* W1  = (const float*)d_in[2];
    const float* as1 = (const float*)d_in[3];
    const float* ad1 = (const float*)d_in[4];
    const float* b1  = (const float*)d_in[5];
    const float* W2  = (const float*)d_in[6];
    const float* as2 = (const float*)d_in[7];
    const float* ad2 = (const float*)d_in[8];
    const float* b2  = (const float*)d_in[9];
    const float* W3  = (const float*)d_in[10];
    const float* as3 = (const float*)d_in[11];
    const float* ad3 = (const float*)d_in[12];
    const float* b3  = (const float*)d_in[13];
    float* out = (float*)d_out;

    __half *p_h2, *p_f1h;
    cudaGetSymbolAddress((void**)&p_h2, g_h2);
    cudaGetSymbolAddress((void**)&p_f1h, g_f1h);

    const int GEMM_SMEM = 65536 + 1024;    // 4 x 16KB planes + att
    cudaFuncSetAttribute(k_gemm_mma, cudaFuncAttributeMaxDynamicSharedMemorySize, GEMM_SMEM);

    const int TPB = 256;
    int nbN = (NN + TPB - 1) / TPB;           // 196
    int nbE = (ET + TPB - 1) / TPB;           // 3321
    int nbW = (NN * 32 + TPB - 1) / TPB;      // 6250 (warp per node)
    int nbT = (NN + 127) / 128;               // 391 gemm tiles

    // order chosen so the profiled launch (0-based index 3) is k_gemm_mma
    k_wprep<<<16, 128>>>(W1);                                                 // 0
    k_zero_cnt<<<nbN, TPB>>>();                                               // 1
    k_hist<<<nbE, TPB>>>(ei);                                                 // 2
    k_gemm_mma<<<nbT, 512, GEMM_SMEM>>>(x, nullptr, as1, ad1, p_h2, NN);      // 3  <- profiled
    k_scan_block<<<nbN, TPB>>>();                                             // 4
    k_scan_tops<<<1, 256>>>(nbN);                                             // 5
    k_scan_finish<<<nbN, TPB>>>();                                            // 6
    k_scatter<<<nbE, TPB>>>(ei);                                              // 7

    // layer 1 aggregation (writes fp16 f1)
    k_aggregate4<<<nbW, TPB>>>(p_h2, b1, p_f1h, 0, W3, as3, ad3);

    // layer 2 (+ fused layer-3 prep in aggregation)
    k_wprep<<<16, 128>>>(W2);
    k_gemm_mma<<<nbT, 512, GEMM_SMEM>>>(nullptr, p_f1h, as2, ad2, p_h2, NN);
    k_aggregate4<<<nbW, TPB>>>(p_h2, b2, nullptr, 1, W3, as3, ad3);

    // layer 3 final aggregate + log_softmax
    k_aggregate1<<<nbW, TPB>>>(b3, out);
}

// round 12
// speedup vs baseline: 2.1081x; 1.0017x over previous
#include <cuda_runtime.h>
#include <cuda_bf16.h>
#include <cuda_fp16.h>
#include <math.h>
#include <stdint.h>

#define NN   50000
#define EE   800000
#define ET   (EE + NN)      // 850000 edges incl. self loops
#define FDIM 128
#define NH   4
#define CH   32
#define NEG_SLOPE 0.2f

// ---------------- device scratch (module-load allocated, no cudaMalloc) ----
__device__ int   g_cnt[NN];
__device__ int   g_rowptr[NN + 1];
__device__ int   g_cursor[NN];
__device__ int   g_csr[ET];
__device__ int   g_bsums[256];

__device__ __half g_h2[NN * FDIM];    // transformed features, fp16 (edge gather)
__device__ __half g_f1h[NN * FDIM];   // layer1 output, fp16 (feeds GEMM2)
__device__ float g_alpha[NN * 2 * NH];// per-node alpha_src[0..3], alpha_dst[4..7]
__device__ float g_hw3[NN * 2];
__device__ float g_a3[NN * 2];

// pre-swizzled bf16 hi/lo planes of W, per-half layout:
// [half(0/1)][16KB: rows n=0..127 x 8 chunks of 16B, xor-swizzled]
__device__ __align__(16) uint8_t g_wh[32768];
__device__ __align__(16) uint8_t g_wl[32768];

// ---------------- warp helpers ----------------------------------------------
__device__ __forceinline__ float wsum(float v) {
    #pragma unroll
    for (int o = 16; o; o >>= 1) v += __shfl_xor_sync(0xffffffffu, v, o);
    return v;
}

// ---------------- mma helpers ------------------------------------------------
__device__ __forceinline__ uint32_t smem_u32(const void* p) {
    uint32_t a;
    asm("{ .reg .u64 tmp; cvta.to.shared.u64 tmp, %1; cvt.u32.u64 %0, tmp; }"
        : "=r"(a) : "l"(p));
    return a;
}
__device__ __forceinline__ void ldsm_x4(uint32_t& r0, uint32_t& r1,
                                        uint32_t& r2, uint32_t& r3, uint32_t addr) {
    asm volatile("ldmatrix.sync.aligned.m8n8.x4.shared.b16 {%0,%1,%2,%3}, [%4];"
                 : "=r"(r0), "=r"(r1), "=r"(r2), "=r"(r3) : "r"(addr));
}
__device__ __forceinline__ void mma16816(float* c, uint32_t a0, uint32_t a1,
                                         uint32_t a2, uint32_t a3,
                                         uint32_t b0, uint32_t b1) {
    asm volatile("mma.sync.aligned.m16n8k16.row.col.f32.bf16.bf16.f32 "
                 "{%0,%1,%2,%3}, {%4,%5,%6,%7}, {%8,%9}, {%0,%1,%2,%3};"
                 : "+f"(c[0]), "+f"(c[1]), "+f"(c[2]), "+f"(c[3])
                 : "r"(a0), "r"(a1), "r"(a2), "r"(a3), "r"(b0), "r"(b1));
}
// half-K plane: 128 rows x 64 bf16 (128B rows, 8 chunks of 16B), xor swizzle
__device__ __forceinline__ uint32_t soff64(int r, int kc) {
    return (uint32_t)((r << 7) + (((kc ^ r) & 7) << 4));
}
__device__ __forceinline__ uint32_t pkbf(float x, float y) {
    __nv_bfloat162 p;
    p.x = __float2bfloat16_rn(x);
    p.y = __float2bfloat16_rn(y);
    return *(uint32_t*)&p;
}

// ---------------- CSR construction ------------------------------------------
__global__ void k_hist(const int* __restrict__ ei) {
    int e = blockIdx.x * blockDim.x + threadIdx.x;
    if (e >= ET) return;
    int dst = (e < EE) ? ei[EE + e] : (e - EE);
    atomicAdd(&g_cnt[dst], 1);
}
__global__ void k_scan_block() {
    __shared__ int sm[256];
    int i = blockIdx.x * 256 + threadIdx.x;
    int v = (i < NN) ? g_cnt[i] : 0;
    sm[threadIdx.x] = v;
    __syncthreads();
    #pragma unroll
    for (int o = 1; o < 256; o <<= 1) {
        int t = (threadIdx.x >= o) ? sm[threadIdx.x - o] : 0;
        __syncthreads();
        sm[threadIdx.x] += t;
        __syncthreads();
    }
    if (i < NN) g_rowptr[i] = sm[threadIdx.x] - v;
    if (threadIdx.x == 255) g_bsums[blockIdx.x] = sm[255];
}
__global__ void k_scan_tops(int nb) {
    __shared__ int sm[256];
    int v = (threadIdx.x < nb) ? g_bsums[threadIdx.x] : 0;
    sm[threadIdx.x] = v;
    __syncthreads();
    #pragma unroll
    for (int o = 1; o < 256; o <<= 1) {
        int t = (threadIdx.x >= o) ? sm[threadIdx.x - o] : 0;
        __syncthreads();
        sm[threadIdx.x] += t;
        __syncthreads();
    }
    g_bsums[threadIdx.x] = sm[threadIdx.x] - v;
}
__global__ void k_scan_finish() {
    int i = blockIdx.x * blockDim.x + threadIdx.x;
    if (i < NN) {
        int r = g_rowptr[i] + g_bsums[i >> 8];
        g_rowptr[i] = r;
        g_cursor[i] = r;
    }
    if (i == 0) g_rowptr[NN] = ET;
}
__global__ void k_scatter(const int* __restrict__ ei) {
    int e = blockIdx.x * blockDim.x + threadIdx.x;
    if (e >= ET) return;
    int src, dst;
    if (e < EE) { src = ei[e]; dst = ei[EE + e]; }
    else        { src = dst = e - EE; }
    int p = atomicAdd(&g_cursor[dst], 1);
    g_csr[p] = src;
}

// ---------------- combined prep: W planes + zero g_cnt ----------------------
// grid 196x256: threads 0..2047 do W conversion; all threads zero g_cnt.
__global__ void k_prep(const float* __restrict__ W) {
    int idx = blockIdx.x * blockDim.x + threadIdx.x;
    if (idx < NN) g_cnt[idx] = 0;
    if (idx < 2048) {
        int n = idx >> 4, kc = idx & 15;
        uint32_t hp[4], lp[4];
        #pragma unroll
        for (int j = 0; j < 4; j++) {
            float w0 = W[(kc * 8 + 2 * j) * 128 + n];
            float w1 = W[(kc * 8 + 2 * j + 1) * 128 + n];
            __nv_bfloat16 h0 = __float2bfloat16_rn(w0);
            __nv_bfloat16 h1 = __float2bfloat16_rn(w1);
            __nv_bfloat162 hh; hh.x = h0; hh.y = h1;
            hp[j] = *(uint32_t*)&hh;
            lp[j] = pkbf(w0 - __bfloat162float(h0), w1 - __bfloat162float(h1));
        }
        int half = kc >> 3;
        uint32_t off = half * 16384 + soff64(n, kc & 7);
        *(uint4*)(g_wh + off) = make_uint4(hp[0], hp[1], hp[2], hp[3]);
        *(uint4*)(g_wl + off) = make_uint4(lp[0], lp[1], lp[2], lp[3]);
    }
}

// ---------------- tensor-core GEMM + fused per-node alpha -------------------
// 128x128 tile, 512 threads (4x4 warps, warp tile 32x32), K in two 64-halves,
// 4 x 16KB smem planes -> 2 CTAs/SM.
// TERMS=3: D = Ah*Wh + Al*Wh + Ah*Wl (fp32 A split).
// TERMS=2: D = A*Wh + A*Wl (A pre-rounded to bf16; used for fp16 input).
template <int TERMS>
__global__ void __launch_bounds__(512, 2)
k_gemm_mma(const float* __restrict__ Af, const __half* __restrict__ Ahalf,
           const float* __restrict__ asrc, const float* __restrict__ adst,
           __half* __restrict__ H2, int M) {
    extern __shared__ __align__(16) char smem[];
    const int S_AH = 0, S_AL = 16384, S_BH = 32768, S_BL = 49152, S_ATT = 65536;
    int t = threadIdx.x;
    int row0 = blockIdx.x * 128;
    uint32_t sb = smem_u32(smem);
    float* att_s = (float*)(smem + S_ATT);      // [0..127] asrc, [128..255] adst

    if (t < 128)              att_s[t] = asrc[t];
    else if (t < 256)         att_s[t] = adst[t - 128];

    int wid = t >> 5, lane = t & 31;
    int wm = wid & 3;          // 4 row groups x 32 rows
    int wn = wid >> 2;         // 4 col groups x 32 cols (= head wn)

    float acc[2][4][4];
    #pragma unroll
    for (int mt = 0; mt < 2; mt++)
        #pragma unroll
        for (int nt = 0; nt < 4; nt++)
            #pragma unroll
            for (int q = 0; q < 4; q++) acc[mt][nt][q] = 0.f;

    int aRow = wm * 32 + (lane & 15);
    int aSel = lane >> 4;
    int bRow = wn * 32 + (lane & 7) + ((lane >> 4) << 3);
    int bSel = (lane >> 3) & 1;

    #pragma unroll
    for (int ks = 0; ks < 2; ks++) {
        if (ks) __syncthreads();     // previous mainloop must finish reading
        // copy pre-swizzled W half planes (2 x 16KB = 2 x 1024 uint4)
        {
            const uint4* wh4 = (const uint4*)g_wh + ks * 1024;
            const uint4* wl4 = (const uint4*)g_wl + ks * 1024;
            uint4* bh = (uint4*)(smem + S_BH);
            uint4* bl = (uint4*)(smem + S_BL);
            #pragma unroll
            for (int i = 0; i < 2; i++) {
                bh[i * 512 + t] = wh4[i * 512 + t];
                bl[i * 512 + t] = wl4[i * 512 + t];
            }
        }
        // convert A rows (128 rows x 8 chunks = 1024 chunks)
        #pragma unroll
        for (int ii = 0; ii < 2; ii++) {
            int i = ii * 512 + t;
            int r = i >> 3, kc = i & 7;
            int gr = row0 + r;
            int col = ks * 64 + kc * 8;
            float4 v0 = make_float4(0.f, 0.f, 0.f, 0.f), v1 = v0;
            if (gr < M) {
                if (TERMS == 2) {
                    uint4 raw = *(const uint4*)&Ahalf[gr * 128 + col];
                    float2 f0 = __half22float2(*(__half2*)&raw.x);
                    float2 f1p = __half22float2(*(__half2*)&raw.y);
                    float2 f2 = __half22float2(*(__half2*)&raw.z);
                    float2 f3 = __half22float2(*(__half2*)&raw.w);
                    v0 = make_float4(f0.x, f0.y, f1p.x, f1p.y);
                    v1 = make_float4(f2.x, f2.y, f3.x, f3.y);
                } else {
                    v0 = *(const float4*)&Af[gr * 128 + col];
                    v1 = *(const float4*)&Af[gr * 128 + col + 4];
                }
            }
            __nv_bfloat162 h0, h1, h2, h3;
            h0.x = __float2bfloat16_rn(v0.x); h0.y = __float2bfloat16_rn(v0.y);
            h1.x = __float2bfloat16_rn(v0.z); h1.y = __float2bfloat16_rn(v0.w);
            h2.x = __float2bfloat16_rn(v1.x); h2.y = __float2bfloat16_rn(v1.y);
            h3.x = __float2bfloat16_rn(v1.z); h3.y = __float2bfloat16_rn(v1.w);
            uint32_t off = soff64(r, kc);
            *(uint4*)(smem + S_AH + off) = make_uint4(*(uint32_t*)&h0, *(uint32_t*)&h1,
                                                      *(uint32_t*)&h2, *(uint32_t*)&h3);
            if (TERMS == 3) {
                *(uint4*)(smem + S_AL + off) = make_uint4(
                    pkbf(v0.x - __bfloat162float(h0.x), v0.y - __bfloat162float(h0.y)),
                    pkbf(v0.z - __bfloat162float(h1.x), v0.w - __bfloat162float(h1.y)),
                    pkbf(v1.x - __bfloat162float(h2.x), v1.y - __bfloat162float(h2.y)),
                    pkbf(v1.z - __bfloat162float(h3.x), v1.w - __bfloat162float(h3.y)));
            }
        }
        __syncthreads();

        // mainloop over this K half (4 x k16)
        #pragma unroll
        for (int k16 = 0; k16 < 4; k16++) {
            int kc = k16 * 2;
            uint32_t ah[2][4], al[2][4];
            #pragma unroll
            for (int mt = 0; mt < 2; mt++) {
                ldsm_x4(ah[mt][0], ah[mt][1], ah[mt][2], ah[mt][3],
                        sb + S_AH + soff64(aRow + mt * 16, kc + aSel));
                if (TERMS == 3)
                    ldsm_x4(al[mt][0], al[mt][1], al[mt][2], al[mt][3],
                            sb + S_AL + soff64(aRow + mt * 16, kc + aSel));
            }
            #pragma unroll
            for (int np = 0; np < 2; np++) {
                uint32_t bh0, bh1, bh2, bh3, bl0, bl1, bl2, bl3;
                ldsm_x4(bh0, bh1, bh2, bh3, sb + S_BH + soff64(bRow + np * 16, kc + bSel));
                ldsm_x4(bl0, bl1, bl2, bl3, sb + S_BL + soff64(bRow + np * 16, kc + bSel));
                #pragma unroll
                for (int mt = 0; mt < 2; mt++) {
                    mma16816(acc[mt][np * 2],     ah[mt][0], ah[mt][1], ah[mt][2], ah[mt][3], bh0, bh1);
                    mma16816(acc[mt][np * 2 + 1], ah[mt][0], ah[mt][1], ah[mt][2], ah[mt][3], bh2, bh3);
                    if (TERMS == 3) {
                        mma16816(acc[mt][np * 2],     al[mt][0], al[mt][1], al[mt][2], al[mt][3], bh0, bh1);
                        mma16816(acc[mt][np * 2 + 1], al[mt][0], al[mt][1], al[mt][2], al[mt][3], bh2, bh3);
                    }
                    mma16816(acc[mt][np * 2],     ah[mt][0], ah[mt][1], ah[mt][2], ah[mt][3], bl0, bl1);
                    mma16816(acc[mt][np * 2 + 1], ah[mt][0], ah[mt][1], ah[mt][2], ah[mt][3], bl2, bl3);
                }
            }
        }
    }

    // epilogue: fp16 feature store + fused alpha (head h = wn)
    #pragma unroll
    for (int mt = 0; mt < 2; mt++) {
        int rg = row0 + wm * 32 + mt * 16 + (lane >> 2);
        #pragma unroll
        for (int nt = 0; nt < 4; nt++) {
            int n = wn * 32 + nt * 8 + (lane & 3) * 2;
            if (rg < M) {
                __half2 hv; hv.x = __float2half(acc[mt][nt][0]); hv.y = __float2half(acc[mt][nt][1]);
                *(__half2*)&H2[rg * 128 + n] = hv;
            }
            if (rg + 8 < M) {
                __half2 hv; hv.x = __float2half(acc[mt][nt][2]); hv.y = __float2half(acc[mt][nt][3]);
                *(__half2*)&H2[(rg + 8) * 128 + n] = hv;
            }
        }
        float ps0 = 0.f, pd0 = 0.f, ps1 = 0.f, pd1 = 0.f;
        #pragma unroll
        for (int nt = 0; nt < 4; nt++) {
            int n = wn * 32 + nt * 8 + (lane & 3) * 2;
            float w0s = att_s[n], w1s = att_s[n + 1];
            float w0d = att_s[128 + n], w1d = att_s[128 + n + 1];
            ps0 += acc[mt][nt][0] * w0s + acc[mt][nt][1] * w1s;
            pd0 += acc[mt][nt][0] * w0d + acc[mt][nt][1] * w1d;
            ps1 += acc[mt][nt][2] * w0s + acc[mt][nt][3] * w1s;
            pd1 += acc[mt][nt][2] * w0d + acc[mt][nt][3] * w1d;
        }
        #pragma unroll
        for (int o = 1; o <= 2; o <<= 1) {
            ps0 += __shfl_xor_sync(0xffffffffu, ps0, o);
            pd0 += __shfl_xor_sync(0xffffffffu, pd0, o);
            ps1 += __shfl_xor_sync(0xffffffffu, ps1, o);
            pd1 += __shfl_xor_sync(0xffffffffu, pd1, o);
        }
        if ((lane & 3) == 0) {
            if (rg < M) {
                g_alpha[rg * 8 + wn]     = ps0;
                g_alpha[rg * 8 + 4 + wn] = pd0;
            }
            if (rg + 8 < M) {
                g_alpha[(rg + 8) * 8 + wn]     = ps1;
                g_alpha[(rg + 8) * 8 + 4 + wn] = pd1;
            }
        }
    }
}

// ---------------- edge softmax + aggregation (H=4, C=32) --------------------
// Single edge pass; features gathered in fp16 (2 x 128B lines per edge).
// mode 0: write ELU(out) fp16 to `outh` (feeds next GEMM).
// mode 1: fuse layer-3 prep — dot ELU(out) with W3 -> g_hw3, alphas -> g_a3.
__global__ void k_aggregate4(const __half* __restrict__ h2,
                             const float* __restrict__ bias,
                             __half* __restrict__ outh, int mode,
                             const float* __restrict__ W3,
                             const float* __restrict__ as3,
                             const float* __restrict__ ad3) {
    __shared__ float4 sm_e[8][32];
    __shared__ int    sm_s[8][32];
    int n = (blockIdx.x * blockDim.x + threadIdx.x) >> 5;
    if (n >= NN) return;
    int lane = threadIdx.x & 31;
    int wrp  = (threadIdx.x >> 5);
    int hsel = lane >> 4;
    int s0 = g_rowptr[n], s1 = g_rowptr[n + 1];
    float4 ad = *(const float4*)&g_alpha[n * 8 + 4];

    float sum0 = 0.f, sum1 = 0.f, sum2 = 0.f, sum3 = 0.f;
    float2 accA = make_float2(0.f, 0.f), accB = make_float2(0.f, 0.f);
    for (int base = s0; base < s1; base += 32) {
        int i = base + lane;
        int s = 0;
        float4 e = make_float4(0.f, 0.f, 0.f, 0.f);
        if (i < s1) {
            s = g_csr[i];
            float4 al = *(const float4*)&g_alpha[s * 8];
            float a;
            a = al.x + ad.x; a = (a > 0.f) ? a : NEG_SLOPE * a; e.x = __expf(a); sum0 += e.x;
            a = al.y + ad.y; a = (a > 0.f) ? a : NEG_SLOPE * a; e.y = __expf(a); sum1 += e.y;
            a = al.z + ad.z; a = (a > 0.f) ? a : NEG_SLOPE * a; e.z = __expf(a); sum2 += e.z;
            a = al.w + ad.w; a = (a > 0.f) ? a : NEG_SLOPE * a; e.w = __expf(a); sum3 += e.w;
        }
        sm_s[wrp][lane] = s;
        sm_e[wrp][lane] = e;
        __syncwarp();
        int cnt = min(32, s1 - base);
        #pragma unroll 4
        for (int j = 0; j < cnt; j++) {
            int ss = sm_s[wrp][j];
            float4 ee = sm_e[wrp][j];
            const __half2* hp = (const __half2*)(h2 + ss * FDIM);
            float2 fa = __half22float2(hp[lane]);
            float2 fb = __half22float2(hp[32 + lane]);
            float wA = hsel ? ee.y : ee.x;
            float wB = hsel ? ee.w : ee.z;
            accA.x += wA * fa.x; accA.y += wA * fa.y;
            accB.x += wB * fb.x; accB.y += wB * fb.y;
        }
        __syncwarp();
    }
    float inv0 = 1.f / wsum(sum0);
    float inv1 = 1.f / wsum(sum1);
    float inv2 = 1.f / wsum(sum2);
    float inv3 = 1.f / wsum(sum3);
    float invA = hsel ? inv1 : inv0;
    float invB = hsel ? inv3 : inv2;

    int c = 2 * lane;
    float v0 = accA.x * invA + bias[c];
    float v1 = accA.y * invA + bias[c + 1];
    float v2 = accB.x * invB + bias[64 + c];
    float v3 = accB.y * invB + bias[64 + c + 1];
    v0 = (v0 > 0.f) ? v0 : (__expf(v0) - 1.f);
    v1 = (v1 > 0.f) ? v1 : (__expf(v1) - 1.f);
    v2 = (v2 > 0.f) ? v2 : (__expf(v2) - 1.f);
    v3 = (v3 > 0.f) ? v3 : (__expf(v3) - 1.f);

    if (mode == 0) {
        __half2 o0; o0.x = __float2half(v0); o0.y = __float2half(v1);
        __half2 o1; o1.x = __float2half(v2); o1.y = __float2half(v3);
        *(__half2*)&outh[n * FDIM + c]      = o0;
        *(__half2*)&outh[n * FDIM + 64 + c] = o1;
    } else {
        // layer-3 prep: hw3 = f2 @ W3 ([128,2]); a3 from as3/ad3
        float4 wA4 = *(const float4*)&W3[2 * c];
        float4 wB4 = *(const float4*)&W3[128 + 2 * c];
        float p0 = v0 * wA4.x + v1 * wA4.z + v2 * wB4.x + v3 * wB4.z;
        float p1 = v0 * wA4.y + v1 * wA4.w + v2 * wB4.y + v3 * wB4.w;
        p0 = wsum(p0); p1 = wsum(p1);
        if (lane == 0) {
            g_hw3[n * 2] = p0; g_hw3[n * 2 + 1] = p1;
            g_a3[n * 2]     = p0 * as3[0] + p1 * as3[1];
            g_a3[n * 2 + 1] = p0 * ad3[0] + p1 * ad3[1];
        }
    }
}

// layer-3 aggregate (H=1,C=2) + bias + log_softmax, single edge pass
__global__ void k_aggregate1(const float* __restrict__ b3, float* __restrict__ out) {
    int n = (blockIdx.x * blockDim.x + threadIdx.x) >> 5;
    if (n >= NN) return;
    int lane = threadIdx.x & 31;
    int s0 = g_rowptr[n], s1 = g_rowptr[n + 1];
    float ad = g_a3[n * 2 + 1];

    float sum = 0.f, a0 = 0.f, a1 = 0.f;
    for (int i = s0 + lane; i < s1; i += 32) {
        int s = g_csr[i];
        float2 al = *(const float2*)&g_a3[s * 2];
        float a = al.x + ad;
        a = (a > 0.f) ? a : NEG_SLOPE * a;
        float e = __expf(a);
        sum += e;
        float2 h = *(const float2*)&g_hw3[s * 2];
        a0 += e * h.x;
        a1 += e * h.y;
    }
    sum = wsum(sum); a0 = wsum(a0); a1 = wsum(a1);

    if (lane == 0) {
        float inv = 1.f / sum;
        float z0 = a0 * inv + b3[0];
        float z1 = a1 * inv + b3[1];
        float mx = fmaxf(z0, z1);
        float l  = logf(__expf(z0 - mx) + __expf(z1 - mx));
        out[n * 2]     = z0 - mx - l;
        out[n * 2 + 1] = z1 - mx - l;
    }
}

// ---------------- host driver -----------------------------------------------
extern "C" void kernel_launch(void* const* d_in, const int* in_sizes, int n_in,
                              void* d_out, int out_size) {
    const float* x   = (const float*)d_in[0];
    const int*   ei  = (const int*)  d_in[1];
    const float* W1  = (const float*)d_in[2];
    const float* as1 = (const float*)d_in[3];
    const float* ad1 = (const float*)d_in[4];
    const float* b1  = (const float*)d_in[5];
    const float* W2  = (const float*)d_in[6];
    const float* as2 = (const float*)d_in[7];
    const float* ad2 = (const float*)d_in[8];
    const float* b2  = (const float*)d_in[9];
    const float* W3  = (const float*)d_in[10];
    const float* as3 = (const float*)d_in[11];
    const float* ad3 = (const float*)d_in[12];
    const float* b3  = (const float*)d_in[13];
    float* out = (float*)d_out;

    __half *p_h2, *p_f1h;
    cudaGetSymbolAddress((void**)&p_h2, g_h2);
    cudaGetSymbolAddress((void**)&p_f1h, g_f1h);

    const int GEMM_SMEM = 65536 + 1024;    // 4 x 16KB planes + att
    cudaFuncSetAttribute(k_gemm_mma<3>, cudaFuncAttributeMaxDynamicSharedMemorySize, GEMM_SMEM);
    cudaFuncSetAttribute(k_gemm_mma<2>, cudaFuncAttributeMaxDynamicSharedMemorySize, GEMM_SMEM);

    const int TPB = 256;
    int nbN = (NN + TPB - 1) / TPB;           // 196
    int nbE = (ET + TPB - 1) / TPB;           // 3321
    int nbW = (NN * 32 + TPB - 1) / TPB;      // 6250 (warp per node)
    int nbT = (NN + 127) / 128;               // 391 gemm tiles

    // order chosen so the profiled launch (0-based index 3) is k_gemm_mma
    k_prep<<<nbN, TPB>>>(W1);                                                 // 0  (W1 planes + zero cnt)
    k_hist<<<nbE, TPB>>>(ei);                                                 // 1
    k_scan_block<<<nbN, TPB>>>();                                             // 2
    k_gemm_mma<3><<<nbT, 512, GEMM_SMEM>>>(x, nullptr, as1, ad1, p_h2, NN);   // 3  <- profiled
    k_scan_tops<<<1, 256>>>(nbN);                                             // 4
    k_scan_finish<<<nbN, TPB>>>();                                            // 5
    k_scatter<<<nbE, TPB>>>(ei);                                              // 6

    // layer 1 aggregation (writes fp16 f1)
    k_aggregate4<<<nbW, TPB>>>(p_h2, b1, p_f1h, 0, W3, as3, ad3);             // 7

    // layer 2 (+ fused layer-3 prep in aggregation)
    k_prep<<<nbN, TPB>>>(W2);                                                 // 8
    k_gemm_mma<2><<<nbT, 512, GEMM_SMEM>>>(nullptr, p_f1h, as2, ad2, p_h2, NN); // 9
    k_aggregate4<<<nbW, TPB>>>(p_h2, b2, nullptr, 1, W3, as3, ad3);           // 10

    // layer 3 final aggregate + log_softmax
    k_aggregate1<<<nbW, TPB>>>(b3, out);                                      // 11
}

// round 13
// speedup vs baseline: 2.2281x; 1.0569x over previous
#include <cuda_runtime.h>
#include <cuda_bf16.h>
#include <cuda_fp16.h>
#include <math.h>
#include <stdint.h>

#define NN   50000
#define EE   800000
#define ET   (EE + NN)      // 850000 edges incl. self loops
#define FDIM 128
#define NH   4
#define CH   32
#define NEG_SLOPE 0.2f

// ---------------- device scratch (module-load allocated, no cudaMalloc) ----
__device__ int   g_cnt[NN];
__device__ int   g_rowptr[NN + 1];
__device__ int   g_cursor[NN];
__device__ int   g_csr[ET];
__device__ int   g_bsums[256];

__device__ __half g_h2[NN * FDIM];    // transformed features, fp16 (edge gather)
__device__ __half g_f1h[NN * FDIM];   // layer1 output, fp16 (feeds GEMM2)
__device__ float g_alpha[NN * 2 * NH];// per-node alpha_src[0..3], alpha_dst[4..7]
__device__ float g_hw3[NN * 2];
__device__ float g_a3[NN * 2];

// pre-swizzled bf16 hi/lo planes of W, per-half layout:
// [half(0/1)][16KB: rows n=0..127 x 8 chunks of 16B, xor-swizzled]
__device__ __align__(16) uint8_t g_wh[32768];
__device__ __align__(16) uint8_t g_wl[32768];

// ---------------- warp helpers ----------------------------------------------
__device__ __forceinline__ float wsum(float v) {
    #pragma unroll
    for (int o = 16; o; o >>= 1) v += __shfl_xor_sync(0xffffffffu, v, o);
    return v;
}

// ---------------- mma helpers ------------------------------------------------
__device__ __forceinline__ uint32_t smem_u32(const void* p) {
    uint32_t a;
    asm("{ .reg .u64 tmp; cvta.to.shared.u64 tmp, %1; cvt.u32.u64 %0, tmp; }"
        : "=r"(a) : "l"(p));
    return a;
}
__device__ __forceinline__ void ldsm_x4(uint32_t& r0, uint32_t& r1,
                                        uint32_t& r2, uint32_t& r3, uint32_t addr) {
    asm volatile("ldmatrix.sync.aligned.m8n8.x4.shared.b16 {%0,%1,%2,%3}, [%4];"
                 : "=r"(r0), "=r"(r1), "=r"(r2), "=r"(r3) : "r"(addr));
}
__device__ __forceinline__ void mma16816(float* c, uint32_t a0, uint32_t a1,
                                         uint32_t a2, uint32_t a3,
                                         uint32_t b0, uint32_t b1) {
    asm volatile("mma.sync.aligned.m16n8k16.row.col.f32.bf16.bf16.f32 "
                 "{%0,%1,%2,%3}, {%4,%5,%6,%7}, {%8,%9}, {%0,%1,%2,%3};"
                 : "+f"(c[0]), "+f"(c[1]), "+f"(c[2]), "+f"(c[3])
                 : "r"(a0), "r"(a1), "r"(a2), "r"(a3), "r"(b0), "r"(b1));
}
// half-K plane: 128 rows x 64 bf16 (128B rows, 8 chunks of 16B), xor swizzle
__device__ __forceinline__ uint32_t soff64(int r, int kc) {
    return (uint32_t)((r << 7) + (((kc ^ r) & 7) << 4));
}
__device__ __forceinline__ uint32_t pkbf(float x, float y) {
    __nv_bfloat162 p;
    p.x = __float2bfloat16_rn(x);
    p.y = __float2bfloat16_rn(y);
    return *(uint32_t*)&p;
}

// ---------------- CSR construction ------------------------------------------
__global__ void k_zero_cnt() {
    int i = blockIdx.x * blockDim.x + threadIdx.x;
    if (i < NN) g_cnt[i] = 0;
}
__global__ void k_hist(const int* __restrict__ ei) {
    int e = blockIdx.x * blockDim.x + threadIdx.x;
    if (e >= ET) return;
    int dst = (e < EE) ? ei[EE + e] : (e - EE);
    atomicAdd(&g_cnt[dst], 1);
}
__global__ void k_scan_block() {
    __shared__ int sm[256];
    int i = blockIdx.x * 256 + threadIdx.x;
    int v = (i < NN) ? g_cnt[i] : 0;
    sm[threadIdx.x] = v;
    __syncthreads();
    #pragma unroll
    for (int o = 1; o < 256; o <<= 1) {
        int t = (threadIdx.x >= o) ? sm[threadIdx.x - o] : 0;
        __syncthreads();
        sm[threadIdx.x] += t;
        __syncthreads();
    }
    if (i < NN) g_rowptr[i] = sm[threadIdx.x] - v;
    if (threadIdx.x == 255) g_bsums[blockIdx.x] = sm[255];
}
__global__ void k_scan_tops(int nb) {
    __shared__ int sm[256];
    int v = (threadIdx.x < nb) ? g_bsums[threadIdx.x] : 0;
    sm[threadIdx.x] = v;
    __syncthreads();
    #pragma unroll
    for (int o = 1; o < 256; o <<= 1) {
        int t = (threadIdx.x >= o) ? sm[threadIdx.x - o] : 0;
        __syncthreads();
        sm[threadIdx.x] += t;
        __syncthreads();
    }
    g_bsums[threadIdx.x] = sm[threadIdx.x] - v;
}
__global__ void k_scan_finish() {
    int i = blockIdx.x * blockDim.x + threadIdx.x;
    if (i < NN) {
        int r = g_rowptr[i] + g_bsums[i >> 8];
        g_rowptr[i] = r;
        g_cursor[i] = r;
    }
    if (i == 0) g_rowptr[NN] = ET;
}
__global__ void k_scatter(const int* __restrict__ ei) {
    int e = blockIdx.x * blockDim.x + threadIdx.x;
    if (e >= ET) return;
    int src, dst;
    if (e < EE) { src = ei[e]; dst = ei[EE + e]; }
    else        { src = dst = e - EE; }
    int p = atomicAdd(&g_cursor[dst], 1);
    g_csr[p] = src;
}

// ---------------- W prep: fp32 [128k,128n] -> 2 half-K swizzled planes ------
__global__ void k_wprep(const float* __restrict__ W) {
    int i = blockIdx.x * blockDim.x + threadIdx.x;   // 2048 chunks
    if (i >= 2048) return;
    int n = i >> 4, kc = i & 15;
    uint32_t hp[4], lp[4];
    #pragma unroll
    for (int j = 0; j < 4; j++) {
        float w0 = W[(kc * 8 + 2 * j) * 128 + n];
        float w1 = W[(kc * 8 + 2 * j + 1) * 128 + n];
        __nv_bfloat16 h0 = __float2bfloat16_rn(w0);
        __nv_bfloat16 h1 = __float2bfloat16_rn(w1);
        __nv_bfloat162 hh; hh.x = h0; hh.y = h1;
        hp[j] = *(uint32_t*)&hh;
        lp[j] = pkbf(w0 - __bfloat162float(h0), w1 - __bfloat162float(h1));
    }
    int half = kc >> 3;
    uint32_t off = half * 16384 + soff64(n, kc & 7);
    *(uint4*)(g_wh + off) = make_uint4(hp[0], hp[1], hp[2], hp[3]);
    *(uint4*)(g_wl + off) = make_uint4(lp[0], lp[1], lp[2], lp[3]);
}

// ---------------- tensor-core GEMM + fused per-node alpha -------------------
// 128x128 tile, 512 threads (4x4 warps, warp tile 32x32), K in two 64-halves,
// 4 x 16KB smem planes -> 2 CTAs/SM.
// TERMS=3: D = Ah*Wh + Al*Wh + Ah*Wl (fp32 A split).
// TERMS=2: D = A*Wh + A*Wl (A pre-rounded to bf16; used for fp16 input).
template <int TERMS>
__global__ void __launch_bounds__(512, 2)
k_gemm_mma(const float* __restrict__ Af, const __half* __restrict__ Ahalf,
           const float* __restrict__ asrc, const float* __restrict__ adst,
           __half* __restrict__ H2, int M) {
    extern __shared__ __align__(16) char smem[];
    const int S_AH = 0, S_AL = 16384, S_BH = 32768, S_BL = 49152, S_ATT = 65536;
    int t = threadIdx.x;
    int row0 = blockIdx.x * 128;
    uint32_t sb = smem_u32(smem);
    float* att_s = (float*)(smem + S_ATT);      // [0..127] asrc, [128..255] adst

    if (t < 128)              att_s[t] = asrc[t];
    else if (t < 256)         att_s[t] = adst[t - 128];

    int wid = t >> 5, lane = t & 31;
    int wm = wid & 3;          // 4 row groups x 32 rows
    int wn = wid >> 2;         // 4 col groups x 32 cols (= head wn)

    float acc[2][4][4];
    #pragma unroll
    for (int mt = 0; mt < 2; mt++)
        #pragma unroll
        for (int nt = 0; nt < 4; nt++)
            #pragma unroll
            for (int q = 0; q < 4; q++) acc[mt][nt][q] = 0.f;

    int aRow = wm * 32 + (lane & 15);
    int aSel = lane >> 4;
    int bRow = wn * 32 + (lane & 7) + ((lane >> 4) << 3);
    int bSel = (lane >> 3) & 1;

    #pragma unroll
    for (int ks = 0; ks < 2; ks++) {
        if (ks) __syncthreads();     // previous mainloop must finish reading
        // copy pre-swizzled W half planes (2 x 16KB = 2 x 1024 uint4)
        {
            const uint4* wh4 = (const uint4*)g_wh + ks * 1024;
            const uint4* wl4 = (const uint4*)g_wl + ks * 1024;
            uint4* bh = (uint4*)(smem + S_BH);
            uint4* bl = (uint4*)(smem + S_BL);
            #pragma unroll
            for (int i = 0; i < 2; i++) {
                bh[i * 512 + t] = wh4[i * 512 + t];
                bl[i * 512 + t] = wl4[i * 512 + t];
            }
        }
        // convert A rows (128 rows x 8 chunks = 1024 chunks)
        #pragma unroll
        for (int ii = 0; ii < 2; ii++) {
            int i = ii * 512 + t;
            int r = i >> 3, kc = i & 7;
            int gr = row0 + r;
            int col = ks * 64 + kc * 8;
            float4 v0 = make_float4(0.f, 0.f, 0.f, 0.f), v1 = v0;
            if (gr < M) {
                if (TERMS == 2) {
                    uint4 raw = *(const uint4*)&Ahalf[gr * 128 + col];
                    float2 f0 = __half22float2(*(__half2*)&raw.x);
                    float2 f1p = __half22float2(*(__half2*)&raw.y);
                    float2 f2 = __half22float2(*(__half2*)&raw.z);
                    float2 f3 = __half22float2(*(__half2*)&raw.w);
                    v0 = make_float4(f0.x, f0.y, f1p.x, f1p.y);
                    v1 = make_float4(f2.x, f2.y, f3.x, f3.y);
                } else {
                    v0 = *(const float4*)&Af[gr * 128 + col];
                    v1 = *(const float4*)&Af[gr * 128 + col + 4];
                }
            }
            __nv_bfloat162 h0, h1, h2, h3;
            h0.x = __float2bfloat16_rn(v0.x); h0.y = __float2bfloat16_rn(v0.y);
            h1.x = __float2bfloat16_rn(v0.z); h1.y = __float2bfloat16_rn(v0.w);
            h2.x = __float2bfloat16_rn(v1.x); h2.y = __float2bfloat16_rn(v1.y);
            h3.x = __float2bfloat16_rn(v1.z); h3.y = __float2bfloat16_rn(v1.w);
            uint32_t off = soff64(r, kc);
            *(uint4*)(smem + S_AH + off) = make_uint4(*(uint32_t*)&h0, *(uint32_t*)&h1,
                                                      *(uint32_t*)&h2, *(uint32_t*)&h3);
            if (TERMS == 3) {
                *(uint4*)(smem + S_AL + off) = make_uint4(
                    pkbf(v0.x - __bfloat162float(h0.x), v0.y - __bfloat162float(h0.y)),
                    pkbf(v0.z - __bfloat162float(h1.x), v0.w - __bfloat162float(h1.y)),
                    pkbf(v1.x - __bfloat162float(h2.x), v1.y - __bfloat162float(h2.y)),
                    pkbf(v1.z - __bfloat162float(h3.x), v1.w - __bfloat162float(h3.y)));
            }
        }
        __syncthreads();

        // mainloop over this K half (4 x k16)
        #pragma unroll
        for (int k16 = 0; k16 < 4; k16++) {
            int kc = k16 * 2;
            uint32_t ah[2][4], al[2][4];
            #pragma unroll
            for (int mt = 0; mt < 2; mt++) {
                ldsm_x4(ah[mt][0], ah[mt][1], ah[mt][2], ah[mt][3],
                        sb + S_AH + soff64(aRow + mt * 16, kc + aSel));
                if (TERMS == 3)
                    ldsm_x4(al[mt][0], al[mt][1], al[mt][2], al[mt][3],
                            sb + S_AL + soff64(aRow + mt * 16, kc + aSel));
            }
            #pragma unroll
            for (int np = 0; np < 2; np++) {
                uint32_t bh0, bh1, bh2, bh3, bl0, bl1, bl2, bl3;
                ldsm_x4(bh0, bh1, bh2, bh3, sb + S_BH + soff64(bRow + np * 16, kc + bSel));
                ldsm_x4(bl0, bl1, bl2, bl3, sb + S_BL + soff64(bRow + np * 16, kc + bSel));
                #pragma unroll
                for (int mt = 0; mt < 2; mt++) {
                    mma16816(acc[mt][np * 2],     ah[mt][0], ah[mt][1], ah[mt][2], ah[mt][3], bh0, bh1);
                    mma16816(acc[mt][np * 2 + 1], ah[mt][0], ah[mt][1], ah[mt][2], ah[mt][3], bh2, bh3);
                    if (TERMS == 3) {
                        mma16816(acc[mt][np * 2],     al[mt][0], al[mt][1], al[mt][2], al[mt][3], bh0, bh1);
                        mma16816(acc[mt][np * 2 + 1], al[mt][0], al[mt][1], al[mt][2], al[mt][3], bh2, bh3);
                    }
                    mma16816(acc[mt][np * 2],     ah[mt][0], ah[mt][1], ah[mt][2], ah[mt][3], bl0, bl1);
                    mma16816(acc[mt][np * 2 + 1], ah[mt][0], ah[mt][1], ah[mt][2], ah[mt][3], bl2, bl3);
                }
            }
        }
    }

    // epilogue: fp16 feature store + fused alpha (head h = wn)
    #pragma unroll
    for (int mt = 0; mt < 2; mt++) {
        int rg = row0 + wm * 32 + mt * 16 + (lane >> 2);
        #pragma unroll
        for (int nt = 0; nt < 4; nt++) {
            int n = wn * 32 + nt * 8 + (lane & 3) * 2;
            if (rg < M) {
                __half2 hv; hv.x = __float2half(acc[mt][nt][0]); hv.y = __float2half(acc[mt][nt][1]);
                *(__half2*)&H2[rg * 128 + n] = hv;
            }
            if (rg + 8 < M) {
                __half2 hv; hv.x = __float2half(acc[mt][nt][2]); hv.y = __float2half(acc[mt][nt][3]);
                *(__half2*)&H2[(rg + 8) * 128 + n] = hv;
            }
        }
        float ps0 = 0.f, pd0 = 0.f, ps1 = 0.f, pd1 = 0.f;
        #pragma unroll
        for (int nt = 0; nt < 4; nt++) {
            int n = wn * 32 + nt * 8 + (lane & 3) * 2;
            float w0s = att_s[n], w1s = att_s[n + 1];
            float w0d = att_s[128 + n], w1d = att_s[128 + n + 1];
            ps0 += acc[mt][nt][0] * w0s + acc[mt][nt][1] * w1s;
            pd0 += acc[mt][nt][0] * w0d + acc[mt][nt][1] * w1d;
            ps1 += acc[mt][nt][2] * w0s + acc[mt][nt][3] * w1s;
            pd1 += acc[mt][nt][2] * w0d + acc[mt][nt][3] * w1d;
        }
        #pragma unroll
        for (int o = 1; o <= 2; o <<= 1) {
            ps0 += __shfl_xor_sync(0xffffffffu, ps0, o);
            pd0 += __shfl_xor_sync(0xffffffffu, pd0, o);
            ps1 += __shfl_xor_sync(0xffffffffu, ps1, o);
            pd1 += __shfl_xor_sync(0xffffffffu, pd1, o);
        }
        if ((lane & 3) == 0) {
            if (rg < M) {
                g_alpha[rg * 8 + wn]     = ps0;
                g_alpha[rg * 8 + 4 + wn] = pd0;
            }
            if (rg + 8 < M) {
                g_alpha[(rg + 8) * 8 + wn]     = ps1;
                g_alpha[(rg + 8) * 8 + 4 + wn] = pd1;
            }
        }
    }
}

// ---------------- edge softmax + aggregation (H=4, C=32) --------------------
__global__ void k_aggregate4(const __half* __restrict__ h2,
                             const float* __restrict__ bias,
                             __half* __restrict__ outh, int mode,
                             const float* __restrict__ W3,
                             const float* __restrict__ as3,
                             const float* __restrict__ ad3) {
    __shared__ float4 sm_e[8][32];
    __shared__ int    sm_s[8][32];
    int n = (blockIdx.x * blockDim.x + threadIdx.x) >> 5;
    if (n >= NN) return;
    int lane = threadIdx.x & 31;
    int wrp  = (threadIdx.x >> 5);
    int hsel = lane >> 4;
    int s0 = g_rowptr[n], s1 = g_rowptr[n + 1];
    float4 ad = *(const float4*)&g_alpha[n * 8 + 4];

    float sum0 = 0.f, sum1 = 0.f, sum2 = 0.f, sum3 = 0.f;
    float2 accA = make_float2(0.f, 0.f), accB = make_float2(0.f, 0.f);
    for (int base = s0; base < s1; base += 32) {
        int i = base + lane;
        int s = 0;
        float4 e = make_float4(0.f, 0.f, 0.f, 0.f);
        if (i < s1) {
            s = g_csr[i];
            float4 al = *(const float4*)&g_alpha[s * 8];
            float a;
            a = al.x + ad.x; a = (a > 0.f) ? a : NEG_SLOPE * a; e.x = __expf(a); sum0 += e.x;
            a = al.y + ad.y; a = (a > 0.f) ? a : NEG_SLOPE * a; e.y = __expf(a); sum1 += e.y;
            a = al.z + ad.z; a = (a > 0.f) ? a : NEG_SLOPE * a; e.z = __expf(a); sum2 += e.z;
            a = al.w + ad.w; a = (a > 0.f) ? a : NEG_SLOPE * a; e.w = __expf(a); sum3 += e.w;
        }
        sm_s[wrp][lane] = s;
        sm_e[wrp][lane] = e;
        __syncwarp();
        int cnt = min(32, s1 - base);
        #pragma unroll 4
        for (int j = 0; j < cnt; j++) {
            int ss = sm_s[wrp][j];
            float4 ee = sm_e[wrp][j];
            const __half2* hp = (const __half2*)(h2 + ss * FDIM);
            float2 fa = __half22float2(hp[lane]);
            float2 fb = __half22float2(hp[32 + lane]);
            float wA = hsel ? ee.y : ee.x;
            float wB = hsel ? ee.w : ee.z;
            accA.x += wA * fa.x; accA.y += wA * fa.y;
            accB.x += wB * fb.x; accB.y += wB * fb.y;
        }
        __syncwarp();
    }
    float inv0 = 1.f / wsum(sum0);
    float inv1 = 1.f / wsum(sum1);
    float inv2 = 1.f / wsum(sum2);
    float inv3 = 1.f / wsum(sum3);
    float invA = hsel ? inv1 : inv0;
    float invB = hsel ? inv3 : inv2;

    int c = 2 * lane;
    float v0 = accA.x * invA + bias[c];
    float v1 = accA.y * invA + bias[c + 1];
    float v2 = accB.x * invB + bias[64 + c];
    float v3 = accB.y * invB + bias[64 + c + 1];
    v0 = (v0 > 0.f) ? v0 : (__expf(v0) - 1.f);
    v1 = (v1 > 0.f) ? v1 : (__expf(v1) - 1.f);
    v2 = (v2 > 0.f) ? v2 : (__expf(v2) - 1.f);
    v3 = (v3 > 0.f) ? v3 : (__expf(v3) - 1.f);

    if (mode == 0) {
        __half2 o0; o0.x = __float2half(v0); o0.y = __float2half(v1);
        __half2 o1; o1.x = __float2half(v2); o1.y = __float2half(v3);
        *(__half2*)&outh[n * FDIM + c]      = o0;
        *(__half2*)&outh[n * FDIM + 64 + c] = o1;
    } else {
        // layer-3 prep: hw3 = f2 @ W3 ([128,2]); a3 from as3/ad3
        float4 wA4 = *(const float4*)&W3[2 * c];
        float4 wB4 = *(const float4*)&W3[128 + 2 * c];
        float p0 = v0 * wA4.x + v1 * wA4.z + v2 * wB4.x + v3 * wB4.z;
        float p1 = v0 * wA4.y + v1 * wA4.w + v2 * wB4.y + v3 * wB4.w;
        p0 = wsum(p0); p1 = wsum(p1);
        if (lane == 0) {
            g_hw3[n * 2] = p0; g_hw3[n * 2 + 1] = p1;
            g_a3[n * 2]     = p0 * as3[0] + p1 * as3[1];
            g_a3[n * 2 + 1] = p0 * ad3[0] + p1 * ad3[1];
        }
    }
}

// layer-3 aggregate (H=1,C=2) + bias + log_softmax, single edge pass
__global__ void k_aggregate1(const float* __restrict__ b3, float* __restrict__ out) {
    int n = (blockIdx.x * blockDim.x + threadIdx.x) >> 5;
    if (n >= NN) return;
    int lane = threadIdx.x & 31;
    int s0 = g_rowptr[n], s1 = g_rowptr[n + 1];
    float ad = g_a3[n * 2 + 1];

    float sum = 0.f, a0 = 0.f, a1 = 0.f;
    for (int i = s0 + lane; i < s1; i += 32) {
        int s = g_csr[i];
        float2 al = *(const float2*)&g_a3[s * 2];
        float a = al.x + ad;
        a = (a > 0.f) ? a : NEG_SLOPE * a;
        float e = __expf(a);
        sum += e;
        float2 h = *(const float2*)&g_hw3[s * 2];
        a0 += e * h.x;
        a1 += e * h.y;
    }
    sum = wsum(sum); a0 = wsum(a0); a1 = wsum(a1);

    if (lane == 0) {
        float inv = 1.f / sum;
        float z0 = a0 * inv + b3[0];
        float z1 = a1 * inv + b3[1];
        float mx = fmaxf(z0, z1);
        float l  = logf(__expf(z0 - mx) + __expf(z1 - mx));
        out[n * 2]     = z0 - mx - l;
        out[n * 2 + 1] = z1 - mx - l;
    }
}

// ---------------- host driver -----------------------------------------------
extern "C" void kernel_launch(void* const* d_in, const int* in_sizes, int n_in,
                              void* d_out, int out_size) {
    const float* x   = (const float*)d_in[0];
    const int*   ei  = (const int*)  d_in[1];
    const float* W1  = (const float*)d_in[2];
    const float* as1 = (const float*)d_in[3];
    const float* ad1 = (const float*)d_in[4];
    const float* b1  = (const float*)d_in[5];
    const float* W2  = (const float*)d_in[6];
    const float* as2 = (const float*)d_in[7];
    const float* ad2 = (const float*)d_in[8];
    const float* b2  = (const float*)d_in[9];
    const float* W3  = (const float*)d_in[10];
    const float* as3 = (const float*)d_in[11];
    const float* ad3 = (const float*)d_in[12];
    const float* b3  = (const float*)d_in[13];
    float* out = (float*)d_out;

    __half *p_h2, *p_f1h;
    cudaGetSymbolAddress((void**)&p_h2, g_h2);
    cudaGetSymbolAddress((void**)&p_f1h, g_f1h);

    const int GEMM_SMEM = 65536 + 1024;    // 4 x 16KB planes + att
    cudaFuncSetAttribute(k_gemm_mma<3>, cudaFuncAttributeMaxDynamicSharedMemorySize, GEMM_SMEM);
    cudaFuncSetAttribute(k_gemm_mma<2>, cudaFuncAttributeMaxDynamicSharedMemorySize, GEMM_SMEM);

    // one-time host resources (same pattern as the attr guard that passed in R5)
    static cudaStream_t s1 = nullptr;
    static cudaEvent_t evFork = nullptr, evCsr = nullptr, evG1 = nullptr, evW2 = nullptr;
    if (!s1) {
        cudaStreamCreateWithFlags(&s1, cudaStreamNonBlocking);
        cudaEventCreateWithFlags(&evFork, cudaEventDisableTiming);
        cudaEventCreateWithFlags(&evCsr,  cudaEventDisableTiming);
        cudaEventCreateWithFlags(&evG1,   cudaEventDisableTiming);
        cudaEventCreateWithFlags(&evW2,   cudaEventDisableTiming);
    }

    const int TPB = 256;
    int nbN = (NN + TPB - 1) / TPB;           // 196
    int nbE = (ET + TPB - 1) / TPB;           // 3321
    int nbW = (NN * 32 + TPB - 1) / TPB;      // 6250 (warp per node)
    int nbT = (NN + 127) / 128;               // 391 gemm tiles

    // fork: CSR branch on s1, GEMM branch on the launch stream (0)
    cudaEventRecord(evFork, 0);
    cudaStreamWaitEvent(s1, evFork, 0);

    // --- branch A (s1): CSR build ---
    k_zero_cnt<<<nbN, TPB, 0, s1>>>();
    k_hist<<<nbE, TPB, 0, s1>>>(ei);
    k_scan_block<<<nbN, TPB, 0, s1>>>();
    k_scan_tops<<<1, 256, 0, s1>>>(nbN);
    k_scan_finish<<<nbN, TPB, 0, s1>>>();
    k_scatter<<<nbE, TPB, 0, s1>>>(ei);
    cudaEventRecord(evCsr, s1);

    // --- branch B (stream 0): W1 prep + GEMM1 ---
    k_wprep<<<16, 128>>>(W1);
    k_gemm_mma<3><<<nbT, 512, GEMM_SMEM>>>(x, nullptr, as1, ad1, p_h2, NN);
    cudaEventRecord(evG1, 0);

    // W2 prep on s1, overlapped with layer-1 aggregation (needs GEMM1 done
    // reading the W planes)
    cudaStreamWaitEvent(s1, evG1, 0);
    k_wprep<<<16, 128, 0, s1>>>(W2);
    cudaEventRecord(evW2, s1);

    // join: layer-1 aggregation needs CSR + GEMM1
    cudaStreamWaitEvent(0, evCsr, 0);
    k_aggregate4<<<nbW, TPB>>>(p_h2, b1, p_f1h, 0, W3, as3, ad3);

    // layer 2 (needs W2 planes)
    cudaStreamWaitEvent(0, evW2, 0);
    k_gemm_mma<2><<<nbT, 512, GEMM_SMEM>>>(nullptr, p_f1h, as2, ad2, p_h2, NN);
    k_aggregate4<<<nbW, TPB>>>(p_h2, b2, nullptr, 1, W3, as3, ad3);

    // layer 3 final aggregate + log_softmax
    k_aggregate1<<<nbW, TPB>>>(b3, out);
}